// round 5
// baseline (speedup 1.0000x reference)
#include <cuda_runtime.h>
#include <cuda_bf16.h>
#include <math.h>
#include <stdint.h>

// ---------------- problem constants ----------------
#define V_   32000
#define D_   1024
#define H_   16
#define KVH_ 4
#define HD_  64
#define F_   4096
#define L_   2
#define B_   2
#define S_   2048
#define T_   (B_*S_)
#define REP_ (H_/KVH_)
#define EPS_ 1e-5f
#define SCALE_ 0.125f
#define QKV_ 1536            // fused q|k|v width
#define GU_  8192            // fused gate|up width

typedef __nv_bfloat16 bf16;

// ---------------- scratch ----------------
__device__ float g_x  [T_*D_];
__device__ float g_qkv[T_*QKV_];
__device__ float g_gu [T_*GU_];
__device__ int   g_is64;

// activation bf16 planes
__device__ bf16 g_nh[T_*D_],  g_nl[T_*D_];
__device__ bf16 g_qh[T_*D_],  g_ql[T_*D_];
__device__ bf16 g_kh[T_*KVH_*HD_], g_kl[T_*KVH_*HD_];
__device__ bf16 g_vh[T_*KVH_*HD_], g_vl[T_*KVH_*HD_];
__device__ bf16 g_ch[T_*D_],  g_cl[T_*D_];
__device__ bf16 g_gh[T_*F_],  g_gl[T_*F_];

// transposed weight planes, [N, K] K-major
__device__ bf16 g_wqkvT_h[L_*QKV_*D_], g_wqkvT_l[L_*QKV_*D_];
__device__ bf16 g_woT_h  [L_*D_*D_],   g_woT_l  [L_*D_*D_];
__device__ bf16 g_wguT_h [L_*GU_*D_],  g_wguT_l [L_*GU_*D_];
__device__ bf16 g_wdT_h  [L_*D_*F_],   g_wdT_l  [L_*D_*F_];
__device__ bf16 g_woutT_h[V_*D_],      g_woutT_l[V_*D_];

// ---------------- helpers ----------------
__device__ __forceinline__ uint32_t pack2(bf16 a, bf16 b) {
    __nv_bfloat162 t = __halves2bfloat162(a, b);
    return *reinterpret_cast<uint32_t*>(&t);
}
__device__ __forceinline__ void split1(float v, bf16& h, bf16& l) {
    h = __float2bfloat16(v);
    l = __float2bfloat16(v - __bfloat162float(h));
}

#define LDSM4(r, addr) \
    asm volatile("ldmatrix.sync.aligned.m8n8.x4.shared.b16 {%0,%1,%2,%3}, [%4];" \
        : "=r"((r)[0]), "=r"((r)[1]), "=r"((r)[2]), "=r"((r)[3]) : "r"(addr))
#define LDSM4T(r, addr) \
    asm volatile("ldmatrix.sync.aligned.m8n8.x4.trans.shared.b16 {%0,%1,%2,%3}, [%4];" \
        : "=r"((r)[0]), "=r"((r)[1]), "=r"((r)[2]), "=r"((r)[3]) : "r"(addr))
#define MMA_BF16(acc, a, b0, b1) \
    asm volatile("mma.sync.aligned.m16n8k16.row.col.f32.bf16.bf16.f32 " \
        "{%0,%1,%2,%3}, {%4,%5,%6,%7}, {%8,%9}, {%0,%1,%2,%3};" \
        : "+f"((acc)[0]), "+f"((acc)[1]), "+f"((acc)[2]), "+f"((acc)[3]) \
        : "r"((a)[0]), "r"((a)[1]), "r"((a)[2]), "r"((a)[3]), "r"(b0), "r"(b1))
#define CP16(dst, src) \
    asm volatile("cp.async.cg.shared.global [%0], [%1], 16;\n" :: "r"(dst), "l"(src) : "memory")
#define CP_COMMIT() asm volatile("cp.async.commit_group;\n" ::: "memory")
#define CP_WAIT(n)  asm volatile("cp.async.wait_group %0;\n" :: "n"(n) : "memory")

// ---------------- idx detection + embed ----------------
__global__ void detect_idx_kernel(const int* idx) {
    __shared__ int ok;
    if (threadIdx.x == 0) ok = 1;
    __syncthreads();
    int bad = 0;
    for (int i = threadIdx.x; i < T_/2; i += blockDim.x)
        if (idx[2*i + 1] != 0) bad = 1;
    if (bad) atomicAnd(&ok, 0);
    __syncthreads();
    if (threadIdx.x == 0) g_is64 = ok;
}
__global__ void embed_kernel(const void* idx, const float* __restrict__ emb) {
    int t = blockIdx.x;
    int tok = g_is64 ? (int)((const long long*)idx)[t] : ((const int*)idx)[t];
    ((float4*)(g_x + (size_t)t * D_))[threadIdx.x] =
        ((const float4*)(emb + (size_t)tok * D_))[threadIdx.x];
}

// ---------------- RMSNorm -> bf16 planes ----------------
__global__ void rmsnorm_split_kernel(const float* __restrict__ x,
                                     const float* __restrict__ w,
                                     bf16* __restrict__ oh, bf16* __restrict__ ol) {
    int t = blockIdx.x;
    __shared__ float red[8];
    float4 v = ((const float4*)(x + (size_t)t * D_))[threadIdx.x];
    float ss = v.x*v.x + v.y*v.y + v.z*v.z + v.w*v.w;
    #pragma unroll
    for (int o = 16; o > 0; o >>= 1) ss += __shfl_xor_sync(0xffffffffu, ss, o);
    if ((threadIdx.x & 31) == 0) red[threadIdx.x >> 5] = ss;
    __syncthreads();
    if (threadIdx.x < 8) {
        float s = red[threadIdx.x];
        #pragma unroll
        for (int o = 4; o > 0; o >>= 1) s += __shfl_xor_sync(0xffu, s, o);
        if (threadIdx.x == 0) red[0] = s;
    }
    __syncthreads();
    float inv = rsqrtf(red[0] * (1.0f / D_) + EPS_);
    float4 wv = ((const float4*)w)[threadIdx.x];
    float vv[4] = {v.x*inv*wv.x, v.y*inv*wv.y, v.z*inv*wv.z, v.w*inv*wv.w};
    bf16 h[4], l[4];
    #pragma unroll
    for (int j = 0; j < 4; j++) split1(vv[j], h[j], l[j]);
    ((uint2*)(oh + (size_t)t*D_))[threadIdx.x] = make_uint2(pack2(h[0],h[1]), pack2(h[2],h[3]));
    ((uint2*)(ol + (size_t)t*D_))[threadIdx.x] = make_uint2(pack2(l[0],l[1]), pack2(l[2],l[3]));
}

// ---------------- RoPE (strided in) -> dense bf16 planes ----------------
__global__ void rope_split_kernel(const float* __restrict__ x, int xStride, int xOff,
                                  bf16* __restrict__ xh, bf16* __restrict__ xl,
                                  int nheads, float scl) {
    int t   = blockIdx.x;
    int pos = t % S_;
    int j   = threadIdx.x & 31;
    int h   = threadIdx.x >> 5;
    float invf = powf(500000.0f, -(float)(2 * j) / (float)HD_);
    float ang = (float)pos * invf;
    float s, c;
    sincosf(ang, &s, &c);
    const float* p = x + (size_t)t * xStride + xOff + h * HD_;
    size_t ob = (size_t)t * nheads * HD_ + h * HD_;
    float a = p[j], b = p[j + 32];
    float r0 = (a * c - b * s) * scl;
    float r1 = (b * c + a * s) * scl;
    bf16 h0, l0, h1, l1;
    split1(r0, h0, l0); split1(r1, h1, l1);
    xh[ob + j] = h0; xl[ob + j] = l0;
    xh[ob + j + 32] = h1; xl[ob + j + 32] = l1;
}

// ---------------- strided V split ----------------
__global__ void vsplit_kernel(const float* __restrict__ x,
                              bf16* __restrict__ oh, bf16* __restrict__ ol) {
    int t = blockIdx.x, i = threadIdx.x;   // 64 threads * float4 = 256
    float4 v = *(const float4*)(x + (size_t)t*QKV_ + 1280 + i*4);
    float vv[4] = {v.x, v.y, v.z, v.w};
    bf16 h[4], l[4];
    #pragma unroll
    for (int j = 0; j < 4; j++) split1(vv[j], h[j], l[j]);
    ((uint2*)(oh + (size_t)t*256))[i] = make_uint2(pack2(h[0],h[1]), pack2(h[2],h[3]));
    ((uint2*)(ol + (size_t)t*256))[i] = make_uint2(pack2(l[0],l[1]), pack2(l[2],l[3]));
}

// ---------------- SwiGLU from fused gu buffer -> bf16 planes ----------------
__global__ void silu_split_kernel(const float* __restrict__ gu,
                                  bf16* __restrict__ oh, bf16* __restrict__ ol) {
    int i = blockIdx.x * blockDim.x + threadIdx.x;   // float4 idx over T*F
    int e = i * 4;
    int t = e >> 12;         // / F_
    int f = e & 4095;
    float4 g4 = *(const float4*)(gu + (size_t)t*GU_ + f);
    float4 u4 = *(const float4*)(gu + (size_t)t*GU_ + 4096 + f);
    float vv[4];
    vv[0] = g4.x / (1.f + __expf(-g4.x)) * u4.x;
    vv[1] = g4.y / (1.f + __expf(-g4.y)) * u4.y;
    vv[2] = g4.z / (1.f + __expf(-g4.z)) * u4.z;
    vv[3] = g4.w / (1.f + __expf(-g4.w)) * u4.w;
    bf16 h[4], l[4];
    #pragma unroll
    for (int j = 0; j < 4; j++) split1(vv[j], h[j], l[j]);
    ((uint2*)oh)[i] = make_uint2(pack2(h[0],h[1]), pack2(h[2],h[3]));
    ((uint2*)ol)[i] = make_uint2(pack2(l[0],l[1]), pack2(l[2],l[3]));
}

// ---------------- weight transpose + split: in[K,N] -> out planes [N,K] ----
__global__ void tsplit_kernel(const float* __restrict__ in,
                              bf16* __restrict__ oh, bf16* __restrict__ ol,
                              int K, int N) {
    __shared__ float tile[32][33];
    int n0 = blockIdx.x * 32, k0 = blockIdx.y * 32;
    int tx = threadIdx.x, ty = threadIdx.y;
    #pragma unroll
    for (int i = ty; i < 32; i += 8)
        tile[i][tx] = in[(size_t)(k0 + i) * N + n0 + tx];
    __syncthreads();
    #pragma unroll
    for (int i = ty; i < 32; i += 8) {
        float v = tile[tx][i];
        bf16 h, l; split1(v, h, l);
        oh[(size_t)(n0 + i) * K + k0 + tx] = h;
        ol[(size_t)(n0 + i) * K + k0 + tx] = l;
    }
}

// ================= bf16-split HMMA GEMM, B in [N,K] K-major ==============
// C[M,N] = (Ah+Al)[M,K] @ (Bh+Bl)[N,K]^T (+Res); 3 MMAs (hh, hl, lh).
#define BM_  128
#define BN_  128
#define BKK_ 32
#define AST_ 40                 // padded row stride (bf16 elems)
#define TSZ_ (128*AST_)         // per-plane tile (A and B identical: 128 rows)
#define STG_ (4*TSZ_)           // elems per stage: Ah,Al,Bh,Bl
#define BG_SMEM (2*STG_*2)      // bytes: 2 stages

__global__ void __launch_bounds__(256, 2)
bgemm_kernel(const bf16* __restrict__ Ahg, const bf16* __restrict__ Alg,
             const bf16* __restrict__ Bhg, const bf16* __restrict__ Blg,
             const float* __restrict__ Res, float* __restrict__ C,
             int M, int N, int K) {
    extern __shared__ bf16 sm[];

    const int tid  = threadIdx.x;
    const int lane = tid & 31, warp = tid >> 5;
    const int warpM = warp >> 1, warpN = warp & 1;   // 4 x 2 warp grid
    const int bx = blockIdx.x, by = blockIdx.y;      // bx: N tile, by: M tile

    const bf16* Ahb = Ahg + (size_t)by * BM_ * K;
    const bf16* Alb = Alg + (size_t)by * BM_ * K;
    const bf16* Bhb = Bhg + (size_t)bx * BN_ * K;    // row n of [N,K]
    const bf16* Blb = Blg + (size_t)bx * BN_ * K;

    const uint32_t uS = (uint32_t)__cvta_generic_to_shared(sm);

    // loader: each plane 128 rows x 4 chunks(8 bf16) = 512 chunks; 2/thread
    const int lr = tid >> 1, lc = (tid & 1) * 16;    // 2 chunks side by side
    auto load_stage = [&](int st, int k0) {
        uint32_t base = uS + (uint32_t)(st * STG_ * 2);
        uint32_t doff = (uint32_t)((lr * AST_ + lc) * 2);
        const size_t gs = (size_t)lr * K + k0 + lc;
        CP16(base + doff,                Ahb + gs);
        CP16(base + doff + 16,           Ahb + gs + 8);
        CP16(base + TSZ_*2 + doff,       Alb + gs);
        CP16(base + TSZ_*2 + doff + 16,  Alb + gs + 8);
        CP16(base + TSZ_*4 + doff,       Bhb + gs);
        CP16(base + TSZ_*4 + doff + 16,  Bhb + gs + 8);
        CP16(base + TSZ_*6 + doff,       Blb + gs);
        CP16(base + TSZ_*6 + doff + 16,  Blb + gs + 8);
    };

    float acc[2][8][4];
    #pragma unroll
    for (int i = 0; i < 2; i++)
        #pragma unroll
        for (int j = 0; j < 8; j++)
            #pragma unroll
            for (int q = 0; q < 4; q++) acc[i][j][q] = 0.f;

    // fragment addresses
    const int arow = warpM*32 + (lane & 15);
    const int acol = (lane >> 4) * 8;
    const int brow = (lane & 7) | (((lane >> 3) & 1) << 3);
    const int bcol = (lane >> 4) * 8;

    const int kIters = K / BKK_;
    load_stage(0, 0);
    CP_COMMIT();

    for (int it = 0; it < kIters; ++it) {
        if (it + 1 < kIters) {
            load_stage((it+1)&1, (it+1)*BKK_);
            CP_COMMIT();
            CP_WAIT(1);
        } else {
            CP_WAIT(0);
        }
        __syncthreads();
        const uint32_t sb = uS + (uint32_t)((it&1) * STG_ * 2);
        const uint32_t aH = sb, aL = sb + TSZ_*2*1;
        const uint32_t bH = sb + TSZ_*4, bL = sb + TSZ_*6;
        #pragma unroll
        for (int kk = 0; kk < BKK_; kk += 16) {
            uint32_t ah[2][4], al[2][4];
            #pragma unroll
            for (int mt = 0; mt < 2; mt++) {
                uint32_t off = (uint32_t)(((arow + mt*16)*AST_ + kk + acol) * 2);
                LDSM4(ah[mt], aH + off);
                LDSM4(al[mt], aL + off);
            }
            #pragma unroll
            for (int pr = 0; pr < 4; pr++) {
                uint32_t off = (uint32_t)(((warpN*64 + pr*16 + brow)*AST_ + kk + bcol) * 2);
                uint32_t bh[4], bl[4];
                LDSM4(bh, bH + off);
                LDSM4(bl, bL + off);
                #pragma unroll
                for (int mt = 0; mt < 2; mt++) {
                    MMA_BF16(acc[mt][pr*2],   ah[mt], bh[0], bh[2]);
                    MMA_BF16(acc[mt][pr*2],   ah[mt], bl[0], bl[2]);
                    MMA_BF16(acc[mt][pr*2],   al[mt], bh[0], bh[2]);
                    MMA_BF16(acc[mt][pr*2+1], ah[mt], bh[1], bh[3]);
                    MMA_BF16(acc[mt][pr*2+1], ah[mt], bl[1], bl[3]);
                    MMA_BF16(acc[mt][pr*2+1], al[mt], bh[1], bh[3]);
                }
            }
        }
        __syncthreads();
    }

    const int g = lane >> 2, tg = lane & 3;
    #pragma unroll
    for (int mt = 0; mt < 2; mt++) {
        #pragma unroll
        for (int nt = 0; nt < 8; nt++) {
            size_t r0 = (size_t)by*BM_ + warpM*32 + mt*16 + g;
            size_t c  = (size_t)bx*BN_ + warpN*64 + nt*8 + tg*2;
            float2 v0 = make_float2(acc[mt][nt][0], acc[mt][nt][1]);
            float2 v1 = make_float2(acc[mt][nt][2], acc[mt][nt][3]);
            if (Res) {
                float2 q0 = *(const float2*)(Res + r0*N + c);
                float2 q1 = *(const float2*)(Res + (r0+8)*N + c);
                v0.x += q0.x; v0.y += q0.y; v1.x += q1.x; v1.y += q1.y;
            }
            *(float2*)(C + r0*N + c)     = v0;
            *(float2*)(C + (r0+8)*N + c) = v1;
        }
    }
}

// ================= tensor-core flash attention (proven) =================
#define FST 72
#define FQSZ (64*FST)

__global__ void __launch_bounds__(128)
flash_tc_kernel(const bf16* __restrict__ qh, const bf16* __restrict__ ql,
                const bf16* __restrict__ kh, const bf16* __restrict__ kl,
                const bf16* __restrict__ vh, const bf16* __restrict__ vl,
                bf16* __restrict__ ch, bf16* __restrict__ cl) {
    extern __shared__ bf16 fsm[];
    bf16* sQh = fsm;
    bf16* sQl = sQh + FQSZ;
    bf16* sKh = sQl + FQSZ;
    bf16* sKl = sKh + FQSZ;
    bf16* sVh = sKl + FQSZ;
    bf16* sVl = sVh + FQSZ;

    const int q0  = blockIdx.x * 64;
    const int h   = blockIdx.y;
    const int b   = blockIdx.z;
    const int kvh = h / REP_;
    const int tid = threadIdx.x;
    const int lane = tid & 31, warp = tid >> 5;
    const int g = lane >> 2, tg = lane & 3;

    for (int li = tid; li < 512; li += 128) {
        int r = li >> 3, c8 = (li & 7) * 8;
        size_t src = ((size_t)(b * S_ + q0 + r) * D_ + h * HD_ + c8);
        *(uint4*)&sQh[r*FST + c8] = *(const uint4*)(qh + src);
        *(uint4*)&sQl[r*FST + c8] = *(const uint4*)(ql + src);
    }

    float mrow[2] = {-INFINITY, -INFINITY};
    float lrow[2] = {0.f, 0.f};
    float o[8][4] = {};

    const uint32_t uQh = (uint32_t)__cvta_generic_to_shared(sQh);
    const uint32_t uQl = (uint32_t)__cvta_generic_to_shared(sQl);
    const uint32_t uKh = (uint32_t)__cvta_generic_to_shared(sKh);
    const uint32_t uKl = (uint32_t)__cvta_generic_to_shared(sKl);
    const uint32_t uVh = (uint32_t)__cvta_generic_to_shared(sVh);
    const uint32_t uVl = (uint32_t)__cvta_generic_to_shared(sVl);
    const int fr = (lane & 15);
    const int fc = (lane >> 4) * 8;

    const int ntiles = q0 / 64 + 1;
    for (int tI = 0; tI < ntiles; tI++) {
        int kv0 = tI * 64;
        __syncthreads();
        for (int li = tid; li < 512; li += 128) {
            int r = li >> 3, c8 = (li & 7) * 8;
            size_t src = ((size_t)(b * S_ + kv0 + r) * (KVH_*HD_) + kvh * HD_ + c8);
            *(uint4*)&sKh[r*FST + c8] = *(const uint4*)(kh + src);
            *(uint4*)&sKl[r*FST + c8] = *(const uint4*)(kl + src);
            *(uint4*)&sVh[r*FST + c8] = *(const uint4*)(vh + src);
            *(uint4*)&sVl[r*FST + c8] = *(const uint4*)(vl + src);
        }
        __syncthreads();

        float s[8][4] = {};
        #pragma unroll
        for (int kk = 0; kk < 64; kk += 16) {
            uint32_t aqh[4], aql[4];
            uint32_t qoff = (uint32_t)(((warp*16 + fr)*FST + kk + fc) * 2);
            LDSM4(aqh, uQh + qoff);
            LDSM4(aql, uQl + qoff);
            #pragma unroll
            for (int nb = 0; nb < 4; nb++) {
                uint32_t koff = (uint32_t)(((nb*16 + fr)*FST + kk + fc) * 2);
                uint32_t k4h[4], k4l[4];
                LDSM4(k4h, uKh + koff);
                LDSM4(k4l, uKl + koff);
                MMA_BF16(s[nb*2],   aqh, k4h[0], k4h[2]);
                MMA_BF16(s[nb*2],   aqh, k4l[0], k4l[2]);
                MMA_BF16(s[nb*2],   aql, k4h[0], k4h[2]);
                MMA_BF16(s[nb*2+1], aqh, k4h[1], k4h[3]);
                MMA_BF16(s[nb*2+1], aqh, k4l[1], k4l[3]);
                MMA_BF16(s[nb*2+1], aql, k4h[1], k4h[3]);
            }
        }

        if (tI == ntiles - 1) {
            #pragma unroll
            for (int nt = 0; nt < 8; nt++) {
                int col = kv0 + nt*8 + tg*2;
                int r0g = q0 + warp*16 + g;
                if (col     > r0g)   s[nt][0] = -INFINITY;
                if (col + 1 > r0g)   s[nt][1] = -INFINITY;
                if (col     > r0g+8) s[nt][2] = -INFINITY;
                if (col + 1 > r0g+8) s[nt][3] = -INFINITY;
            }
        }

        #pragma unroll
        for (int qi = 0; qi < 2; qi++) {
            float mx = -INFINITY;
            #pragma unroll
            for (int nt = 0; nt < 8; nt++)
                mx = fmaxf(mx, fmaxf(s[nt][qi*2], s[nt][qi*2+1]));
            mx = fmaxf(mx, __shfl_xor_sync(0xffffffffu, mx, 1));
            mx = fmaxf(mx, __shfl_xor_sync(0xffffffffu, mx, 2));
            float mnew = fmaxf(mrow[qi], mx);
            float scale = __expf(mrow[qi] - mnew);
            mrow[qi] = mnew;
            float sum = 0.f;
            #pragma unroll
            for (int nt = 0; nt < 8; nt++) {
                float p0 = __expf(s[nt][qi*2]   - mnew);
                float p1 = __expf(s[nt][qi*2+1] - mnew);
                s[nt][qi*2] = p0; s[nt][qi*2+1] = p1;
                sum += p0 + p1;
            }
            sum += __shfl_xor_sync(0xffffffffu, sum, 1);
            sum += __shfl_xor_sync(0xffffffffu, sum, 2);
            lrow[qi] = lrow[qi]*scale + sum;
            #pragma unroll
            for (int nt = 0; nt < 8; nt++) {
                o[nt][qi*2]   *= scale;
                o[nt][qi*2+1] *= scale;
            }
        }

        #pragma unroll
        for (int ks = 0; ks < 4; ks++) {
            const float* s0 = s[2*ks];
            const float* s1 = s[2*ks+1];
            uint32_t ph[4], pl[4];
            {
                bf16 h0,l0,h1,l1;
                split1(s0[0], h0, l0); split1(s0[1], h1, l1);
                ph[0] = pack2(h0,h1); pl[0] = pack2(l0,l1);
                split1(s0[2], h0, l0); split1(s0[3], h1, l1);
                ph[1] = pack2(h0,h1); pl[1] = pack2(l0,l1);
                split1(s1[0], h0, l0); split1(s1[1], h1, l1);
                ph[2] = pack2(h0,h1); pl[2] = pack2(l0,l1);
                split1(s1[2], h0, l0); split1(s1[3], h1, l1);
                ph[3] = pack2(h0,h1); pl[3] = pack2(l0,l1);
            }
            #pragma unroll
            for (int nb = 0; nb < 4; nb++) {
                uint32_t voff = (uint32_t)(((ks*16 + fr)*FST + nb*16 + fc) * 2);
                uint32_t v4h[4], v4l[4];
                LDSM4T(v4h, uVh + voff);
                LDSM4T(v4l, uVl + voff);
                MMA_BF16(o[nb*2],   ph, v4h[0], v4h[1]);
                MMA_BF16(o[nb*2],   ph, v4l[0], v4l[1]);
                MMA_BF16(o[nb*2],   pl, v4h[0], v4h[1]);
                MMA_BF16(o[nb*2+1], ph, v4h[2], v4h[3]);
                MMA_BF16(o[nb*2+1], ph, v4l[2], v4l[3]);
                MMA_BF16(o[nb*2+1], pl, v4h[2], v4h[3]);
            }
        }
    }

    #pragma unroll
    for (int qi = 0; qi < 2; qi++) {
        float inv = 1.0f / lrow[qi];
        int r = q0 + warp*16 + g + qi*8;
        size_t base = (size_t)(b * S_ + r) * D_ + h * HD_;
        #pragma unroll
        for (int nt = 0; nt < 8; nt++) {
            int c = nt*8 + tg*2;
            float v0 = o[nt][qi*2]   * inv;
            float v1 = o[nt][qi*2+1] * inv;
            bf16 h0,l0,h1,l1;
            split1(v0, h0, l0); split1(v1, h1, l1);
            *(uint32_t*)(ch + base + c) = pack2(h0,h1);
            *(uint32_t*)(cl + base + c) = pack2(l0,l1);
        }
    }
}

// ---------------- host orchestration ----------------
#define FL_SMEM (6 * FQSZ * 2)

static inline void run_bgemm(const bf16* Ah, const bf16* Al,
                             const bf16* Bh, const bf16* Bl,
                             const float* Res, float* C, int M, int N, int K) {
    dim3 grid(N / BN_, M / BM_);
    bgemm_kernel<<<grid, 256, BG_SMEM>>>(Ah, Al, Bh, Bl, Res, C, M, N, K);
}
static inline void run_tsplit(const float* in, bf16* oh, bf16* ol, int K, int N) {
    tsplit_kernel<<<dim3(N/32, K/32), dim3(32, 8)>>>(in, oh, ol, K, N);
}

extern "C" void kernel_launch(void* const* d_in, const int* in_sizes, int n_in,
                              void* d_out, int out_size) {
    const void*  idx    = d_in[0];
    const float* emb    = (const float*)d_in[1];
    const float* wq     = (const float*)d_in[2];
    const float* wk     = (const float*)d_in[3];
    const float* wv     = (const float*)d_in[4];
    const float* wo     = (const float*)d_in[5];
    const float* wgate  = (const float*)d_in[6];
    const float* wup    = (const float*)d_in[7];
    const float* wdown  = (const float*)d_in[8];
    const float* na     = (const float*)d_in[9];
    const float* nf     = (const float*)d_in[10];
    const float* nfin   = (const float*)d_in[11];
    const float* wout   = (const float*)d_in[12];

    float *x, *qkv, *gu;
    cudaGetSymbolAddress((void**)&x,   g_x);
    cudaGetSymbolAddress((void**)&qkv, g_qkv);
    cudaGetSymbolAddress((void**)&gu,  g_gu);

    bf16 *nh,*nl,*qh,*ql,*kh,*kl,*vh,*vl,*ch,*cl,*gh,*gl;
    cudaGetSymbolAddress((void**)&nh, g_nh); cudaGetSymbolAddress((void**)&nl, g_nl);
    cudaGetSymbolAddress((void**)&qh, g_qh); cudaGetSymbolAddress((void**)&ql, g_ql);
    cudaGetSymbolAddress((void**)&kh, g_kh); cudaGetSymbolAddress((void**)&kl, g_kl);
    cudaGetSymbolAddress((void**)&vh, g_vh); cudaGetSymbolAddress((void**)&vl, g_vl);
    cudaGetSymbolAddress((void**)&ch, g_ch); cudaGetSymbolAddress((void**)&cl, g_cl);
    cudaGetSymbolAddress((void**)&gh, g_gh); cudaGetSymbolAddress((void**)&gl, g_gl);

    bf16 *wqkvT_h,*wqkvT_l,*woT_h,*woT_l,*wguT_h,*wguT_l,*wdT_h,*wdT_l,*woutT_h,*woutT_l;
    cudaGetSymbolAddress((void**)&wqkvT_h, g_wqkvT_h); cudaGetSymbolAddress((void**)&wqkvT_l, g_wqkvT_l);
    cudaGetSymbolAddress((void**)&woT_h,  g_woT_h);   cudaGetSymbolAddress((void**)&woT_l,  g_woT_l);
    cudaGetSymbolAddress((void**)&wguT_h, g_wguT_h);  cudaGetSymbolAddress((void**)&wguT_l, g_wguT_l);
    cudaGetSymbolAddress((void**)&wdT_h,  g_wdT_h);   cudaGetSymbolAddress((void**)&wdT_l,  g_wdT_l);
    cudaGetSymbolAddress((void**)&woutT_h,g_woutT_h); cudaGetSymbolAddress((void**)&woutT_l,g_woutT_l);

    cudaFuncSetAttribute(bgemm_kernel,
                         cudaFuncAttributeMaxDynamicSharedMemorySize, BG_SMEM);
    cudaFuncSetAttribute(flash_tc_kernel,
                         cudaFuncAttributeMaxDynamicSharedMemorySize, FL_SMEM);

    // weight transpose+split into fused [N,K] plane buffers
    for (int l = 0; l < L_; l++) {
        size_t qo = (size_t)l * QKV_ * D_;
        run_tsplit(wq + (size_t)l*D_*D_,   wqkvT_h + qo,                   wqkvT_l + qo,                   D_, D_);
        run_tsplit(wk + (size_t)l*D_*256,  wqkvT_h + qo + (size_t)1024*D_, wqkvT_l + qo + (size_t)1024*D_, D_, 256);
        run_tsplit(wv + (size_t)l*D_*256,  wqkvT_h + qo + (size_t)1280*D_, wqkvT_l + qo + (size_t)1280*D_, D_, 256);
        run_tsplit(wo + (size_t)l*D_*D_,   woT_h + (size_t)l*D_*D_,        woT_l + (size_t)l*D_*D_,        D_, D_);
        size_t go = (size_t)l * GU_ * D_;
        run_tsplit(wgate + (size_t)l*D_*F_, wguT_h + go,                   wguT_l + go,                   D_, F_);
        run_tsplit(wup   + (size_t)l*D_*F_, wguT_h + go + (size_t)F_*D_,   wguT_l + go + (size_t)F_*D_,   D_, F_);
        run_tsplit(wdown + (size_t)l*F_*D_, wdT_h + (size_t)l*D_*F_,       wdT_l + (size_t)l*D_*F_,       F_, D_);
    }
    run_tsplit(wout, woutT_h, woutT_l, D_, V_);

    detect_idx_kernel<<<1, 256>>>((const int*)idx);
    embed_kernel<<<T_, 256>>>(idx, emb);

    for (int l = 0; l < L_; l++) {
        size_t qo = (size_t)l * QKV_ * D_;
        size_t go = (size_t)l * GU_ * D_;
        rmsnorm_split_kernel<<<T_, 256>>>(x, na + (size_t)l * D_, nh, nl);
        run_bgemm(nh, nl, wqkvT_h + qo, wqkvT_l + qo, nullptr, qkv, T_, QKV_, D_);
        rope_split_kernel<<<T_, H_*32>>>(qkv, QKV_, 0, qh, ql, H_, SCALE_);
        rope_split_kernel<<<T_, KVH_*32>>>(qkv, QKV_, 1024, kh, kl, KVH_, 1.0f);
        vsplit_kernel<<<T_, 64>>>(qkv, vh, vl);
        flash_tc_kernel<<<dim3(S_/64, H_, B_), 128, FL_SMEM>>>(qh,ql,kh,kl,vh,vl,ch,cl);
        run_bgemm(ch, cl, woT_h + (size_t)l*D_*D_, woT_l + (size_t)l*D_*D_, x, x, T_, D_, D_);
        rmsnorm_split_kernel<<<T_, 256>>>(x, nf + (size_t)l * D_, nh, nl);
        run_bgemm(nh, nl, wguT_h + go, wguT_l + go, nullptr, gu, T_, GU_, D_);
        silu_split_kernel<<<(T_*F_/4)/256, 256>>>(gu, gh, gl);
        run_bgemm(gh, gl, wdT_h + (size_t)l*D_*F_, wdT_l + (size_t)l*D_*F_, x, x, T_, D_, F_);
    }

    rmsnorm_split_kernel<<<T_, 256>>>(x, nfin, nh, nl);
    run_bgemm(nh, nl, woutT_h, woutT_l, nullptr, (float*)d_out, T_, V_, D_);
}

// round 6
// speedup vs baseline: 1.2717x; 1.2717x over previous
#include <cuda_runtime.h>
#include <cuda_bf16.h>
#include <math.h>
#include <stdint.h>

// ---------------- problem constants ----------------
#define V_   32000
#define D_   1024
#define H_   16
#define KVH_ 4
#define HD_  64
#define F_   4096
#define L_   2
#define B_   2
#define S_   2048
#define T_   (B_*S_)
#define REP_ (H_/KVH_)
#define EPS_ 1e-5f
#define SCALE_ 0.125f
#define QKV_ 1536            // fused q|k|v width
#define GU_  8192            // fused gate|up width

typedef __nv_bfloat16 bf16;

// ---------------- scratch ----------------
__device__ float g_x  [T_*D_];
__device__ float g_qkv[T_*QKV_];
__device__ float g_gu [T_*GU_];
__device__ int   g_is64;

// activation bf16 planes
__device__ bf16 g_nh[T_*D_],  g_nl[T_*D_];
__device__ bf16 g_qh[T_*D_],  g_ql[T_*D_];
__device__ bf16 g_kh[T_*KVH_*HD_], g_kl[T_*KVH_*HD_];
__device__ bf16 g_vh[T_*KVH_*HD_], g_vl[T_*KVH_*HD_];
__device__ bf16 g_ch[T_*D_],  g_cl[T_*D_];
__device__ bf16 g_gh[T_*F_],  g_gl[T_*F_];

// weight planes, [K, N] layout (same as input, bf16 hi/lo), fused along N
__device__ bf16 g_wqkvB_h[L_*D_*QKV_], g_wqkvB_l[L_*D_*QKV_];
__device__ bf16 g_woB_h  [L_*D_*D_],   g_woB_l  [L_*D_*D_];
__device__ bf16 g_wguB_h [L_*D_*GU_],  g_wguB_l [L_*D_*GU_];
__device__ bf16 g_wdB_h  [L_*F_*D_],   g_wdB_l  [L_*F_*D_];
__device__ bf16 g_woutB_h[D_*V_],      g_woutB_l[D_*V_];

// ---------------- helpers ----------------
__device__ __forceinline__ uint32_t pack2(bf16 a, bf16 b) {
    __nv_bfloat162 t = __halves2bfloat162(a, b);
    return *reinterpret_cast<uint32_t*>(&t);
}
__device__ __forceinline__ void split1(float v, bf16& h, bf16& l) {
    h = __float2bfloat16(v);
    l = __float2bfloat16(v - __bfloat162float(h));
}

#define LDSM4(r, addr) \
    asm volatile("ldmatrix.sync.aligned.m8n8.x4.shared.b16 {%0,%1,%2,%3}, [%4];" \
        : "=r"((r)[0]), "=r"((r)[1]), "=r"((r)[2]), "=r"((r)[3]) : "r"(addr))
#define LDSM4T(r, addr) \
    asm volatile("ldmatrix.sync.aligned.m8n8.x4.trans.shared.b16 {%0,%1,%2,%3}, [%4];" \
        : "=r"((r)[0]), "=r"((r)[1]), "=r"((r)[2]), "=r"((r)[3]) : "r"(addr))
#define MMA_BF16(acc, a, b0, b1) \
    asm volatile("mma.sync.aligned.m16n8k16.row.col.f32.bf16.bf16.f32 " \
        "{%0,%1,%2,%3}, {%4,%5,%6,%7}, {%8,%9}, {%0,%1,%2,%3};" \
        : "+f"((acc)[0]), "+f"((acc)[1]), "+f"((acc)[2]), "+f"((acc)[3]) \
        : "r"((a)[0]), "r"((a)[1]), "r"((a)[2]), "r"((a)[3]), "r"(b0), "r"(b1))
#define CP16(dst, src) \
    asm volatile("cp.async.cg.shared.global [%0], [%1], 16;\n" :: "r"(dst), "l"(src) : "memory")
#define CP_COMMIT() asm volatile("cp.async.commit_group;\n" ::: "memory")
#define CP_WAIT(n)  asm volatile("cp.async.wait_group %0;\n" :: "n"(n) : "memory")

// ---------------- fp32 -> bf16 hi/lo split (4 float4 per thread) --------
__global__ void split_kernel(const float* __restrict__ in,
                             bf16* __restrict__ hi, bf16* __restrict__ lo, int n4) {
    int i0 = (blockIdx.x * blockDim.x + threadIdx.x) * 4;
    float4 v[4];
    #pragma unroll
    for (int j = 0; j < 4; j++)
        if (i0 + j < n4) v[j] = ((const float4*)in)[i0 + j];
    #pragma unroll
    for (int j = 0; j < 4; j++) {
        if (i0 + j >= n4) break;
        float vv[4] = {v[j].x, v[j].y, v[j].z, v[j].w};
        bf16 h[4], l[4];
        #pragma unroll
        for (int q = 0; q < 4; q++) split1(vv[q], h[q], l[q]);
        ((uint2*)hi)[i0 + j] = make_uint2(pack2(h[0],h[1]), pack2(h[2],h[3]));
        ((uint2*)lo)[i0 + j] = make_uint2(pack2(l[0],l[1]), pack2(l[2],l[3]));
    }
}

// ---- strided split: in[K,Nin] -> out planes[K,Nout] at column cOff -----
__global__ void splitw_kernel(const float* __restrict__ in,
                              bf16* __restrict__ oh, bf16* __restrict__ ol,
                              int Nin, int Nout, int cOff, int n4) {
    int i0 = (blockIdx.x * blockDim.x + threadIdx.x) * 4;
    int rc4 = Nin >> 2;
    #pragma unroll
    for (int j = 0; j < 4; j++) {
        int i = i0 + j;
        if (i >= n4) break;
        int r = i / rc4, c4 = i - r * rc4;
        float4 v = ((const float4*)in)[i];
        float vv[4] = {v.x, v.y, v.z, v.w};
        bf16 h[4], l[4];
        #pragma unroll
        for (int q = 0; q < 4; q++) split1(vv[q], h[q], l[q]);
        size_t oi = ((size_t)r * Nout + cOff) / 4 + c4;
        ((uint2*)oh)[oi] = make_uint2(pack2(h[0],h[1]), pack2(h[2],h[3]));
        ((uint2*)ol)[oi] = make_uint2(pack2(l[0],l[1]), pack2(l[2],l[3]));
    }
}

// ---------------- idx detection + embed ----------------
__global__ void detect_idx_kernel(const int* idx) {
    __shared__ int ok;
    if (threadIdx.x == 0) ok = 1;
    __syncthreads();
    int bad = 0;
    for (int i = threadIdx.x; i < T_/2; i += blockDim.x)
        if (idx[2*i + 1] != 0) bad = 1;
    if (bad) atomicAnd(&ok, 0);
    __syncthreads();
    if (threadIdx.x == 0) g_is64 = ok;
}
__global__ void embed_kernel(const void* idx, const float* __restrict__ emb) {
    int t = blockIdx.x;
    int tok = g_is64 ? (int)((const long long*)idx)[t] : ((const int*)idx)[t];
    ((float4*)(g_x + (size_t)t * D_))[threadIdx.x] =
        ((const float4*)(emb + (size_t)tok * D_))[threadIdx.x];
}

// ---------------- RMSNorm -> bf16 planes ----------------
__global__ void rmsnorm_split_kernel(const float* __restrict__ x,
                                     const float* __restrict__ w,
                                     bf16* __restrict__ oh, bf16* __restrict__ ol) {
    int t = blockIdx.x;
    __shared__ float red[8];
    float4 v = ((const float4*)(x + (size_t)t * D_))[threadIdx.x];
    float ss = v.x*v.x + v.y*v.y + v.z*v.z + v.w*v.w;
    #pragma unroll
    for (int o = 16; o > 0; o >>= 1) ss += __shfl_xor_sync(0xffffffffu, ss, o);
    if ((threadIdx.x & 31) == 0) red[threadIdx.x >> 5] = ss;
    __syncthreads();
    if (threadIdx.x < 8) {
        float s = red[threadIdx.x];
        #pragma unroll
        for (int o = 4; o > 0; o >>= 1) s += __shfl_xor_sync(0xffu, s, o);
        if (threadIdx.x == 0) red[0] = s;
    }
    __syncthreads();
    float inv = rsqrtf(red[0] * (1.0f / D_) + EPS_);
    float4 wv = ((const float4*)w)[threadIdx.x];
    float vv[4] = {v.x*inv*wv.x, v.y*inv*wv.y, v.z*inv*wv.z, v.w*inv*wv.w};
    bf16 h[4], l[4];
    #pragma unroll
    for (int j = 0; j < 4; j++) split1(vv[j], h[j], l[j]);
    ((uint2*)(oh + (size_t)t*D_))[threadIdx.x] = make_uint2(pack2(h[0],h[1]), pack2(h[2],h[3]));
    ((uint2*)(ol + (size_t)t*D_))[threadIdx.x] = make_uint2(pack2(l[0],l[1]), pack2(l[2],l[3]));
}

// ---------------- RoPE (strided in) -> dense bf16 planes ----------------
__global__ void rope_split_kernel(const float* __restrict__ x, int xStride, int xOff,
                                  bf16* __restrict__ xh, bf16* __restrict__ xl,
                                  int nheads, float scl) {
    int t   = blockIdx.x;
    int pos = t % S_;
    int j   = threadIdx.x & 31;
    int h   = threadIdx.x >> 5;
    float invf = powf(500000.0f, -(float)(2 * j) / (float)HD_);
    float ang = (float)pos * invf;
    float s, c;
    sincosf(ang, &s, &c);
    const float* p = x + (size_t)t * xStride + xOff + h * HD_;
    size_t ob = (size_t)t * nheads * HD_ + h * HD_;
    float a = p[j], b = p[j + 32];
    float r0 = (a * c - b * s) * scl;
    float r1 = (b * c + a * s) * scl;
    bf16 h0, l0, h1, l1;
    split1(r0, h0, l0); split1(r1, h1, l1);
    xh[ob + j] = h0; xl[ob + j] = l0;
    xh[ob + j + 32] = h1; xl[ob + j + 32] = l1;
}

// ---------------- strided V split ----------------
__global__ void vsplit_kernel(const float* __restrict__ x,
                              bf16* __restrict__ oh, bf16* __restrict__ ol) {
    int t = blockIdx.x, i = threadIdx.x;   // 64 threads * float4 = 256
    float4 v = *(const float4*)(x + (size_t)t*QKV_ + 1280 + i*4);
    float vv[4] = {v.x, v.y, v.z, v.w};
    bf16 h[4], l[4];
    #pragma unroll
    for (int j = 0; j < 4; j++) split1(vv[j], h[j], l[j]);
    ((uint2*)(oh + (size_t)t*256))[i] = make_uint2(pack2(h[0],h[1]), pack2(h[2],h[3]));
    ((uint2*)(ol + (size_t)t*256))[i] = make_uint2(pack2(l[0],l[1]), pack2(l[2],l[3]));
}

// ---------------- SwiGLU from fused gu buffer -> bf16 planes ------------
__global__ void silu_split_kernel(const float* __restrict__ gu,
                                  bf16* __restrict__ oh, bf16* __restrict__ ol) {
    int i = blockIdx.x * blockDim.x + threadIdx.x;   // float4 idx over T*F
    int e = i * 4;
    int t = e >> 12;         // / F_
    int f = e & 4095;
    float4 g4 = *(const float4*)(gu + (size_t)t*GU_ + f);
    float4 u4 = *(const float4*)(gu + (size_t)t*GU_ + 4096 + f);
    float vv[4];
    vv[0] = g4.x / (1.f + __expf(-g4.x)) * u4.x;
    vv[1] = g4.y / (1.f + __expf(-g4.y)) * u4.y;
    vv[2] = g4.z / (1.f + __expf(-g4.z)) * u4.z;
    vv[3] = g4.w / (1.f + __expf(-g4.w)) * u4.w;
    bf16 h[4], l[4];
    #pragma unroll
    for (int j = 0; j < 4; j++) split1(vv[j], h[j], l[j]);
    ((uint2*)oh)[i] = make_uint2(pack2(h[0],h[1]), pack2(h[2],h[3]));
    ((uint2*)ol)[i] = make_uint2(pack2(l[0],l[1]), pack2(l[2],l[3]));
}

// ================= bf16-split HMMA GEMM (R3 proven core) ================
// C[M,N] = (Ah+Al)[M,K] @ (Bh+Bl)[K,N] (+Res); 3 MMAs (hh, hl, lh).
#define BM_  128
#define BN_  128
#define BKK_ 32
#define AST_ 40
#define BST_ 136
#define ASZ_ (BM_*AST_)
#define BSZ_ (BKK_*BST_)
#define BG_SMEM ((2*ASZ_*2 + 2*BSZ_*2) * 2)

__global__ void __launch_bounds__(256)
bgemm_kernel(const bf16* __restrict__ Ahg, const bf16* __restrict__ Alg,
             const bf16* __restrict__ Bhg, const bf16* __restrict__ Blg,
             const float* __restrict__ Res, float* __restrict__ C,
             int M, int N, int K) {
    extern __shared__ bf16 sm[];
    bf16* sAh = sm;                 // 2 stages
    bf16* sAl = sAh + 2*ASZ_;
    bf16* sBh = sAl + 2*ASZ_;
    bf16* sBl = sBh + 2*BSZ_;

    const int tid  = threadIdx.x;
    const int lane = tid & 31, warp = tid >> 5;
    const int warpM = warp >> 1, warpN = warp & 1;
    const int bx = blockIdx.x, by = blockIdx.y;

    const bf16* Ahb = Ahg + (size_t)by * BM_ * K;
    const bf16* Alb = Alg + (size_t)by * BM_ * K;
    const bf16* Bhb = Bhg + (size_t)bx * BN_;
    const bf16* Blb = Blg + (size_t)bx * BN_;

    const uint32_t uAh = (uint32_t)__cvta_generic_to_shared(sAh);
    const uint32_t uAl = (uint32_t)__cvta_generic_to_shared(sAl);
    const uint32_t uBh = (uint32_t)__cvta_generic_to_shared(sBh);
    const uint32_t uBl = (uint32_t)__cvta_generic_to_shared(sBl);

    const int ar = tid >> 2, ac = (tid & 3) * 8;
    const int br = tid >> 4, bc = (tid & 15) * 8;

    auto load_stage = [&](int st, int k0) {
        #pragma unroll
        for (int p = 0; p < 2; p++) {
            int r = ar + p*64;
            uint32_t d = (uint32_t)((st*ASZ_ + r*AST_ + ac) * 2);
            CP16(uAh + d, Ahb + (size_t)r*K + k0 + ac);
            CP16(uAl + d, Alb + (size_t)r*K + k0 + ac);
        }
        #pragma unroll
        for (int p = 0; p < 2; p++) {
            int r = br + p*16;
            uint32_t d = (uint32_t)((st*BSZ_ + r*BST_ + bc) * 2);
            CP16(uBh + d, Bhb + (size_t)(k0 + r)*N + bc);
            CP16(uBl + d, Blb + (size_t)(k0 + r)*N + bc);
        }
    };

    float acc[2][8][4];
    #pragma unroll
    for (int i = 0; i < 2; i++)
        #pragma unroll
        for (int j = 0; j < 8; j++)
            #pragma unroll
            for (int q = 0; q < 4; q++) acc[i][j][q] = 0.f;

    const int arow = warpM*32 + (lane & 15);
    const int acol = (lane >> 4) * 8;
    const int brow = (lane & 15);
    const int bcol = warpN*64 + (lane >> 4) * 8;

    const int kIters = K / BKK_;
    load_stage(0, 0);
    CP_COMMIT();

    for (int it = 0; it < kIters; ++it) {
        if (it + 1 < kIters) {
            load_stage((it+1)&1, (it+1)*BKK_);
            CP_COMMIT();
            CP_WAIT(1);
        } else {
            CP_WAIT(0);
        }
        __syncthreads();
        const int st = it & 1;
        const uint32_t aH = uAh + (uint32_t)(st*ASZ_*2);
        const uint32_t aL = uAl + (uint32_t)(st*ASZ_*2);
        const uint32_t bH = uBh + (uint32_t)(st*BSZ_*2);
        const uint32_t bL = uBl + (uint32_t)(st*BSZ_*2);
        #pragma unroll
        for (int kk = 0; kk < BKK_; kk += 16) {
            uint32_t ah[2][4], al[2][4];
            #pragma unroll
            for (int mt = 0; mt < 2; mt++) {
                uint32_t off = (uint32_t)(((arow + mt*16)*AST_ + kk + acol) * 2);
                LDSM4(ah[mt], aH + off);
                LDSM4(al[mt], aL + off);
            }
            #pragma unroll
            for (int pr = 0; pr < 4; pr++) {
                uint32_t off = (uint32_t)(((brow + kk)*BST_ + bcol + pr*16) * 2);
                uint32_t bh[4], bl[4];
                LDSM4T(bh, bH + off);
                LDSM4T(bl, bL + off);
                #pragma unroll
                for (int mt = 0; mt < 2; mt++) {
                    #pragma unroll
                    for (int h2 = 0; h2 < 2; h2++) {
                        int nt = pr*2 + h2;
                        MMA_BF16(acc[mt][nt], ah[mt], bh[h2*2], bh[h2*2+1]);
                        MMA_BF16(acc[mt][nt], ah[mt], bl[h2*2], bl[h2*2+1]);
                        MMA_BF16(acc[mt][nt], al[mt], bh[h2*2], bh[h2*2+1]);
                    }
                }
            }
        }
        __syncthreads();
    }

    const int g = lane >> 2, tg = lane & 3;
    #pragma unroll
    for (int mt = 0; mt < 2; mt++) {
        #pragma unroll
        for (int nt = 0; nt < 8; nt++) {
            size_t r0 = (size_t)by*BM_ + warpM*32 + mt*16 + g;
            size_t c  = (size_t)bx*BN_ + warpN*64 + nt*8 + tg*2;
            float2 v0 = make_float2(acc[mt][nt][0], acc[mt][nt][1]);
            float2 v1 = make_float2(acc[mt][nt][2], acc[mt][nt][3]);
            if (Res) {
                float2 q0 = *(const float2*)(Res + r0*N + c);
                float2 q1 = *(const float2*)(Res + (r0+8)*N + c);
                v0.x += q0.x; v0.y += q0.y; v1.x += q1.x; v1.y += q1.y;
            }
            *(float2*)(C + r0*N + c)     = v0;
            *(float2*)(C + (r0+8)*N + c) = v1;
        }
    }
}

// ================= tensor-core flash attention (proven) =================
#define FST 72
#define FQSZ (64*FST)

__global__ void __launch_bounds__(128)
flash_tc_kernel(const bf16* __restrict__ qh, const bf16* __restrict__ ql,
                const bf16* __restrict__ kh, const bf16* __restrict__ kl,
                const bf16* __restrict__ vh, const bf16* __restrict__ vl,
                bf16* __restrict__ ch, bf16* __restrict__ cl) {
    extern __shared__ bf16 fsm[];
    bf16* sQh = fsm;
    bf16* sQl = sQh + FQSZ;
    bf16* sKh = sQl + FQSZ;
    bf16* sKl = sKh + FQSZ;
    bf16* sVh = sKl + FQSZ;
    bf16* sVl = sVh + FQSZ;

    const int q0  = blockIdx.x * 64;
    const int h   = blockIdx.y;
    const int b   = blockIdx.z;
    const int kvh = h / REP_;
    const int tid = threadIdx.x;
    const int lane = tid & 31, warp = tid >> 5;
    const int g = lane >> 2, tg = lane & 3;

    for (int li = tid; li < 512; li += 128) {
        int r = li >> 3, c8 = (li & 7) * 8;
        size_t src = ((size_t)(b * S_ + q0 + r) * D_ + h * HD_ + c8);
        *(uint4*)&sQh[r*FST + c8] = *(const uint4*)(qh + src);
        *(uint4*)&sQl[r*FST + c8] = *(const uint4*)(ql + src);
    }

    float mrow[2] = {-INFINITY, -INFINITY};
    float lrow[2] = {0.f, 0.f};
    float o[8][4] = {};

    const uint32_t uQh = (uint32_t)__cvta_generic_to_shared(sQh);
    const uint32_t uQl = (uint32_t)__cvta_generic_to_shared(sQl);
    const uint32_t uKh = (uint32_t)__cvta_generic_to_shared(sKh);
    const uint32_t uKl = (uint32_t)__cvta_generic_to_shared(sKl);
    const uint32_t uVh = (uint32_t)__cvta_generic_to_shared(sVh);
    const uint32_t uVl = (uint32_t)__cvta_generic_to_shared(sVl);
    const int fr = (lane & 15);
    const int fc = (lane >> 4) * 8;

    const int ntiles = q0 / 64 + 1;
    for (int tI = 0; tI < ntiles; tI++) {
        int kv0 = tI * 64;
        __syncthreads();
        for (int li = tid; li < 512; li += 128) {
            int r = li >> 3, c8 = (li & 7) * 8;
            size_t src = ((size_t)(b * S_ + kv0 + r) * (KVH_*HD_) + kvh * HD_ + c8);
            *(uint4*)&sKh[r*FST + c8] = *(const uint4*)(kh + src);
            *(uint4*)&sKl[r*FST + c8] = *(const uint4*)(kl + src);
            *(uint4*)&sVh[r*FST + c8] = *(const uint4*)(vh + src);
            *(uint4*)&sVl[r*FST + c8] = *(const uint4*)(vl + src);
        }
        __syncthreads();

        float s[8][4] = {};
        #pragma unroll
        for (int kk = 0; kk < 64; kk += 16) {
            uint32_t aqh[4], aql[4];
            uint32_t qoff = (uint32_t)(((warp*16 + fr)*FST + kk + fc) * 2);
            LDSM4(aqh, uQh + qoff);
            LDSM4(aql, uQl + qoff);
            #pragma unroll
            for (int nb = 0; nb < 4; nb++) {
                uint32_t koff = (uint32_t)(((nb*16 + fr)*FST + kk + fc) * 2);
                uint32_t k4h[4], k4l[4];
                LDSM4(k4h, uKh + koff);
                LDSM4(k4l, uKl + koff);
                MMA_BF16(s[nb*2],   aqh, k4h[0], k4h[2]);
                MMA_BF16(s[nb*2],   aqh, k4l[0], k4l[2]);
                MMA_BF16(s[nb*2],   aql, k4h[0], k4h[2]);
                MMA_BF16(s[nb*2+1], aqh, k4h[1], k4h[3]);
                MMA_BF16(s[nb*2+1], aqh, k4l[1], k4l[3]);
                MMA_BF16(s[nb*2+1], aql, k4h[1], k4h[3]);
            }
        }

        if (tI == ntiles - 1) {
            #pragma unroll
            for (int nt = 0; nt < 8; nt++) {
                int col = kv0 + nt*8 + tg*2;
                int r0g = q0 + warp*16 + g;
                if (col     > r0g)   s[nt][0] = -INFINITY;
                if (col + 1 > r0g)   s[nt][1] = -INFINITY;
                if (col     > r0g+8) s[nt][2] = -INFINITY;
                if (col + 1 > r0g+8) s[nt][3] = -INFINITY;
            }
        }

        #pragma unroll
        for (int qi = 0; qi < 2; qi++) {
            float mx = -INFINITY;
            #pragma unroll
            for (int nt = 0; nt < 8; nt++)
                mx = fmaxf(mx, fmaxf(s[nt][qi*2], s[nt][qi*2+1]));
            mx = fmaxf(mx, __shfl_xor_sync(0xffffffffu, mx, 1));
            mx = fmaxf(mx, __shfl_xor_sync(0xffffffffu, mx, 2));
            float mnew = fmaxf(mrow[qi], mx);
            float scale = __expf(mrow[qi] - mnew);
            mrow[qi] = mnew;
            float sum = 0.f;
            #pragma unroll
            for (int nt = 0; nt < 8; nt++) {
                float p0 = __expf(s[nt][qi*2]   - mnew);
                float p1 = __expf(s[nt][qi*2+1] - mnew);
                s[nt][qi*2] = p0; s[nt][qi*2+1] = p1;
                sum += p0 + p1;
            }
            sum += __shfl_xor_sync(0xffffffffu, sum, 1);
            sum += __shfl_xor_sync(0xffffffffu, sum, 2);
            lrow[qi] = lrow[qi]*scale + sum;
            #pragma unroll
            for (int nt = 0; nt < 8; nt++) {
                o[nt][qi*2]   *= scale;
                o[nt][qi*2+1] *= scale;
            }
        }

        #pragma unroll
        for (int ks = 0; ks < 4; ks++) {
            const float* s0 = s[2*ks];
            const float* s1 = s[2*ks+1];
            uint32_t ph[4], pl[4];
            {
                bf16 h0,l0,h1,l1;
                split1(s0[0], h0, l0); split1(s0[1], h1, l1);
                ph[0] = pack2(h0,h1); pl[0] = pack2(l0,l1);
                split1(s0[2], h0, l0); split1(s0[3], h1, l1);
                ph[1] = pack2(h0,h1); pl[1] = pack2(l0,l1);
                split1(s1[0], h0, l0); split1(s1[1], h1, l1);
                ph[2] = pack2(h0,h1); pl[2] = pack2(l0,l1);
                split1(s1[2], h0, l0); split1(s1[3], h1, l1);
                ph[3] = pack2(h0,h1); pl[3] = pack2(l0,l1);
            }
            #pragma unroll
            for (int nb = 0; nb < 4; nb++) {
                uint32_t voff = (uint32_t)(((ks*16 + fr)*FST + nb*16 + fc) * 2);
                uint32_t v4h[4], v4l[4];
                LDSM4T(v4h, uVh + voff);
                LDSM4T(v4l, uVl + voff);
                MMA_BF16(o[nb*2],   ph, v4h[0], v4h[1]);
                MMA_BF16(o[nb*2],   ph, v4l[0], v4l[1]);
                MMA_BF16(o[nb*2],   pl, v4h[0], v4h[1]);
                MMA_BF16(o[nb*2+1], ph, v4h[2], v4h[3]);
                MMA_BF16(o[nb*2+1], ph, v4l[2], v4l[3]);
                MMA_BF16(o[nb*2+1], pl, v4h[2], v4h[3]);
            }
        }
    }

    #pragma unroll
    for (int qi = 0; qi < 2; qi++) {
        float inv = 1.0f / lrow[qi];
        int r = q0 + warp*16 + g + qi*8;
        size_t base = (size_t)(b * S_ + r) * D_ + h * HD_;
        #pragma unroll
        for (int nt = 0; nt < 8; nt++) {
            int c = nt*8 + tg*2;
            float v0 = o[nt][qi*2]   * inv;
            float v1 = o[nt][qi*2+1] * inv;
            bf16 h0,l0,h1,l1;
            split1(v0, h0, l0); split1(v1, h1, l1);
            *(uint32_t*)(ch + base + c) = pack2(h0,h1);
            *(uint32_t*)(cl + base + c) = pack2(l0,l1);
        }
    }
}

// ---------------- host orchestration ----------------
#define FL_SMEM (6 * FQSZ * 2)

static inline void run_bgemm(const bf16* Ah, const bf16* Al,
                             const bf16* Bh, const bf16* Bl,
                             const float* Res, float* C, int M, int N, int K) {
    dim3 grid(N / BN_, M / BM_);
    bgemm_kernel<<<grid, 256, BG_SMEM>>>(Ah, Al, Bh, Bl, Res, C, M, N, K);
}
static inline void run_split(const float* src, bf16* h, bf16* l, size_t n) {
    int n4 = (int)(n / 4);
    int thr = (n4 + 3) / 4;
    split_kernel<<<(thr + 255) / 256, 256>>>(src, h, l, n4);
}
static inline void run_splitw(const float* src, bf16* h, bf16* l,
                              int K, int Nin, int Nout, int cOff) {
    int n4 = K * Nin / 4;
    int thr = (n4 + 3) / 4;
    splitw_kernel<<<(thr + 255) / 256, 256>>>(src, h, l, Nin, Nout, cOff, n4);
}

extern "C" void kernel_launch(void* const* d_in, const int* in_sizes, int n_in,
                              void* d_out, int out_size) {
    const void*  idx    = d_in[0];
    const float* emb    = (const float*)d_in[1];
    const float* wq     = (const float*)d_in[2];
    const float* wk     = (const float*)d_in[3];
    const float* wv     = (const float*)d_in[4];
    const float* wo     = (const float*)d_in[5];
    const float* wgate  = (const float*)d_in[6];
    const float* wup    = (const float*)d_in[7];
    const float* wdown  = (const float*)d_in[8];
    const float* na     = (const float*)d_in[9];
    const float* nf     = (const float*)d_in[10];
    const float* nfin   = (const float*)d_in[11];
    const float* wout   = (const float*)d_in[12];

    float *x, *qkv, *gu;
    cudaGetSymbolAddress((void**)&x,   g_x);
    cudaGetSymbolAddress((void**)&qkv, g_qkv);
    cudaGetSymbolAddress((void**)&gu,  g_gu);

    bf16 *nh,*nl,*qh,*ql,*kh,*kl,*vh,*vl,*ch,*cl,*gh,*gl;
    cudaGetSymbolAddress((void**)&nh, g_nh); cudaGetSymbolAddress((void**)&nl, g_nl);
    cudaGetSymbolAddress((void**)&qh, g_qh); cudaGetSymbolAddress((void**)&ql, g_ql);
    cudaGetSymbolAddress((void**)&kh, g_kh); cudaGetSymbolAddress((void**)&kl, g_kl);
    cudaGetSymbolAddress((void**)&vh, g_vh); cudaGetSymbolAddress((void**)&vl, g_vl);
    cudaGetSymbolAddress((void**)&ch, g_ch); cudaGetSymbolAddress((void**)&cl, g_cl);
    cudaGetSymbolAddress((void**)&gh, g_gh); cudaGetSymbolAddress((void**)&gl, g_gl);

    bf16 *wqkvB_h,*wqkvB_l,*woB_h,*woB_l,*wguB_h,*wguB_l,*wdB_h,*wdB_l,*woutB_h,*woutB_l;
    cudaGetSymbolAddress((void**)&wqkvB_h, g_wqkvB_h); cudaGetSymbolAddress((void**)&wqkvB_l, g_wqkvB_l);
    cudaGetSymbolAddress((void**)&woB_h,  g_woB_h);   cudaGetSymbolAddress((void**)&woB_l,  g_woB_l);
    cudaGetSymbolAddress((void**)&wguB_h, g_wguB_h);  cudaGetSymbolAddress((void**)&wguB_l, g_wguB_l);
    cudaGetSymbolAddress((void**)&wdB_h,  g_wdB_h);   cudaGetSymbolAddress((void**)&wdB_l,  g_wdB_l);
    cudaGetSymbolAddress((void**)&woutB_h,g_woutB_h); cudaGetSymbolAddress((void**)&woutB_l,g_woutB_l);

    cudaFuncSetAttribute(bgemm_kernel,
                         cudaFuncAttributeMaxDynamicSharedMemorySize, BG_SMEM);
    cudaFuncSetAttribute(flash_tc_kernel,
                         cudaFuncAttributeMaxDynamicSharedMemorySize, FL_SMEM);

    // weight splits into fused [K,N] plane buffers (no transpose)
    for (int l = 0; l < L_; l++) {
        size_t qo = (size_t)l * D_ * QKV_;
        run_splitw(wq + (size_t)l*D_*D_,   wqkvB_h + qo, wqkvB_l + qo, D_, D_,   QKV_, 0);
        run_splitw(wk + (size_t)l*D_*256,  wqkvB_h + qo, wqkvB_l + qo, D_, 256,  QKV_, 1024);
        run_splitw(wv + (size_t)l*D_*256,  wqkvB_h + qo, wqkvB_l + qo, D_, 256,  QKV_, 1280);
        run_split(wo + (size_t)l*D_*D_,  woB_h + (size_t)l*D_*D_, woB_l + (size_t)l*D_*D_, (size_t)D_*D_);
        size_t go = (size_t)l * D_ * GU_;
        run_splitw(wgate + (size_t)l*D_*F_, wguB_h + go, wguB_l + go, D_, F_, GU_, 0);
        run_splitw(wup   + (size_t)l*D_*F_, wguB_h + go, wguB_l + go, D_, F_, GU_, F_);
        run_split(wdown + (size_t)l*F_*D_, wdB_h + (size_t)l*F_*D_, wdB_l + (size_t)l*F_*D_, (size_t)F_*D_);
    }
    run_split(wout, woutB_h, woutB_l, (size_t)D_*V_);

    detect_idx_kernel<<<1, 256>>>((const int*)idx);
    embed_kernel<<<T_, 256>>>(idx, emb);

    for (int l = 0; l < L_; l++) {
        size_t qo = (size_t)l * D_ * QKV_;
        size_t go = (size_t)l * D_ * GU_;
        rmsnorm_split_kernel<<<T_, 256>>>(x, na + (size_t)l * D_, nh, nl);
        run_bgemm(nh, nl, wqkvB_h + qo, wqkvB_l + qo, nullptr, qkv, T_, QKV_, D_);
        rope_split_kernel<<<T_, H_*32>>>(qkv, QKV_, 0, qh, ql, H_, SCALE_);
        rope_split_kernel<<<T_, KVH_*32>>>(qkv, QKV_, 1024, kh, kl, KVH_, 1.0f);
        vsplit_kernel<<<T_, 64>>>(qkv, vh, vl);
        flash_tc_kernel<<<dim3(S_/64, H_, B_), 128, FL_SMEM>>>(qh,ql,kh,kl,vh,vl,ch,cl);
        run_bgemm(ch, cl, woB_h + (size_t)l*D_*D_, woB_l + (size_t)l*D_*D_, x, x, T_, D_, D_);
        rmsnorm_split_kernel<<<T_, 256>>>(x, nf + (size_t)l * D_, nh, nl);
        run_bgemm(nh, nl, wguB_h + go, wguB_l + go, nullptr, gu, T_, GU_, D_);
        silu_split_kernel<<<(T_*F_/4)/256, 256>>>(gu, gh, gl);
        run_bgemm(gh, gl, wdB_h + (size_t)l*F_*D_, wdB_l + (size_t)l*F_*D_, x, x, T_, D_, F_);
    }

    rmsnorm_split_kernel<<<T_, 256>>>(x, nfin, nh, nl);
    run_bgemm(nh, nl, woutB_h, woutB_l, nullptr, (float*)d_out, T_, V_, D_);
}

// round 7
// speedup vs baseline: 1.2955x; 1.0187x over previous
#include <cuda_runtime.h>
#include <cuda_bf16.h>
#include <math.h>
#include <stdint.h>

// ---------------- problem constants ----------------
#define V_   32000
#define D_   1024
#define H_   16
#define KVH_ 4
#define HD_  64
#define F_   4096
#define L_   2
#define B_   2
#define S_   2048
#define T_   (B_*S_)
#define REP_ (H_/KVH_)
#define EPS_ 1e-5f
#define SCALE_ 0.125f
#define QKV_ 1536            // fused q|k|v width
#define GU_  8192            // fused gate|up width (interleaved: even=gate, odd=up)

typedef __nv_bfloat16 bf16;

// ---------------- scratch ----------------
__device__ float g_x  [T_*D_];
__device__ float g_qkv[T_*QKV_];
__device__ int   g_is64;

// activation bf16 planes
__device__ bf16 g_nh[T_*D_],  g_nl[T_*D_];
__device__ bf16 g_qh[T_*D_],  g_ql[T_*D_];
__device__ bf16 g_kh[T_*KVH_*HD_], g_kl[T_*KVH_*HD_];
__device__ bf16 g_vh[T_*KVH_*HD_], g_vl[T_*KVH_*HD_];
__device__ bf16 g_ch[T_*D_],  g_cl[T_*D_];
__device__ bf16 g_gh[T_*F_],  g_gl[T_*F_];

// weight planes, [K, N] layout, fused along N
__device__ bf16 g_wqkvB_h[L_*D_*QKV_], g_wqkvB_l[L_*D_*QKV_];
__device__ bf16 g_woB_h  [L_*D_*D_],   g_woB_l  [L_*D_*D_];
__device__ bf16 g_wguB_h [L_*D_*GU_],  g_wguB_l [L_*D_*GU_];   // interleaved g/u
__device__ bf16 g_wdB_h  [L_*F_*D_],   g_wdB_l  [L_*F_*D_];
__device__ bf16 g_woutB_h[D_*V_],      g_woutB_l[D_*V_];

// ---------------- helpers ----------------
__device__ __forceinline__ uint32_t pack2(bf16 a, bf16 b) {
    __nv_bfloat162 t = __halves2bfloat162(a, b);
    return *reinterpret_cast<uint32_t*>(&t);
}
__device__ __forceinline__ void split1(float v, bf16& h, bf16& l) {
    h = __float2bfloat16(v);
    l = __float2bfloat16(v - __bfloat162float(h));
}

#define LDSM4(r, addr) \
    asm volatile("ldmatrix.sync.aligned.m8n8.x4.shared.b16 {%0,%1,%2,%3}, [%4];" \
        : "=r"((r)[0]), "=r"((r)[1]), "=r"((r)[2]), "=r"((r)[3]) : "r"(addr))
#define LDSM4T(r, addr) \
    asm volatile("ldmatrix.sync.aligned.m8n8.x4.trans.shared.b16 {%0,%1,%2,%3}, [%4];" \
        : "=r"((r)[0]), "=r"((r)[1]), "=r"((r)[2]), "=r"((r)[3]) : "r"(addr))
#define MMA_BF16(acc, a, b0, b1) \
    asm volatile("mma.sync.aligned.m16n8k16.row.col.f32.bf16.bf16.f32 " \
        "{%0,%1,%2,%3}, {%4,%5,%6,%7}, {%8,%9}, {%0,%1,%2,%3};" \
        : "+f"((acc)[0]), "+f"((acc)[1]), "+f"((acc)[2]), "+f"((acc)[3]) \
        : "r"((a)[0]), "r"((a)[1]), "r"((a)[2]), "r"((a)[3]), "r"(b0), "r"(b1))
#define CP16(dst, src) \
    asm volatile("cp.async.cg.shared.global [%0], [%1], 16;\n" :: "r"(dst), "l"(src) : "memory")
#define CP_COMMIT() asm volatile("cp.async.commit_group;\n" ::: "memory")
#define CP_WAIT(n)  asm volatile("cp.async.wait_group %0;\n" :: "n"(n) : "memory")

// ---------------- fp32 -> bf16 hi/lo split (proven simple form) ---------
__global__ void split_kernel(const float* __restrict__ in,
                             bf16* __restrict__ hi, bf16* __restrict__ lo, int n4) {
    int i = blockIdx.x * blockDim.x + threadIdx.x;
    if (i >= n4) return;
    float4 v = ((const float4*)in)[i];
    float vv[4] = {v.x, v.y, v.z, v.w};
    bf16 h[4], l[4];
    #pragma unroll
    for (int j = 0; j < 4; j++) split1(vv[j], h[j], l[j]);
    ((uint2*)hi)[i] = make_uint2(pack2(h[0],h[1]), pack2(h[2],h[3]));
    ((uint2*)lo)[i] = make_uint2(pack2(l[0],l[1]), pack2(l[2],l[3]));
}

// ---- strided split: in[K,Nin] -> out planes[K,Nout] at column cOff -----
__global__ void splitw_kernel(const float* __restrict__ in,
                              bf16* __restrict__ oh, bf16* __restrict__ ol,
                              int Nin, int Nout, int cOff, int n4) {
    int i = blockIdx.x * blockDim.x + threadIdx.x;
    if (i >= n4) return;
    int rc4 = Nin >> 2;
    int r = i / rc4, c4 = i - r * rc4;
    float4 v = ((const float4*)in)[i];
    float vv[4] = {v.x, v.y, v.z, v.w};
    bf16 h[4], l[4];
    #pragma unroll
    for (int q = 0; q < 4; q++) split1(vv[q], h[q], l[q]);
    size_t oi = ((size_t)r * Nout + cOff) / 4 + c4;
    ((uint2*)oh)[oi] = make_uint2(pack2(h[0],h[1]), pack2(h[2],h[3]));
    ((uint2*)ol)[oi] = make_uint2(pack2(l[0],l[1]), pack2(l[2],l[3]));
}

// ---- gate/up interleaved split: wg[k][j]->col 2j, wu[k][j]->col 2j+1 ---
__global__ void splitgu_kernel(const float* __restrict__ wg,
                               const float* __restrict__ wu,
                               bf16* __restrict__ oh, bf16* __restrict__ ol, int n4) {
    int i = blockIdx.x * blockDim.x + threadIdx.x;   // float4 over [K,F]
    if (i >= n4) return;
    float4 gv = ((const float4*)wg)[i];
    float4 uv = ((const float4*)wu)[i];
    float gg[4] = {gv.x, gv.y, gv.z, gv.w};
    float uu[4] = {uv.x, uv.y, uv.z, uv.w};
    bf16 ghh[4], gll[4], uhh[4], ull[4];
    #pragma unroll
    for (int q = 0; q < 4; q++) { split1(gg[q], ghh[q], gll[q]); split1(uu[q], uhh[q], ull[q]); }
    // output: 8 interleaved bf16 = one uint4 per plane at offset 2*i (in uint2 units -> i in uint4 units)
    uint4 hO, lO;
    hO.x = pack2(ghh[0], uhh[0]); hO.y = pack2(ghh[1], uhh[1]);
    hO.z = pack2(ghh[2], uhh[2]); hO.w = pack2(ghh[3], uhh[3]);
    lO.x = pack2(gll[0], ull[0]); lO.y = pack2(gll[1], ull[1]);
    lO.z = pack2(gll[2], ull[2]); lO.w = pack2(gll[3], ull[3]);
    ((uint4*)oh)[i] = hO;
    ((uint4*)ol)[i] = lO;
}

// ---------------- idx detection + embed ----------------
__global__ void detect_idx_kernel(const int* idx) {
    __shared__ int ok;
    if (threadIdx.x == 0) ok = 1;
    __syncthreads();
    int bad = 0;
    for (int i = threadIdx.x; i < T_/2; i += blockDim.x)
        if (idx[2*i + 1] != 0) bad = 1;
    if (bad) atomicAnd(&ok, 0);
    __syncthreads();
    if (threadIdx.x == 0) g_is64 = ok;
}
__global__ void embed_kernel(const void* idx, const float* __restrict__ emb) {
    int t = blockIdx.x;
    int tok = g_is64 ? (int)((const long long*)idx)[t] : ((const int*)idx)[t];
    ((float4*)(g_x + (size_t)t * D_))[threadIdx.x] =
        ((const float4*)(emb + (size_t)tok * D_))[threadIdx.x];
}

// ---------------- RMSNorm -> bf16 planes ----------------
__global__ void rmsnorm_split_kernel(const float* __restrict__ x,
                                     const float* __restrict__ w,
                                     bf16* __restrict__ oh, bf16* __restrict__ ol) {
    int t = blockIdx.x;
    __shared__ float red[8];
    float4 v = ((const float4*)(x + (size_t)t * D_))[threadIdx.x];
    float ss = v.x*v.x + v.y*v.y + v.z*v.z + v.w*v.w;
    #pragma unroll
    for (int o = 16; o > 0; o >>= 1) ss += __shfl_xor_sync(0xffffffffu, ss, o);
    if ((threadIdx.x & 31) == 0) red[threadIdx.x >> 5] = ss;
    __syncthreads();
    if (threadIdx.x < 8) {
        float s = red[threadIdx.x];
        #pragma unroll
        for (int o = 4; o > 0; o >>= 1) s += __shfl_xor_sync(0xffu, s, o);
        if (threadIdx.x == 0) red[0] = s;
    }
    __syncthreads();
    float inv = rsqrtf(red[0] * (1.0f / D_) + EPS_);
    float4 wv = ((const float4*)w)[threadIdx.x];
    float vv[4] = {v.x*inv*wv.x, v.y*inv*wv.y, v.z*inv*wv.z, v.w*inv*wv.w};
    bf16 h[4], l[4];
    #pragma unroll
    for (int j = 0; j < 4; j++) split1(vv[j], h[j], l[j]);
    ((uint2*)(oh + (size_t)t*D_))[threadIdx.x] = make_uint2(pack2(h[0],h[1]), pack2(h[2],h[3]));
    ((uint2*)(ol + (size_t)t*D_))[threadIdx.x] = make_uint2(pack2(l[0],l[1]), pack2(l[2],l[3]));
}

// ---------------- RoPE (strided in) -> dense bf16 planes ----------------
__global__ void rope_split_kernel(const float* __restrict__ x, int xStride, int xOff,
                                  bf16* __restrict__ xh, bf16* __restrict__ xl,
                                  int nheads, float scl) {
    int t   = blockIdx.x;
    int pos = t % S_;
    int j   = threadIdx.x & 31;
    int h   = threadIdx.x >> 5;
    float invf = powf(500000.0f, -(float)(2 * j) / (float)HD_);
    float ang = (float)pos * invf;
    float s, c;
    sincosf(ang, &s, &c);
    const float* p = x + (size_t)t * xStride + xOff + h * HD_;
    size_t ob = (size_t)t * nheads * HD_ + h * HD_;
    float a = p[j], b = p[j + 32];
    float r0 = (a * c - b * s) * scl;
    float r1 = (b * c + a * s) * scl;
    bf16 h0, l0, h1, l1;
    split1(r0, h0, l0); split1(r1, h1, l1);
    xh[ob + j] = h0; xl[ob + j] = l0;
    xh[ob + j + 32] = h1; xl[ob + j + 32] = l1;
}

// ---------------- strided V split ----------------
__global__ void vsplit_kernel(const float* __restrict__ x,
                              bf16* __restrict__ oh, bf16* __restrict__ ol) {
    int t = blockIdx.x, i = threadIdx.x;   // 64 threads * float4 = 256
    float4 v = *(const float4*)(x + (size_t)t*QKV_ + 1280 + i*4);
    float vv[4] = {v.x, v.y, v.z, v.w};
    bf16 h[4], l[4];
    #pragma unroll
    for (int j = 0; j < 4; j++) split1(vv[j], h[j], l[j]);
    ((uint2*)(oh + (size_t)t*256))[i] = make_uint2(pack2(h[0],h[1]), pack2(h[2],h[3]));
    ((uint2*)(ol + (size_t)t*256))[i] = make_uint2(pack2(l[0],l[1]), pack2(l[2],l[3]));
}

// ================= bf16-split HMMA GEMM (R3 proven core) ================
// C[M,N] = (Ah+Al)[M,K] @ (Bh+Bl)[K,N] (+Res); 3 MMAs (hh, hl, lh).
// EPI: 0 = plain/residual fp32 out; 1 = silu(gate)*up from interleaved cols,
//      bf16 hi/lo plane out of width N/2.
#define BM_  128
#define BN_  128
#define BKK_ 32
#define AST_ 40
#define BST_ 136
#define ASZ_ (BM_*AST_)
#define BSZ_ (BKK_*BST_)
#define BG_SMEM ((2*ASZ_*2 + 2*BSZ_*2) * 2)

template <int EPI>
__global__ void __launch_bounds__(256)
bgemm_kernel(const bf16* __restrict__ Ahg, const bf16* __restrict__ Alg,
             const bf16* __restrict__ Bhg, const bf16* __restrict__ Blg,
             const float* __restrict__ Res, float* __restrict__ C,
             bf16* __restrict__ Oh, bf16* __restrict__ Ol,
             int M, int N, int K) {
    extern __shared__ bf16 sm[];
    bf16* sAh = sm;                 // 2 stages
    bf16* sAl = sAh + 2*ASZ_;
    bf16* sBh = sAl + 2*ASZ_;
    bf16* sBl = sBh + 2*BSZ_;

    const int tid  = threadIdx.x;
    const int lane = tid & 31, warp = tid >> 5;
    const int warpM = warp >> 1, warpN = warp & 1;
    const int bx = blockIdx.x, by = blockIdx.y;

    const bf16* Ahb = Ahg + (size_t)by * BM_ * K;
    const bf16* Alb = Alg + (size_t)by * BM_ * K;
    const bf16* Bhb = Bhg + (size_t)bx * BN_;
    const bf16* Blb = Blg + (size_t)bx * BN_;

    const uint32_t uAh = (uint32_t)__cvta_generic_to_shared(sAh);
    const uint32_t uAl = (uint32_t)__cvta_generic_to_shared(sAl);
    const uint32_t uBh = (uint32_t)__cvta_generic_to_shared(sBh);
    const uint32_t uBl = (uint32_t)__cvta_generic_to_shared(sBl);

    const int ar = tid >> 2, ac = (tid & 3) * 8;
    const int br = tid >> 4, bc = (tid & 15) * 8;

    auto load_stage = [&](int st, int k0) {
        #pragma unroll
        for (int p = 0; p < 2; p++) {
            int r = ar + p*64;
            uint32_t d = (uint32_t)((st*ASZ_ + r*AST_ + ac) * 2);
            CP16(uAh + d, Ahb + (size_t)r*K + k0 + ac);
            CP16(uAl + d, Alb + (size_t)r*K + k0 + ac);
        }
        #pragma unroll
        for (int p = 0; p < 2; p++) {
            int r = br + p*16;
            uint32_t d = (uint32_t)((st*BSZ_ + r*BST_ + bc) * 2);
            CP16(uBh + d, Bhb + (size_t)(k0 + r)*N + bc);
            CP16(uBl + d, Blb + (size_t)(k0 + r)*N + bc);
        }
    };

    float acc[2][8][4];
    #pragma unroll
    for (int i = 0; i < 2; i++)
        #pragma unroll
        for (int j = 0; j < 8; j++)
            #pragma unroll
            for (int q = 0; q < 4; q++) acc[i][j][q] = 0.f;

    const int arow = warpM*32 + (lane & 15);
    const int acol = (lane >> 4) * 8;
    const int brow = (lane & 15);
    const int bcol = warpN*64 + (lane >> 4) * 8;

    const int kIters = K / BKK_;
    load_stage(0, 0);
    CP_COMMIT();

    for (int it = 0; it < kIters; ++it) {
        if (it + 1 < kIters) {
            load_stage((it+1)&1, (it+1)*BKK_);
            CP_COMMIT();
            CP_WAIT(1);
        } else {
            CP_WAIT(0);
        }
        __syncthreads();
        const int st = it & 1;
        const uint32_t aH = uAh + (uint32_t)(st*ASZ_*2);
        const uint32_t aL = uAl + (uint32_t)(st*ASZ_*2);
        const uint32_t bH = uBh + (uint32_t)(st*BSZ_*2);
        const uint32_t bL = uBl + (uint32_t)(st*BSZ_*2);
        #pragma unroll
        for (int kk = 0; kk < BKK_; kk += 16) {
            uint32_t ah[2][4], al[2][4];
            #pragma unroll
            for (int mt = 0; mt < 2; mt++) {
                uint32_t off = (uint32_t)(((arow + mt*16)*AST_ + kk + acol) * 2);
                LDSM4(ah[mt], aH + off);
                LDSM4(al[mt], aL + off);
            }
            #pragma unroll
            for (int pr = 0; pr < 4; pr++) {
                uint32_t off = (uint32_t)(((brow + kk)*BST_ + bcol + pr*16) * 2);
                uint32_t bh[4], bl[4];
                LDSM4T(bh, bH + off);
                LDSM4T(bl, bL + off);
                #pragma unroll
                for (int mt = 0; mt < 2; mt++) {
                    #pragma unroll
                    for (int h2 = 0; h2 < 2; h2++) {
                        int nt = pr*2 + h2;
                        MMA_BF16(acc[mt][nt], ah[mt], bh[h2*2], bh[h2*2+1]);
                        MMA_BF16(acc[mt][nt], ah[mt], bl[h2*2], bl[h2*2+1]);
                        MMA_BF16(acc[mt][nt], al[mt], bh[h2*2], bh[h2*2+1]);
                    }
                }
            }
        }
        __syncthreads();
    }

    const int g = lane >> 2, tg = lane & 3;
    if (EPI == 0) {
        #pragma unroll
        for (int mt = 0; mt < 2; mt++) {
            #pragma unroll
            for (int nt = 0; nt < 8; nt++) {
                size_t r0 = (size_t)by*BM_ + warpM*32 + mt*16 + g;
                size_t c  = (size_t)bx*BN_ + warpN*64 + nt*8 + tg*2;
                float2 v0 = make_float2(acc[mt][nt][0], acc[mt][nt][1]);
                float2 v1 = make_float2(acc[mt][nt][2], acc[mt][nt][3]);
                if (Res) {
                    float2 q0 = *(const float2*)(Res + r0*N + c);
                    float2 q1 = *(const float2*)(Res + (r0+8)*N + c);
                    v0.x += q0.x; v0.y += q0.y; v1.x += q1.x; v1.y += q1.y;
                }
                *(float2*)(C + r0*N + c)     = v0;
                *(float2*)(C + (r0+8)*N + c) = v1;
            }
        }
    } else {
        // silu(gate)*up epilogue: cols (c, c+1) = (gate_j, up_j), j = c/2.
        const int NO = N >> 1;
        #pragma unroll
        for (int mt = 0; mt < 2; mt++) {
            #pragma unroll
            for (int nt = 0; nt < 8; nt++) {
                size_t r0 = (size_t)by*BM_ + warpM*32 + mt*16 + g;
                size_t j  = (size_t)bx*(BN_/2) + warpN*32 + nt*4 + tg;
                float gate0 = acc[mt][nt][0], up0 = acc[mt][nt][1];
                float gate1 = acc[mt][nt][2], up1 = acc[mt][nt][3];
                float v0 = gate0 / (1.f + __expf(-gate0)) * up0;
                float v1 = gate1 / (1.f + __expf(-gate1)) * up1;
                bf16 h0, l0, h1, l1;
                split1(v0, h0, l0); split1(v1, h1, l1);
                Oh[r0*NO + j] = h0;     Ol[r0*NO + j] = l0;
                Oh[(r0+8)*NO + j] = h1; Ol[(r0+8)*NO + j] = l1;
            }
        }
    }
}

// ================= tensor-core flash attention (proven) =================
#define FST 72
#define FQSZ (64*FST)

__global__ void __launch_bounds__(128)
flash_tc_kernel(const bf16* __restrict__ qh, const bf16* __restrict__ ql,
                const bf16* __restrict__ kh, const bf16* __restrict__ kl,
                const bf16* __restrict__ vh, const bf16* __restrict__ vl,
                bf16* __restrict__ ch, bf16* __restrict__ cl) {
    extern __shared__ bf16 fsm[];
    bf16* sQh = fsm;
    bf16* sQl = sQh + FQSZ;
    bf16* sKh = sQl + FQSZ;
    bf16* sKl = sKh + FQSZ;
    bf16* sVh = sKl + FQSZ;
    bf16* sVl = sVh + FQSZ;

    const int q0  = blockIdx.x * 64;
    const int h   = blockIdx.y;
    const int b   = blockIdx.z;
    const int kvh = h / REP_;
    const int tid = threadIdx.x;
    const int lane = tid & 31, warp = tid >> 5;
    const int g = lane >> 2, tg = lane & 3;

    for (int li = tid; li < 512; li += 128) {
        int r = li >> 3, c8 = (li & 7) * 8;
        size_t src = ((size_t)(b * S_ + q0 + r) * D_ + h * HD_ + c8);
        *(uint4*)&sQh[r*FST + c8] = *(const uint4*)(qh + src);
        *(uint4*)&sQl[r*FST + c8] = *(const uint4*)(ql + src);
    }

    float mrow[2] = {-INFINITY, -INFINITY};
    float lrow[2] = {0.f, 0.f};
    float o[8][4] = {};

    const uint32_t uQh = (uint32_t)__cvta_generic_to_shared(sQh);
    const uint32_t uQl = (uint32_t)__cvta_generic_to_shared(sQl);
    const uint32_t uKh = (uint32_t)__cvta_generic_to_shared(sKh);
    const uint32_t uKl = (uint32_t)__cvta_generic_to_shared(sKl);
    const uint32_t uVh = (uint32_t)__cvta_generic_to_shared(sVh);
    const uint32_t uVl = (uint32_t)__cvta_generic_to_shared(sVl);
    const int fr = (lane & 15);
    const int fc = (lane >> 4) * 8;

    const int ntiles = q0 / 64 + 1;
    for (int tI = 0; tI < ntiles; tI++) {
        int kv0 = tI * 64;
        __syncthreads();
        for (int li = tid; li < 512; li += 128) {
            int r = li >> 3, c8 = (li & 7) * 8;
            size_t src = ((size_t)(b * S_ + kv0 + r) * (KVH_*HD_) + kvh * HD_ + c8);
            *(uint4*)&sKh[r*FST + c8] = *(const uint4*)(kh + src);
            *(uint4*)&sKl[r*FST + c8] = *(const uint4*)(kl + src);
            *(uint4*)&sVh[r*FST + c8] = *(const uint4*)(vh + src);
            *(uint4*)&sVl[r*FST + c8] = *(const uint4*)(vl + src);
        }
        __syncthreads();

        float s[8][4] = {};
        #pragma unroll
        for (int kk = 0; kk < 64; kk += 16) {
            uint32_t aqh[4], aql[4];
            uint32_t qoff = (uint32_t)(((warp*16 + fr)*FST + kk + fc) * 2);
            LDSM4(aqh, uQh + qoff);
            LDSM4(aql, uQl + qoff);
            #pragma unroll
            for (int nb = 0; nb < 4; nb++) {
                uint32_t koff = (uint32_t)(((nb*16 + fr)*FST + kk + fc) * 2);
                uint32_t k4h[4], k4l[4];
                LDSM4(k4h, uKh + koff);
                LDSM4(k4l, uKl + koff);
                MMA_BF16(s[nb*2],   aqh, k4h[0], k4h[2]);
                MMA_BF16(s[nb*2],   aqh, k4l[0], k4l[2]);
                MMA_BF16(s[nb*2],   aql, k4h[0], k4h[2]);
                MMA_BF16(s[nb*2+1], aqh, k4h[1], k4h[3]);
                MMA_BF16(s[nb*2+1], aqh, k4l[1], k4l[3]);
                MMA_BF16(s[nb*2+1], aql, k4h[1], k4h[3]);
            }
        }

        if (tI == ntiles - 1) {
            #pragma unroll
            for (int nt = 0; nt < 8; nt++) {
                int col = kv0 + nt*8 + tg*2;
                int r0g = q0 + warp*16 + g;
                if (col     > r0g)   s[nt][0] = -INFINITY;
                if (col + 1 > r0g)   s[nt][1] = -INFINITY;
                if (col     > r0g+8) s[nt][2] = -INFINITY;
                if (col + 1 > r0g+8) s[nt][3] = -INFINITY;
            }
        }

        #pragma unroll
        for (int qi = 0; qi < 2; qi++) {
            float mx = -INFINITY;
            #pragma unroll
            for (int nt = 0; nt < 8; nt++)
                mx = fmaxf(mx, fmaxf(s[nt][qi*2], s[nt][qi*2+1]));
            mx = fmaxf(mx, __shfl_xor_sync(0xffffffffu, mx, 1));
            mx = fmaxf(mx, __shfl_xor_sync(0xffffffffu, mx, 2));
            float mnew = fmaxf(mrow[qi], mx);
            float scale = __expf(mrow[qi] - mnew);
            mrow[qi] = mnew;
            float sum = 0.f;
            #pragma unroll
            for (int nt = 0; nt < 8; nt++) {
                float p0 = __expf(s[nt][qi*2]   - mnew);
                float p1 = __expf(s[nt][qi*2+1] - mnew);
                s[nt][qi*2] = p0; s[nt][qi*2+1] = p1;
                sum += p0 + p1;
            }
            sum += __shfl_xor_sync(0xffffffffu, sum, 1);
            sum += __shfl_xor_sync(0xffffffffu, sum, 2);
            lrow[qi] = lrow[qi]*scale + sum;
            #pragma unroll
            for (int nt = 0; nt < 8; nt++) {
                o[nt][qi*2]   *= scale;
                o[nt][qi*2+1] *= scale;
            }
        }

        #pragma unroll
        for (int ks = 0; ks < 4; ks++) {
            const float* s0 = s[2*ks];
            const float* s1 = s[2*ks+1];
            uint32_t ph[4], pl[4];
            {
                bf16 h0,l0,h1,l1;
                split1(s0[0], h0, l0); split1(s0[1], h1, l1);
                ph[0] = pack2(h0,h1); pl[0] = pack2(l0,l1);
                split1(s0[2], h0, l0); split1(s0[3], h1, l1);
                ph[1] = pack2(h0,h1); pl[1] = pack2(l0,l1);
                split1(s1[0], h0, l0); split1(s1[1], h1, l1);
                ph[2] = pack2(h0,h1); pl[2] = pack2(l0,l1);
                split1(s1[2], h0, l0); split1(s1[3], h1, l1);
                ph[3] = pack2(h0,h1); pl[3] = pack2(l0,l1);
            }
            #pragma unroll
            for (int nb = 0; nb < 4; nb++) {
                uint32_t voff = (uint32_t)(((ks*16 + fr)*FST + nb*16 + fc) * 2);
                uint32_t v4h[4], v4l[4];
                LDSM4T(v4h, uVh + voff);
                LDSM4T(v4l, uVl + voff);
                MMA_BF16(o[nb*2],   ph, v4h[0], v4h[1]);
                MMA_BF16(o[nb*2],   ph, v4l[0], v4l[1]);
                MMA_BF16(o[nb*2],   pl, v4h[0], v4h[1]);
                MMA_BF16(o[nb*2+1], ph, v4h[2], v4h[3]);
                MMA_BF16(o[nb*2+1], ph, v4l[2], v4l[3]);
                MMA_BF16(o[nb*2+1], pl, v4h[2], v4h[3]);
            }
        }
    }

    #pragma unroll
    for (int qi = 0; qi < 2; qi++) {
        float inv = 1.0f / lrow[qi];
        int r = q0 + warp*16 + g + qi*8;
        size_t base = (size_t)(b * S_ + r) * D_ + h * HD_;
        #pragma unroll
        for (int nt = 0; nt < 8; nt++) {
            int c = nt*8 + tg*2;
            float v0 = o[nt][qi*2]   * inv;
            float v1 = o[nt][qi*2+1] * inv;
            bf16 h0,l0,h1,l1;
            split1(v0, h0, l0); split1(v1, h1, l1);
            *(uint32_t*)(ch + base + c) = pack2(h0,h1);
            *(uint32_t*)(cl + base + c) = pack2(l0,l1);
        }
    }
}

// ---------------- host orchestration ----------------
#define FL_SMEM (6 * FQSZ * 2)

static inline void run_bgemm(const bf16* Ah, const bf16* Al,
                             const bf16* Bh, const bf16* Bl,
                             const float* Res, float* C, int M, int N, int K) {
    dim3 grid(N / BN_, M / BM_);
    bgemm_kernel<0><<<grid, 256, BG_SMEM>>>(Ah, Al, Bh, Bl, Res, C,
                                            nullptr, nullptr, M, N, K);
}
static inline void run_bgemm_gu(const bf16* Ah, const bf16* Al,
                                const bf16* Bh, const bf16* Bl,
                                bf16* Oh, bf16* Ol, int M, int N, int K) {
    dim3 grid(N / BN_, M / BM_);
    bgemm_kernel<1><<<grid, 256, BG_SMEM>>>(Ah, Al, Bh, Bl, nullptr, nullptr,
                                            Oh, Ol, M, N, K);
}
static inline void run_split(const float* src, bf16* h, bf16* l, size_t n) {
    int n4 = (int)(n / 4);
    split_kernel<<<(n4 + 255) / 256, 256>>>(src, h, l, n4);
}
static inline void run_splitw(const float* src, bf16* h, bf16* l,
                              int K, int Nin, int Nout, int cOff) {
    int n4 = K * Nin / 4;
    splitw_kernel<<<(n4 + 255) / 256, 256>>>(src, h, l, Nin, Nout, cOff, n4);
}

extern "C" void kernel_launch(void* const* d_in, const int* in_sizes, int n_in,
                              void* d_out, int out_size) {
    const void*  idx    = d_in[0];
    const float* emb    = (const float*)d_in[1];
    const float* wq     = (const float*)d_in[2];
    const float* wk     = (const float*)d_in[3];
    const float* wv     = (const float*)d_in[4];
    const float* wo     = (const float*)d_in[5];
    const float* wgate  = (const float*)d_in[6];
    const float* wup    = (const float*)d_in[7];
    const float* wdown  = (const float*)d_in[8];
    const float* na     = (const float*)d_in[9];
    const float* nf     = (const float*)d_in[10];
    const float* nfin   = (const float*)d_in[11];
    const float* wout   = (const float*)d_in[12];

    float *x, *qkv;
    cudaGetSymbolAddress((void**)&x,   g_x);
    cudaGetSymbolAddress((void**)&qkv, g_qkv);

    bf16 *nh,*nl,*qh,*ql,*kh,*kl,*vh,*vl,*ch,*cl,*gh,*gl;
    cudaGetSymbolAddress((void**)&nh, g_nh); cudaGetSymbolAddress((void**)&nl, g_nl);
    cudaGetSymbolAddress((void**)&qh, g_qh); cudaGetSymbolAddress((void**)&ql, g_ql);
    cudaGetSymbolAddress((void**)&kh, g_kh); cudaGetSymbolAddress((void**)&kl, g_kl);
    cudaGetSymbolAddress((void**)&vh, g_vh); cudaGetSymbolAddress((void**)&vl, g_vl);
    cudaGetSymbolAddress((void**)&ch, g_ch); cudaGetSymbolAddress((void**)&cl, g_cl);
    cudaGetSymbolAddress((void**)&gh, g_gh); cudaGetSymbolAddress((void**)&gl, g_gl);

    bf16 *wqkvB_h,*wqkvB_l,*woB_h,*woB_l,*wguB_h,*wguB_l,*wdB_h,*wdB_l,*woutB_h,*woutB_l;
    cudaGetSymbolAddress((void**)&wqkvB_h, g_wqkvB_h); cudaGetSymbolAddress((void**)&wqkvB_l, g_wqkvB_l);
    cudaGetSymbolAddress((void**)&woB_h,  g_woB_h);   cudaGetSymbolAddress((void**)&woB_l,  g_woB_l);
    cudaGetSymbolAddress((void**)&wguB_h, g_wguB_h);  cudaGetSymbolAddress((void**)&wguB_l, g_wguB_l);
    cudaGetSymbolAddress((void**)&wdB_h,  g_wdB_h);   cudaGetSymbolAddress((void**)&wdB_l,  g_wdB_l);
    cudaGetSymbolAddress((void**)&woutB_h,g_woutB_h); cudaGetSymbolAddress((void**)&woutB_l,g_woutB_l);

    cudaFuncSetAttribute(bgemm_kernel<0>,
                         cudaFuncAttributeMaxDynamicSharedMemorySize, BG_SMEM);
    cudaFuncSetAttribute(bgemm_kernel<1>,
                         cudaFuncAttributeMaxDynamicSharedMemorySize, BG_SMEM);
    cudaFuncSetAttribute(flash_tc_kernel,
                         cudaFuncAttributeMaxDynamicSharedMemorySize, FL_SMEM);

    // weight splits into fused [K,N] plane buffers
    for (int l = 0; l < L_; l++) {
        size_t qo = (size_t)l * D_ * QKV_;
        run_splitw(wq + (size_t)l*D_*D_,   wqkvB_h + qo, wqkvB_l + qo, D_, D_,   QKV_, 0);
        run_splitw(wk + (size_t)l*D_*256,  wqkvB_h + qo, wqkvB_l + qo, D_, 256,  QKV_, 1024);
        run_splitw(wv + (size_t)l*D_*256,  wqkvB_h + qo, wqkvB_l + qo, D_, 256,  QKV_, 1280);
        run_split(wo + (size_t)l*D_*D_,  woB_h + (size_t)l*D_*D_, woB_l + (size_t)l*D_*D_, (size_t)D_*D_);
        size_t go = (size_t)l * D_ * GU_;
        {   // interleaved gate/up split
            int n4 = D_ * F_ / 4;
            splitgu_kernel<<<(n4 + 255) / 256, 256>>>(
                wgate + (size_t)l*D_*F_, wup + (size_t)l*D_*F_,
                wguB_h + go, wguB_l + go, n4);
        }
        run_split(wdown + (size_t)l*F_*D_, wdB_h + (size_t)l*F_*D_, wdB_l + (size_t)l*F_*D_, (size_t)F_*D_);
    }
    run_split(wout, woutB_h, woutB_l, (size_t)D_*V_);

    detect_idx_kernel<<<1, 256>>>((const int*)idx);
    embed_kernel<<<T_, 256>>>(idx, emb);

    for (int l = 0; l < L_; l++) {
        size_t qo = (size_t)l * D_ * QKV_;
        size_t go = (size_t)l * D_ * GU_;
        rmsnorm_split_kernel<<<T_, 256>>>(x, na + (size_t)l * D_, nh, nl);
        run_bgemm(nh, nl, wqkvB_h + qo, wqkvB_l + qo, nullptr, qkv, T_, QKV_, D_);
        rope_split_kernel<<<T_, H_*32>>>(qkv, QKV_, 0, qh, ql, H_, SCALE_);
        rope_split_kernel<<<T_, KVH_*32>>>(qkv, QKV_, 1024, kh, kl, KVH_, 1.0f);
        vsplit_kernel<<<T_, 64>>>(qkv, vh, vl);
        flash_tc_kernel<<<dim3(S_/64, H_, B_), 128, FL_SMEM>>>(qh,ql,kh,kl,vh,vl,ch,cl);
        run_bgemm(ch, cl, woB_h + (size_t)l*D_*D_, woB_l + (size_t)l*D_*D_, x, x, T_, D_, D_);
        rmsnorm_split_kernel<<<T_, 256>>>(x, nf + (size_t)l * D_, nh, nl);
        run_bgemm_gu(nh, nl, wguB_h + go, wguB_l + go, gh, gl, T_, GU_, D_);
        run_bgemm(gh, gl, wdB_h + (size_t)l*F_*D_, wdB_l + (size_t)l*F_*D_, x, x, T_, D_, F_);
    }

    rmsnorm_split_kernel<<<T_, 256>>>(x, nfin, nh, nl);
    run_bgemm(nh, nl, woutB_h, woutB_l, nullptr, (float*)d_out, T_, V_, D_);
}

// round 10
// speedup vs baseline: 1.4525x; 1.1212x over previous
#include <cuda_runtime.h>
#include <cuda_bf16.h>
#include <cuda_fp16.h>
#include <math.h>
#include <stdint.h>

// ---------------- problem constants ----------------
#define V_   32000
#define D_   1024
#define H_   16
#define KVH_ 4
#define HD_  64
#define F_   4096
#define L_   2
#define B_   2
#define S_   2048
#define T_   (B_*S_)
#define REP_ (H_/KVH_)
#define EPS_ 1e-5f
#define SCALE_ 0.125f
#define QKV_ 1536            // fused q|k|v width
#define GU_  8192            // fused gate|up width (interleaved: even=gate, odd=up)

typedef __nv_bfloat16 bf16;
typedef __half fp16;

// ---------------- scratch ----------------
__device__ float g_x  [T_*D_];
__device__ float g_qkv[T_*QKV_];
__device__ int   g_is64;

// activation bf16 planes
__device__ bf16 g_nh[T_*D_],  g_nl[T_*D_];
__device__ bf16 g_qh[T_*D_],  g_ql[T_*D_];
__device__ bf16 g_kh[T_*KVH_*HD_], g_kl[T_*KVH_*HD_];
__device__ bf16 g_vh[T_*KVH_*HD_], g_vl[T_*KVH_*HD_];
__device__ bf16 g_ch[T_*D_],  g_cl[T_*D_];
__device__ bf16 g_gh[T_*F_],  g_gl[T_*F_];
__device__ fp16 g_nH [T_*D_];                       // final norm, fp16 single plane

// weight planes, [K, N] layout, fused along N
__device__ bf16 g_wqkvB_h[L_*D_*QKV_], g_wqkvB_l[L_*D_*QKV_];
__device__ bf16 g_woB_h  [L_*D_*D_],   g_woB_l  [L_*D_*D_];
__device__ bf16 g_wguB_h [L_*D_*GU_],  g_wguB_l [L_*D_*GU_];   // interleaved g/u
__device__ bf16 g_wdB_h  [L_*F_*D_],   g_wdB_l  [L_*F_*D_];
__device__ fp16 g_woutH_h[D_*V_],      g_woutH_l[D_*V_];       // fp16 2-plane

// ---------------- helpers ----------------
__device__ __forceinline__ uint32_t pack2(bf16 a, bf16 b) {
    __nv_bfloat162 t = __halves2bfloat162(a, b);
    return *reinterpret_cast<uint32_t*>(&t);
}
__device__ __forceinline__ uint32_t pack2h(fp16 a, fp16 b) {
    __half2 t = __halves2half2(a, b);
    return *reinterpret_cast<uint32_t*>(&t);
}
__device__ __forceinline__ void split1(float v, bf16& h, bf16& l) {
    h = __float2bfloat16(v);
    l = __float2bfloat16(v - __bfloat162float(h));
}
__device__ __forceinline__ void split1h(float v, fp16& h, fp16& l) {
    h = __float2half(v);
    l = __float2half(v - __half2float(h));
}

#define LDSM4(r, addr) \
    asm volatile("ldmatrix.sync.aligned.m8n8.x4.shared.b16 {%0,%1,%2,%3}, [%4];" \
        : "=r"((r)[0]), "=r"((r)[1]), "=r"((r)[2]), "=r"((r)[3]) : "r"(addr))
#define LDSM4T(r, addr) \
    asm volatile("ldmatrix.sync.aligned.m8n8.x4.trans.shared.b16 {%0,%1,%2,%3}, [%4];" \
        : "=r"((r)[0]), "=r"((r)[1]), "=r"((r)[2]), "=r"((r)[3]) : "r"(addr))
#define MMA_BF16(acc, a, b0, b1) \
    asm volatile("mma.sync.aligned.m16n8k16.row.col.f32.bf16.bf16.f32 " \
        "{%0,%1,%2,%3}, {%4,%5,%6,%7}, {%8,%9}, {%0,%1,%2,%3};" \
        : "+f"((acc)[0]), "+f"((acc)[1]), "+f"((acc)[2]), "+f"((acc)[3]) \
        : "r"((a)[0]), "r"((a)[1]), "r"((a)[2]), "r"((a)[3]), "r"(b0), "r"(b1))
#define MMA_F16(acc, a, b0, b1) \
    asm volatile("mma.sync.aligned.m16n8k16.row.col.f32.f16.f16.f32 " \
        "{%0,%1,%2,%3}, {%4,%5,%6,%7}, {%8,%9}, {%0,%1,%2,%3};" \
        : "+f"((acc)[0]), "+f"((acc)[1]), "+f"((acc)[2]), "+f"((acc)[3]) \
        : "r"((a)[0]), "r"((a)[1]), "r"((a)[2]), "r"((a)[3]), "r"(b0), "r"(b1))
#define CP16(dst, src) \
    asm volatile("cp.async.cg.shared.global [%0], [%1], 16;\n" :: "r"(dst), "l"(src) : "memory")
#define CP_COMMIT() asm volatile("cp.async.commit_group;\n" ::: "memory")
#define CP_WAIT(n)  asm volatile("cp.async.wait_group %0;\n" :: "n"(n) : "memory")

// ---------------- fp32 -> bf16 hi/lo split ----------------
__global__ void split_kernel(const float* __restrict__ in,
                             bf16* __restrict__ hi, bf16* __restrict__ lo, int n4) {
    int i = blockIdx.x * blockDim.x + threadIdx.x;
    if (i >= n4) return;
    float4 v = ((const float4*)in)[i];
    float vv[4] = {v.x, v.y, v.z, v.w};
    bf16 h[4], l[4];
    #pragma unroll
    for (int j = 0; j < 4; j++) split1(vv[j], h[j], l[j]);
    ((uint2*)hi)[i] = make_uint2(pack2(h[0],h[1]), pack2(h[2],h[3]));
    ((uint2*)lo)[i] = make_uint2(pack2(l[0],l[1]), pack2(l[2],l[3]));
}

// ---------------- fp32 -> fp16 hi/lo split (wout weights) ---------------
__global__ void splith_kernel(const float* __restrict__ in,
                              fp16* __restrict__ hi, fp16* __restrict__ lo, int n4) {
    int i = blockIdx.x * blockDim.x + threadIdx.x;
    if (i >= n4) return;
    float4 v = ((const float4*)in)[i];
    float vv[4] = {v.x, v.y, v.z, v.w};
    fp16 h[4], l[4];
    #pragma unroll
    for (int j = 0; j < 4; j++) split1h(vv[j], h[j], l[j]);
    ((uint2*)hi)[i] = make_uint2(pack2h(h[0],h[1]), pack2h(h[2],h[3]));
    ((uint2*)lo)[i] = make_uint2(pack2h(l[0],l[1]), pack2h(l[2],l[3]));
}

// ---- strided split: in[K,Nin] -> out planes[K,Nout] at column cOff -----
__global__ void splitw_kernel(const float* __restrict__ in,
                              bf16* __restrict__ oh, bf16* __restrict__ ol,
                              int Nin, int Nout, int cOff, int n4) {
    int i = blockIdx.x * blockDim.x + threadIdx.x;
    if (i >= n4) return;
    int rc4 = Nin >> 2;
    int r = i / rc4, c4 = i - r * rc4;
    float4 v = ((const float4*)in)[i];
    float vv[4] = {v.x, v.y, v.z, v.w};
    bf16 h[4], l[4];
    #pragma unroll
    for (int q = 0; q < 4; q++) split1(vv[q], h[q], l[q]);
    size_t oi = ((size_t)r * Nout + cOff) / 4 + c4;
    ((uint2*)oh)[oi] = make_uint2(pack2(h[0],h[1]), pack2(h[2],h[3]));
    ((uint2*)ol)[oi] = make_uint2(pack2(l[0],l[1]), pack2(l[2],l[3]));
}

// ---- gate/up interleaved split ----
__global__ void splitgu_kernel(const float* __restrict__ wg,
                               const float* __restrict__ wu,
                               bf16* __restrict__ oh, bf16* __restrict__ ol, int n4) {
    int i = blockIdx.x * blockDim.x + threadIdx.x;
    if (i >= n4) return;
    float4 gv = ((const float4*)wg)[i];
    float4 uv = ((const float4*)wu)[i];
    float gg[4] = {gv.x, gv.y, gv.z, gv.w};
    float uu[4] = {uv.x, uv.y, uv.z, uv.w};
    bf16 ghh[4], gll[4], uhh[4], ull[4];
    #pragma unroll
    for (int q = 0; q < 4; q++) { split1(gg[q], ghh[q], gll[q]); split1(uu[q], uhh[q], ull[q]); }
    uint4 hO, lO;
    hO.x = pack2(ghh[0], uhh[0]); hO.y = pack2(ghh[1], uhh[1]);
    hO.z = pack2(ghh[2], uhh[2]); hO.w = pack2(ghh[3], uhh[3]);
    lO.x = pack2(gll[0], ull[0]); lO.y = pack2(gll[1], ull[1]);
    lO.z = pack2(gll[2], ull[2]); lO.w = pack2(gll[3], ull[3]);
    ((uint4*)oh)[i] = hO;
    ((uint4*)ol)[i] = lO;
}

// ---------------- idx detection + embed ----------------
__global__ void detect_idx_kernel(const int* idx) {
    __shared__ int ok;
    if (threadIdx.x == 0) ok = 1;
    __syncthreads();
    int bad = 0;
    for (int i = threadIdx.x; i < T_/2; i += blockDim.x)
        if (idx[2*i + 1] != 0) bad = 1;
    if (bad) atomicAnd(&ok, 0);
    __syncthreads();
    if (threadIdx.x == 0) g_is64 = ok;
}
__global__ void embed_kernel(const void* idx, const float* __restrict__ emb) {
    int t = blockIdx.x;
    int tok = g_is64 ? (int)((const long long*)idx)[t] : ((const int*)idx)[t];
    ((float4*)(g_x + (size_t)t * D_))[threadIdx.x] =
        ((const float4*)(emb + (size_t)tok * D_))[threadIdx.x];
}

// ---------------- RMSNorm -> bf16 planes ----------------
__global__ void rmsnorm_split_kernel(const float* __restrict__ x,
                                     const float* __restrict__ w,
                                     bf16* __restrict__ oh, bf16* __restrict__ ol) {
    int t = blockIdx.x;
    __shared__ float red[8];
    float4 v = ((const float4*)(x + (size_t)t * D_))[threadIdx.x];
    float ss = v.x*v.x + v.y*v.y + v.z*v.z + v.w*v.w;
    #pragma unroll
    for (int o = 16; o > 0; o >>= 1) ss += __shfl_xor_sync(0xffffffffu, ss, o);
    if ((threadIdx.x & 31) == 0) red[threadIdx.x >> 5] = ss;
    __syncthreads();
    if (threadIdx.x < 8) {
        float s = red[threadIdx.x];
        #pragma unroll
        for (int o = 4; o > 0; o >>= 1) s += __shfl_xor_sync(0xffu, s, o);
        if (threadIdx.x == 0) red[0] = s;
    }
    __syncthreads();
    float inv = rsqrtf(red[0] * (1.0f / D_) + EPS_);
    float4 wv = ((const float4*)w)[threadIdx.x];
    float vv[4] = {v.x*inv*wv.x, v.y*inv*wv.y, v.z*inv*wv.z, v.w*inv*wv.w};
    bf16 h[4], l[4];
    #pragma unroll
    for (int j = 0; j < 4; j++) split1(vv[j], h[j], l[j]);
    ((uint2*)(oh + (size_t)t*D_))[threadIdx.x] = make_uint2(pack2(h[0],h[1]), pack2(h[2],h[3]));
    ((uint2*)(ol + (size_t)t*D_))[threadIdx.x] = make_uint2(pack2(l[0],l[1]), pack2(l[2],l[3]));
}

// ---------------- final RMSNorm -> fp16 single plane --------------------
__global__ void rmsnorm_h_kernel(const float* __restrict__ x,
                                 const float* __restrict__ w,
                                 fp16* __restrict__ o) {
    int t = blockIdx.x;
    __shared__ float red[8];
    float4 v = ((const float4*)(x + (size_t)t * D_))[threadIdx.x];
    float ss = v.x*v.x + v.y*v.y + v.z*v.z + v.w*v.w;
    #pragma unroll
    for (int off = 16; off > 0; off >>= 1) ss += __shfl_xor_sync(0xffffffffu, ss, off);
    if ((threadIdx.x & 31) == 0) red[threadIdx.x >> 5] = ss;
    __syncthreads();
    if (threadIdx.x < 8) {
        float s = red[threadIdx.x];
        #pragma unroll
        for (int off = 4; off > 0; off >>= 1) s += __shfl_xor_sync(0xffu, s, off);
        if (threadIdx.x == 0) red[0] = s;
    }
    __syncthreads();
    float inv = rsqrtf(red[0] * (1.0f / D_) + EPS_);
    float4 wv = ((const float4*)w)[threadIdx.x];
    fp16 h0 = __float2half(v.x*inv*wv.x), h1 = __float2half(v.y*inv*wv.y);
    fp16 h2 = __float2half(v.z*inv*wv.z), h3 = __float2half(v.w*inv*wv.w);
    ((uint2*)(o + (size_t)t*D_))[threadIdx.x] = make_uint2(pack2h(h0,h1), pack2h(h2,h3));
}

// ---------------- RoPE (strided in) -> dense bf16 planes ----------------
__global__ void rope_split_kernel(const float* __restrict__ x, int xStride, int xOff,
                                  bf16* __restrict__ xh, bf16* __restrict__ xl,
                                  int nheads, float scl) {
    int t   = blockIdx.x;
    int pos = t % S_;
    int j   = threadIdx.x & 31;
    int h   = threadIdx.x >> 5;
    float invf = powf(500000.0f, -(float)(2 * j) / (float)HD_);
    float ang = (float)pos * invf;
    float s, c;
    sincosf(ang, &s, &c);
    const float* p = x + (size_t)t * xStride + xOff + h * HD_;
    size_t ob = (size_t)t * nheads * HD_ + h * HD_;
    float a = p[j], b = p[j + 32];
    float r0 = (a * c - b * s) * scl;
    float r1 = (b * c + a * s) * scl;
    bf16 h0, l0, h1, l1;
    split1(r0, h0, l0); split1(r1, h1, l1);
    xh[ob + j] = h0; xl[ob + j] = l0;
    xh[ob + j + 32] = h1; xl[ob + j + 32] = l1;
}

// ---------------- strided V split ----------------
__global__ void vsplit_kernel(const float* __restrict__ x,
                              bf16* __restrict__ oh, bf16* __restrict__ ol) {
    int t = blockIdx.x, i = threadIdx.x;
    float4 v = *(const float4*)(x + (size_t)t*QKV_ + 1280 + i*4);
    float vv[4] = {v.x, v.y, v.z, v.w};
    bf16 h[4], l[4];
    #pragma unroll
    for (int j = 0; j < 4; j++) split1(vv[j], h[j], l[j]);
    ((uint2*)(oh + (size_t)t*256))[i] = make_uint2(pack2(h[0],h[1]), pack2(h[2],h[3]));
    ((uint2*)(ol + (size_t)t*256))[i] = make_uint2(pack2(l[0],l[1]), pack2(l[2],l[3]));
}

// ================= bf16-split HMMA GEMM (proven core) ===================
#define BM_  128
#define BN_  128
#define BKK_ 32
#define AST_ 40
#define BST_ 136
#define ASZ_ (BM_*AST_)
#define BSZ_ (BKK_*BST_)
#define BG_SMEM ((2*ASZ_*2 + 2*BSZ_*2) * 2)

template <int EPI>
__global__ void __launch_bounds__(256)
bgemm_kernel(const bf16* __restrict__ Ahg, const bf16* __restrict__ Alg,
             const bf16* __restrict__ Bhg, const bf16* __restrict__ Blg,
             const float* __restrict__ Res, float* __restrict__ C,
             bf16* __restrict__ Oh, bf16* __restrict__ Ol,
             int M, int N, int K) {
    extern __shared__ bf16 sm[];
    bf16* sAh = sm;
    bf16* sAl = sAh + 2*ASZ_;
    bf16* sBh = sAl + 2*ASZ_;
    bf16* sBl = sBh + 2*BSZ_;

    const int tid  = threadIdx.x;
    const int lane = tid & 31, warp = tid >> 5;
    const int warpM = warp >> 1, warpN = warp & 1;
    const int bx = blockIdx.x, by = blockIdx.y;

    const bf16* Ahb = Ahg + (size_t)by * BM_ * K;
    const bf16* Alb = Alg + (size_t)by * BM_ * K;
    const bf16* Bhb = Bhg + (size_t)bx * BN_;
    const bf16* Blb = Blg + (size_t)bx * BN_;

    const uint32_t uAh = (uint32_t)__cvta_generic_to_shared(sAh);
    const uint32_t uAl = (uint32_t)__cvta_generic_to_shared(sAl);
    const uint32_t uBh = (uint32_t)__cvta_generic_to_shared(sBh);
    const uint32_t uBl = (uint32_t)__cvta_generic_to_shared(sBl);

    const int ar = tid >> 2, ac = (tid & 3) * 8;
    const int br = tid >> 4, bc = (tid & 15) * 8;

    auto load_stage = [&](int st, int k0) {
        #pragma unroll
        for (int p = 0; p < 2; p++) {
            int r = ar + p*64;
            uint32_t d = (uint32_t)((st*ASZ_ + r*AST_ + ac) * 2);
            CP16(uAh + d, Ahb + (size_t)r*K + k0 + ac);
            CP16(uAl + d, Alb + (size_t)r*K + k0 + ac);
        }
        #pragma unroll
        for (int p = 0; p < 2; p++) {
            int r = br + p*16;
            uint32_t d = (uint32_t)((st*BSZ_ + r*BST_ + bc) * 2);
            CP16(uBh + d, Bhb + (size_t)(k0 + r)*N + bc);
            CP16(uBl + d, Blb + (size_t)(k0 + r)*N + bc);
        }
    };

    float acc[2][8][4];
    #pragma unroll
    for (int i = 0; i < 2; i++)
        #pragma unroll
        for (int j = 0; j < 8; j++)
            #pragma unroll
            for (int q = 0; q < 4; q++) acc[i][j][q] = 0.f;

    const int arow = warpM*32 + (lane & 15);
    const int acol = (lane >> 4) * 8;
    const int brow = (lane & 15);
    const int bcol = warpN*64 + (lane >> 4) * 8;

    const int kIters = K / BKK_;
    load_stage(0, 0);
    CP_COMMIT();

    for (int it = 0; it < kIters; ++it) {
        if (it + 1 < kIters) {
            load_stage((it+1)&1, (it+1)*BKK_);
            CP_COMMIT();
            CP_WAIT(1);
        } else {
            CP_WAIT(0);
        }
        __syncthreads();
        const int st = it & 1;
        const uint32_t aH = uAh + (uint32_t)(st*ASZ_*2);
        const uint32_t aL = uAl + (uint32_t)(st*ASZ_*2);
        const uint32_t bH = uBh + (uint32_t)(st*BSZ_*2);
        const uint32_t bL = uBl + (uint32_t)(st*BSZ_*2);
        #pragma unroll
        for (int kk = 0; kk < BKK_; kk += 16) {
            uint32_t ah[2][4], al[2][4];
            #pragma unroll
            for (int mt = 0; mt < 2; mt++) {
                uint32_t off = (uint32_t)(((arow + mt*16)*AST_ + kk + acol) * 2);
                LDSM4(ah[mt], aH + off);
                LDSM4(al[mt], aL + off);
            }
            #pragma unroll
            for (int pr = 0; pr < 4; pr++) {
                uint32_t off = (uint32_t)(((brow + kk)*BST_ + bcol + pr*16) * 2);
                uint32_t bh[4], bl[4];
                LDSM4T(bh, bH + off);
                LDSM4T(bl, bL + off);
                #pragma unroll
                for (int mt = 0; mt < 2; mt++) {
                    #pragma unroll
                    for (int h2 = 0; h2 < 2; h2++) {
                        int nt = pr*2 + h2;
                        MMA_BF16(acc[mt][nt], ah[mt], bh[h2*2], bh[h2*2+1]);
                        MMA_BF16(acc[mt][nt], ah[mt], bl[h2*2], bl[h2*2+1]);
                        MMA_BF16(acc[mt][nt], al[mt], bh[h2*2], bh[h2*2+1]);
                    }
                }
            }
        }
        __syncthreads();
    }

    const int g = lane >> 2, tg = lane & 3;
    if (EPI == 0) {
        #pragma unroll
        for (int mt = 0; mt < 2; mt++) {
            #pragma unroll
            for (int nt = 0; nt < 8; nt++) {
                size_t r0 = (size_t)by*BM_ + warpM*32 + mt*16 + g;
                size_t c  = (size_t)bx*BN_ + warpN*64 + nt*8 + tg*2;
                float2 v0 = make_float2(acc[mt][nt][0], acc[mt][nt][1]);
                float2 v1 = make_float2(acc[mt][nt][2], acc[mt][nt][3]);
                if (Res) {
                    float2 q0 = *(const float2*)(Res + r0*N + c);
                    float2 q1 = *(const float2*)(Res + (r0+8)*N + c);
                    v0.x += q0.x; v0.y += q0.y; v1.x += q1.x; v1.y += q1.y;
                }
                *(float2*)(C + r0*N + c)     = v0;
                *(float2*)(C + (r0+8)*N + c) = v1;
            }
        }
    } else {
        const int NO = N >> 1;
        #pragma unroll
        for (int mt = 0; mt < 2; mt++) {
            #pragma unroll
            for (int nt = 0; nt < 8; nt++) {
                size_t r0 = (size_t)by*BM_ + warpM*32 + mt*16 + g;
                size_t j  = (size_t)bx*(BN_/2) + warpN*32 + nt*4 + tg;
                float gate0 = acc[mt][nt][0], up0 = acc[mt][nt][1];
                float gate1 = acc[mt][nt][2], up1 = acc[mt][nt][3];
                float v0 = gate0 / (1.f + __expf(-gate0)) * up0;
                float v1 = gate1 / (1.f + __expf(-gate1)) * up1;
                bf16 h0, l0, h1, l1;
                split1(v0, h0, l0); split1(v1, h1, l1);
                Oh[r0*NO + j] = h0;     Ol[r0*NO + j] = l0;
                Oh[(r0+8)*NO + j] = h1; Ol[(r0+8)*NO + j] = l1;
            }
        }
    }
}

// ======== fp16 2-MMA GEMM for the vocab projection ======================
// C[M,N] = A[M,K](fp16) @ (Bh+Bl)[K,N](fp16)^; 2 MMAs (A·Bh + A·Bl).
#define HG_SMEM ((2*ASZ_ + 2*BSZ_*2) * 2)

__global__ void __launch_bounds__(256)
hgemm_kernel(const fp16* __restrict__ Ag,
             const fp16* __restrict__ Bhg, const fp16* __restrict__ Blg,
             float* __restrict__ C, int M, int N, int K) {
    extern __shared__ fp16 hsm[];
    fp16* sA  = hsm;
    fp16* sBh = sA + 2*ASZ_;
    fp16* sBl = sBh + 2*BSZ_;

    const int tid  = threadIdx.x;
    const int lane = tid & 31, warp = tid >> 5;
    const int warpM = warp >> 1, warpN = warp & 1;
    const int bx = blockIdx.x, by = blockIdx.y;

    const fp16* Ab  = Ag  + (size_t)by * BM_ * K;
    const fp16* Bhb = Bhg + (size_t)bx * BN_;
    const fp16* Blb = Blg + (size_t)bx * BN_;

    const uint32_t uA  = (uint32_t)__cvta_generic_to_shared(sA);
    const uint32_t uBh = (uint32_t)__cvta_generic_to_shared(sBh);
    const uint32_t uBl = (uint32_t)__cvta_generic_to_shared(sBl);

    const int ar = tid >> 2, ac = (tid & 3) * 8;
    const int br = tid >> 4, bc = (tid & 15) * 8;

    auto load_stage = [&](int st, int k0) {
        #pragma unroll
        for (int p = 0; p < 2; p++) {
            int r = ar + p*64;
            uint32_t d = (uint32_t)((st*ASZ_ + r*AST_ + ac) * 2);
            CP16(uA + d, Ab + (size_t)r*K + k0 + ac);
        }
        #pragma unroll
        for (int p = 0; p < 2; p++) {
            int r = br + p*16;
            uint32_t d = (uint32_t)((st*BSZ_ + r*BST_ + bc) * 2);
            CP16(uBh + d, Bhb + (size_t)(k0 + r)*N + bc);
            CP16(uBl + d, Blb + (size_t)(k0 + r)*N + bc);
        }
    };

    float acc[2][8][4];
    #pragma unroll
    for (int i = 0; i < 2; i++)
        #pragma unroll
        for (int j = 0; j < 8; j++)
            #pragma unroll
            for (int q = 0; q < 4; q++) acc[i][j][q] = 0.f;

    const int arow = warpM*32 + (lane & 15);
    const int acol = (lane >> 4) * 8;
    const int brow = (lane & 15);
    const int bcol = warpN*64 + (lane >> 4) * 8;

    const int kIters = K / BKK_;
    load_stage(0, 0);
    CP_COMMIT();

    for (int it = 0; it < kIters; ++it) {
        if (it + 1 < kIters) {
            load_stage((it+1)&1, (it+1)*BKK_);
            CP_COMMIT();
            CP_WAIT(1);
        } else {
            CP_WAIT(0);
        }
        __syncthreads();
        const int st = it & 1;
        const uint32_t aA = uA  + (uint32_t)(st*ASZ_*2);
        const uint32_t bH = uBh + (uint32_t)(st*BSZ_*2);
        const uint32_t bL = uBl + (uint32_t)(st*BSZ_*2);
        #pragma unroll
        for (int kk = 0; kk < BKK_; kk += 16) {
            uint32_t a4[2][4];
            #pragma unroll
            for (int mt = 0; mt < 2; mt++) {
                uint32_t off = (uint32_t)(((arow + mt*16)*AST_ + kk + acol) * 2);
                LDSM4(a4[mt], aA + off);
            }
            #pragma unroll
            for (int pr = 0; pr < 4; pr++) {
                uint32_t off = (uint32_t)(((brow + kk)*BST_ + bcol + pr*16) * 2);
                uint32_t bh[4], bl[4];
                LDSM4T(bh, bH + off);
                LDSM4T(bl, bL + off);
                #pragma unroll
                for (int mt = 0; mt < 2; mt++) {
                    #pragma unroll
                    for (int h2 = 0; h2 < 2; h2++) {
                        int nt = pr*2 + h2;
                        MMA_F16(acc[mt][nt], a4[mt], bh[h2*2], bh[h2*2+1]);
                        MMA_F16(acc[mt][nt], a4[mt], bl[h2*2], bl[h2*2+1]);
                    }
                }
            }
        }
        __syncthreads();
    }

    const int g = lane >> 2, tg = lane & 3;
    #pragma unroll
    for (int mt = 0; mt < 2; mt++) {
        #pragma unroll
        for (int nt = 0; nt < 8; nt++) {
            size_t r0 = (size_t)by*BM_ + warpM*32 + mt*16 + g;
            size_t c  = (size_t)bx*BN_ + warpN*64 + nt*8 + tg*2;
            *(float2*)(C + r0*N + c)     = make_float2(acc[mt][nt][0], acc[mt][nt][1]);
            *(float2*)(C + (r0+8)*N + c) = make_float2(acc[mt][nt][2], acc[mt][nt][3]);
        }
    }
}

// ================= tensor-core flash attention (proven) =================
#define FST 72
#define FQSZ (64*FST)

__global__ void __launch_bounds__(128)
flash_tc_kernel(const bf16* __restrict__ qh, const bf16* __restrict__ ql,
                const bf16* __restrict__ kh, const bf16* __restrict__ kl,
                const bf16* __restrict__ vh, const bf16* __restrict__ vl,
                bf16* __restrict__ ch, bf16* __restrict__ cl) {
    extern __shared__ bf16 fsm[];
    bf16* sQh = fsm;
    bf16* sQl = sQh + FQSZ;
    bf16* sKh = sQl + FQSZ;
    bf16* sKl = sKh + FQSZ;
    bf16* sVh = sKl + FQSZ;
    bf16* sVl = sVh + FQSZ;

    const int q0  = blockIdx.x * 64;
    const int h   = blockIdx.y;
    const int b   = blockIdx.z;
    const int kvh = h / REP_;
    const int tid = threadIdx.x;
    const int lane = tid & 31, warp = tid >> 5;
    const int g = lane >> 2, tg = lane & 3;

    for (int li = tid; li < 512; li += 128) {
        int r = li >> 3, c8 = (li & 7) * 8;
        size_t src = ((size_t)(b * S_ + q0 + r) * D_ + h * HD_ + c8);
        *(uint4*)&sQh[r*FST + c8] = *(const uint4*)(qh + src);
        *(uint4*)&sQl[r*FST + c8] = *(const uint4*)(ql + src);
    }

    float mrow[2] = {-INFINITY, -INFINITY};
    float lrow[2] = {0.f, 0.f};
    float o[8][4] = {};

    const uint32_t uQh = (uint32_t)__cvta_generic_to_shared(sQh);
    const uint32_t uQl = (uint32_t)__cvta_generic_to_shared(sQl);
    const uint32_t uKh = (uint32_t)__cvta_generic_to_shared(sKh);
    const uint32_t uKl = (uint32_t)__cvta_generic_to_shared(sKl);
    const uint32_t uVh = (uint32_t)__cvta_generic_to_shared(sVh);
    const uint32_t uVl = (uint32_t)__cvta_generic_to_shared(sVl);
    const int fr = (lane & 15);
    const int fc = (lane >> 4) * 8;

    const int ntiles = q0 / 64 + 1;
    for (int tI = 0; tI < ntiles; tI++) {
        int kv0 = tI * 64;
        __syncthreads();
        for (int li = tid; li < 512; li += 128) {
            int r = li >> 3, c8 = (li & 7) * 8;
            size_t src = ((size_t)(b * S_ + kv0 + r) * (KVH_*HD_) + kvh * HD_ + c8);
            *(uint4*)&sKh[r*FST + c8] = *(const uint4*)(kh + src);
            *(uint4*)&sKl[r*FST + c8] = *(const uint4*)(kl + src);
            *(uint4*)&sVh[r*FST + c8] = *(const uint4*)(vh + src);
            *(uint4*)&sVl[r*FST + c8] = *(const uint4*)(vl + src);
        }
        __syncthreads();

        float s[8][4] = {};
        #pragma unroll
        for (int kk = 0; kk < 64; kk += 16) {
            uint32_t aqh[4], aql[4];
            uint32_t qoff = (uint32_t)(((warp*16 + fr)*FST + kk + fc) * 2);
            LDSM4(aqh, uQh + qoff);
            LDSM4(aql, uQl + qoff);
            #pragma unroll
            for (int nb = 0; nb < 4; nb++) {
                uint32_t koff = (uint32_t)(((nb*16 + fr)*FST + kk + fc) * 2);
                uint32_t k4h[4], k4l[4];
                LDSM4(k4h, uKh + koff);
                LDSM4(k4l, uKl + koff);
                MMA_BF16(s[nb*2],   aqh, k4h[0], k4h[2]);
                MMA_BF16(s[nb*2],   aqh, k4l[0], k4l[2]);
                MMA_BF16(s[nb*2],   aql, k4h[0], k4h[2]);
                MMA_BF16(s[nb*2+1], aqh, k4h[1], k4h[3]);
                MMA_BF16(s[nb*2+1], aqh, k4l[1], k4l[3]);
                MMA_BF16(s[nb*2+1], aql, k4h[1], k4h[3]);
            }
        }

        if (tI == ntiles - 1) {
            #pragma unroll
            for (int nt = 0; nt < 8; nt++) {
                int col = kv0 + nt*8 + tg*2;
                int r0g = q0 + warp*16 + g;
                if (col     > r0g)   s[nt][0] = -INFINITY;
                if (col + 1 > r0g)   s[nt][1] = -INFINITY;
                if (col     > r0g+8) s[nt][2] = -INFINITY;
                if (col + 1 > r0g+8) s[nt][3] = -INFINITY;
            }
        }

        #pragma unroll
        for (int qi = 0; qi < 2; qi++) {
            float mx = -INFINITY;
            #pragma unroll
            for (int nt = 0; nt < 8; nt++)
                mx = fmaxf(mx, fmaxf(s[nt][qi*2], s[nt][qi*2+1]));
            mx = fmaxf(mx, __shfl_xor_sync(0xffffffffu, mx, 1));
            mx = fmaxf(mx, __shfl_xor_sync(0xffffffffu, mx, 2));
            float mnew = fmaxf(mrow[qi], mx);
            float scale = __expf(mrow[qi] - mnew);
            mrow[qi] = mnew;
            float sum = 0.f;
            #pragma unroll
            for (int nt = 0; nt < 8; nt++) {
                float p0 = __expf(s[nt][qi*2]   - mnew);
                float p1 = __expf(s[nt][qi*2+1] - mnew);
                s[nt][qi*2] = p0; s[nt][qi*2+1] = p1;
                sum += p0 + p1;
            }
            sum += __shfl_xor_sync(0xffffffffu, sum, 1);
            sum += __shfl_xor_sync(0xffffffffu, sum, 2);
            lrow[qi] = lrow[qi]*scale + sum;
            #pragma unroll
            for (int nt = 0; nt < 8; nt++) {
                o[nt][qi*2]   *= scale;
                o[nt][qi*2+1] *= scale;
            }
        }

        #pragma unroll
        for (int ks = 0; ks < 4; ks++) {
            const float* s0 = s[2*ks];
            const float* s1 = s[2*ks+1];
            uint32_t ph[4], pl[4];
            {
                bf16 h0,l0,h1,l1;
                split1(s0[0], h0, l0); split1(s0[1], h1, l1);
                ph[0] = pack2(h0,h1); pl[0] = pack2(l0,l1);
                split1(s0[2], h0, l0); split1(s0[3], h1, l1);
                ph[1] = pack2(h0,h1); pl[1] = pack2(l0,l1);
                split1(s1[0], h0, l0); split1(s1[1], h1, l1);
                ph[2] = pack2(h0,h1); pl[2] = pack2(l0,l1);
                split1(s1[2], h0, l0); split1(s1[3], h1, l1);
                ph[3] = pack2(h0,h1); pl[3] = pack2(l0,l1);
            }
            #pragma unroll
            for (int nb = 0; nb < 4; nb++) {
                uint32_t voff = (uint32_t)(((ks*16 + fr)*FST + nb*16 + fc) * 2);
                uint32_t v4h[4], v4l[4];
                LDSM4T(v4h, uVh + voff);
                LDSM4T(v4l, uVl + voff);
                MMA_BF16(o[nb*2],   ph, v4h[0], v4h[1]);
                MMA_BF16(o[nb*2],   ph, v4l[0], v4l[1]);
                MMA_BF16(o[nb*2],   pl, v4h[0], v4h[1]);
                MMA_BF16(o[nb*2+1], ph, v4h[2], v4h[3]);
                MMA_BF16(o[nb*2+1], ph, v4l[2], v4l[3]);
                MMA_BF16(o[nb*2+1], pl, v4h[2], v4h[3]);
            }
        }
    }

    #pragma unroll
    for (int qi = 0; qi < 2; qi++) {
        float inv = 1.0f / lrow[qi];
        int r = q0 + warp*16 + g + qi*8;
        size_t base = (size_t)(b * S_ + r) * D_ + h * HD_;
        #pragma unroll
        for (int nt = 0; nt < 8; nt++) {
            int c = nt*8 + tg*2;
            float v0 = o[nt][qi*2]   * inv;
            float v1 = o[nt][qi*2+1] * inv;
            bf16 h0,l0,h1,l1;
            split1(v0, h0, l0); split1(v1, h1, l1);
            *(uint32_t*)(ch + base + c) = pack2(h0,h1);
            *(uint32_t*)(cl + base + c) = pack2(l0,l1);
        }
    }
}

// ---------------- host orchestration ----------------
#define FL_SMEM (6 * FQSZ * 2)

static inline void run_bgemm(const bf16* Ah, const bf16* Al,
                             const bf16* Bh, const bf16* Bl,
                             const float* Res, float* C, int M, int N, int K) {
    dim3 grid(N / BN_, M / BM_);
    bgemm_kernel<0><<<grid, 256, BG_SMEM>>>(Ah, Al, Bh, Bl, Res, C,
                                            nullptr, nullptr, M, N, K);
}
static inline void run_bgemm_gu(const bf16* Ah, const bf16* Al,
                                const bf16* Bh, const bf16* Bl,
                                bf16* Oh, bf16* Ol, int M, int N, int K) {
    dim3 grid(N / BN_, M / BM_);
    bgemm_kernel<1><<<grid, 256, BG_SMEM>>>(Ah, Al, Bh, Bl, nullptr, nullptr,
                                            Oh, Ol, M, N, K);
}
static inline void run_split(const float* src, bf16* h, bf16* l, size_t n) {
    int n4 = (int)(n / 4);
    split_kernel<<<(n4 + 255) / 256, 256>>>(src, h, l, n4);
}
static inline void run_splitw(const float* src, bf16* h, bf16* l,
                              int K, int Nin, int Nout, int cOff) {
    int n4 = K * Nin / 4;
    splitw_kernel<<<(n4 + 255) / 256, 256>>>(src, h, l, Nin, Nout, cOff, n4);
}

extern "C" void kernel_launch(void* const* d_in, const int* in_sizes, int n_in,
                              void* d_out, int out_size) {
    const void*  idx    = d_in[0];
    const float* emb    = (const float*)d_in[1];
    const float* wq     = (const float*)d_in[2];
    const float* wk     = (const float*)d_in[3];
    const float* wv     = (const float*)d_in[4];
    const float* wo     = (const float*)d_in[5];
    const float* wgate  = (const float*)d_in[6];
    const float* wup    = (const float*)d_in[7];
    const float* wdown  = (const float*)d_in[8];
    const float* na     = (const float*)d_in[9];
    const float* nf     = (const float*)d_in[10];
    const float* nfin   = (const float*)d_in[11];
    const float* wout   = (const float*)d_in[12];

    float *x, *qkv;
    cudaGetSymbolAddress((void**)&x,   g_x);
    cudaGetSymbolAddress((void**)&qkv, g_qkv);

    bf16 *nh,*nl,*qh,*ql,*kh,*kl,*vh,*vl,*ch,*cl,*gh,*gl;
    cudaGetSymbolAddress((void**)&nh, g_nh); cudaGetSymbolAddress((void**)&nl, g_nl);
    cudaGetSymbolAddress((void**)&qh, g_qh); cudaGetSymbolAddress((void**)&ql, g_ql);
    cudaGetSymbolAddress((void**)&kh, g_kh); cudaGetSymbolAddress((void**)&kl, g_kl);
    cudaGetSymbolAddress((void**)&vh, g_vh); cudaGetSymbolAddress((void**)&vl, g_vl);
    cudaGetSymbolAddress((void**)&ch, g_ch); cudaGetSymbolAddress((void**)&cl, g_cl);
    cudaGetSymbolAddress((void**)&gh, g_gh); cudaGetSymbolAddress((void**)&gl, g_gl);
    fp16 *nH, *woutH_h, *woutH_l;
    cudaGetSymbolAddress((void**)&nH, g_nH);
    cudaGetSymbolAddress((void**)&woutH_h, g_woutH_h);
    cudaGetSymbolAddress((void**)&woutH_l, g_woutH_l);

    bf16 *wqkvB_h,*wqkvB_l,*woB_h,*woB_l,*wguB_h,*wguB_l,*wdB_h,*wdB_l;
    cudaGetSymbolAddress((void**)&wqkvB_h, g_wqkvB_h); cudaGetSymbolAddress((void**)&wqkvB_l, g_wqkvB_l);
    cudaGetSymbolAddress((void**)&woB_h,  g_woB_h);   cudaGetSymbolAddress((void**)&woB_l,  g_woB_l);
    cudaGetSymbolAddress((void**)&wguB_h, g_wguB_h);  cudaGetSymbolAddress((void**)&wguB_l, g_wguB_l);
    cudaGetSymbolAddress((void**)&wdB_h,  g_wdB_h);   cudaGetSymbolAddress((void**)&wdB_l,  g_wdB_l);

    cudaFuncSetAttribute(bgemm_kernel<0>,
                         cudaFuncAttributeMaxDynamicSharedMemorySize, BG_SMEM);
    cudaFuncSetAttribute(bgemm_kernel<1>,
                         cudaFuncAttributeMaxDynamicSharedMemorySize, BG_SMEM);
    cudaFuncSetAttribute(hgemm_kernel,
                         cudaFuncAttributeMaxDynamicSharedMemorySize, HG_SMEM);
    cudaFuncSetAttribute(flash_tc_kernel,
                         cudaFuncAttributeMaxDynamicSharedMemorySize, FL_SMEM);

    // weight splits
    for (int l = 0; l < L_; l++) {
        size_t qo = (size_t)l * D_ * QKV_;
        run_splitw(wq + (size_t)l*D_*D_,   wqkvB_h + qo, wqkvB_l + qo, D_, D_,   QKV_, 0);
        run_splitw(wk + (size_t)l*D_*256,  wqkvB_h + qo, wqkvB_l + qo, D_, 256,  QKV_, 1024);
        run_splitw(wv + (size_t)l*D_*256,  wqkvB_h + qo, wqkvB_l + qo, D_, 256,  QKV_, 1280);
        run_split(wo + (size_t)l*D_*D_,  woB_h + (size_t)l*D_*D_, woB_l + (size_t)l*D_*D_, (size_t)D_*D_);
        size_t go = (size_t)l * D_ * GU_;
        {
            int n4 = D_ * F_ / 4;
            splitgu_kernel<<<(n4 + 255) / 256, 256>>>(
                wgate + (size_t)l*D_*F_, wup + (size_t)l*D_*F_,
                wguB_h + go, wguB_l + go, n4);
        }
        run_split(wdown + (size_t)l*F_*D_, wdB_h + (size_t)l*F_*D_, wdB_l + (size_t)l*F_*D_, (size_t)F_*D_);
    }
    {   // wout -> fp16 hi/lo
        int n4 = (int)((size_t)D_*V_/4);
        splith_kernel<<<(n4 + 255) / 256, 256>>>(wout, woutH_h, woutH_l, n4);
    }

    detect_idx_kernel<<<1, 256>>>((const int*)idx);
    embed_kernel<<<T_, 256>>>(idx, emb);

    for (int l = 0; l < L_; l++) {
        size_t qo = (size_t)l * D_ * QKV_;
        size_t go = (size_t)l * D_ * GU_;
        rmsnorm_split_kernel<<<T_, 256>>>(x, na + (size_t)l * D_, nh, nl);
        run_bgemm(nh, nl, wqkvB_h + qo, wqkvB_l + qo, nullptr, qkv, T_, QKV_, D_);
        rope_split_kernel<<<T_, H_*32>>>(qkv, QKV_, 0, qh, ql, H_, SCALE_);
        rope_split_kernel<<<T_, KVH_*32>>>(qkv, QKV_, 1024, kh, kl, KVH_, 1.0f);
        vsplit_kernel<<<T_, 64>>>(qkv, vh, vl);
        flash_tc_kernel<<<dim3(S_/64, H_, B_), 128, FL_SMEM>>>(qh,ql,kh,kl,vh,vl,ch,cl);
        run_bgemm(ch, cl, woB_h + (size_t)l*D_*D_, woB_l + (size_t)l*D_*D_, x, x, T_, D_, D_);
        rmsnorm_split_kernel<<<T_, 256>>>(x, nf + (size_t)l * D_, nh, nl);
        run_bgemm_gu(nh, nl, wguB_h + go, wguB_l + go, gh, gl, T_, GU_, D_);
        run_bgemm(gh, gl, wdB_h + (size_t)l*F_*D_, wdB_l + (size_t)l*F_*D_, x, x, T_, D_, F_);
    }

    rmsnorm_h_kernel<<<T_, 256>>>(x, nfin, nH);
    {   // vocab projection: fp16 2-MMA GEMM
        dim3 grid(V_ / BN_, T_ / BM_);
        hgemm_kernel<<<grid, 256, HG_SMEM>>>(nH, woutH_h, woutH_l,
                                             (float*)d_out, T_, V_, D_);
    }
}

// round 11
// speedup vs baseline: 1.6472x; 1.1340x over previous
#include <cuda_runtime.h>
#include <cuda_bf16.h>
#include <cuda_fp16.h>
#include <math.h>
#include <stdint.h>

// ---------------- problem constants ----------------
#define V_   32000
#define D_   1024
#define H_   16
#define KVH_ 4
#define HD_  64
#define F_   4096
#define L_   2
#define B_   2
#define S_   2048
#define T_   (B_*S_)
#define REP_ (H_/KVH_)
#define EPS_ 1e-5f
#define SCALE_ 0.125f
#define QKV_ 1536            // fused q|k|v width
#define GU_  8192            // fused gate|up width (interleaved: even=gate, odd=up)

typedef __nv_bfloat16 bf16;
typedef __half fp16;

// ---------------- scratch ----------------
__device__ float g_x  [T_*D_];
__device__ float g_qkv[T_*QKV_];
__device__ int   g_is64;

// activation planes
__device__ bf16 g_nh[T_*D_],  g_nl[T_*D_];          // attn norm, bf16 2-plane
__device__ bf16 g_qh[T_*D_],  g_ql[T_*D_];
__device__ bf16 g_kh[T_*KVH_*HD_], g_kl[T_*KVH_*HD_];
__device__ bf16 g_vh[T_*KVH_*HD_], g_vl[T_*KVH_*HD_];
__device__ bf16 g_ch[T_*D_],  g_cl[T_*D_];
__device__ fp16 g_nH [T_*D_];                       // ffn/final norm, fp16 1-plane
__device__ fp16 g_gH [T_*F_];                       // silu output, fp16 1-plane

// weight planes, [K, N] layout, fused along N
__device__ bf16 g_wqkvB_h[L_*D_*QKV_], g_wqkvB_l[L_*D_*QKV_];
__device__ bf16 g_woB_h  [L_*D_*D_],   g_woB_l  [L_*D_*D_];
__device__ fp16 g_wguH_h [L_*D_*GU_],  g_wguH_l [L_*D_*GU_];   // fp16, interleaved g/u
__device__ fp16 g_wdH_h  [L_*F_*D_],   g_wdH_l  [L_*F_*D_];    // fp16 2-plane
__device__ fp16 g_woutH_h[D_*V_],      g_woutH_l[D_*V_];       // fp16 2-plane

// ---------------- helpers ----------------
__device__ __forceinline__ uint32_t pack2(bf16 a, bf16 b) {
    __nv_bfloat162 t = __halves2bfloat162(a, b);
    return *reinterpret_cast<uint32_t*>(&t);
}
__device__ __forceinline__ uint32_t pack2h(fp16 a, fp16 b) {
    __half2 t = __halves2half2(a, b);
    return *reinterpret_cast<uint32_t*>(&t);
}
__device__ __forceinline__ void split1(float v, bf16& h, bf16& l) {
    h = __float2bfloat16(v);
    l = __float2bfloat16(v - __bfloat162float(h));
}
__device__ __forceinline__ void split1h(float v, fp16& h, fp16& l) {
    h = __float2half(v);
    l = __float2half(v - __half2float(h));
}

#define LDSM4(r, addr) \
    asm volatile("ldmatrix.sync.aligned.m8n8.x4.shared.b16 {%0,%1,%2,%3}, [%4];" \
        : "=r"((r)[0]), "=r"((r)[1]), "=r"((r)[2]), "=r"((r)[3]) : "r"(addr))
#define LDSM4T(r, addr) \
    asm volatile("ldmatrix.sync.aligned.m8n8.x4.trans.shared.b16 {%0,%1,%2,%3}, [%4];" \
        : "=r"((r)[0]), "=r"((r)[1]), "=r"((r)[2]), "=r"((r)[3]) : "r"(addr))
#define MMA_BF16(acc, a, b0, b1) \
    asm volatile("mma.sync.aligned.m16n8k16.row.col.f32.bf16.bf16.f32 " \
        "{%0,%1,%2,%3}, {%4,%5,%6,%7}, {%8,%9}, {%0,%1,%2,%3};" \
        : "+f"((acc)[0]), "+f"((acc)[1]), "+f"((acc)[2]), "+f"((acc)[3]) \
        : "r"((a)[0]), "r"((a)[1]), "r"((a)[2]), "r"((a)[3]), "r"(b0), "r"(b1))
#define MMA_F16(acc, a, b0, b1) \
    asm volatile("mma.sync.aligned.m16n8k16.row.col.f32.f16.f16.f32 " \
        "{%0,%1,%2,%3}, {%4,%5,%6,%7}, {%8,%9}, {%0,%1,%2,%3};" \
        : "+f"((acc)[0]), "+f"((acc)[1]), "+f"((acc)[2]), "+f"((acc)[3]) \
        : "r"((a)[0]), "r"((a)[1]), "r"((a)[2]), "r"((a)[3]), "r"(b0), "r"(b1))
#define CP16(dst, src) \
    asm volatile("cp.async.cg.shared.global [%0], [%1], 16;\n" :: "r"(dst), "l"(src) : "memory")
#define CP_COMMIT() asm volatile("cp.async.commit_group;\n" ::: "memory")
#define CP_WAIT(n)  asm volatile("cp.async.wait_group %0;\n" :: "n"(n) : "memory")

// ---------------- fp32 -> bf16 hi/lo split ----------------
__global__ void split_kernel(const float* __restrict__ in,
                             bf16* __restrict__ hi, bf16* __restrict__ lo, int n4) {
    int i = blockIdx.x * blockDim.x + threadIdx.x;
    if (i >= n4) return;
    float4 v = ((const float4*)in)[i];
    float vv[4] = {v.x, v.y, v.z, v.w};
    bf16 h[4], l[4];
    #pragma unroll
    for (int j = 0; j < 4; j++) split1(vv[j], h[j], l[j]);
    ((uint2*)hi)[i] = make_uint2(pack2(h[0],h[1]), pack2(h[2],h[3]));
    ((uint2*)lo)[i] = make_uint2(pack2(l[0],l[1]), pack2(l[2],l[3]));
}

// ---------------- fp32 -> fp16 hi/lo split ----------------
__global__ void splith_kernel(const float* __restrict__ in,
                              fp16* __restrict__ hi, fp16* __restrict__ lo, int n4) {
    int i = blockIdx.x * blockDim.x + threadIdx.x;
    if (i >= n4) return;
    float4 v = ((const float4*)in)[i];
    float vv[4] = {v.x, v.y, v.z, v.w};
    fp16 h[4], l[4];
    #pragma unroll
    for (int j = 0; j < 4; j++) split1h(vv[j], h[j], l[j]);
    ((uint2*)hi)[i] = make_uint2(pack2h(h[0],h[1]), pack2h(h[2],h[3]));
    ((uint2*)lo)[i] = make_uint2(pack2h(l[0],l[1]), pack2h(l[2],l[3]));
}

// ---- strided split: in[K,Nin] -> out planes[K,Nout] at column cOff -----
__global__ void splitw_kernel(const float* __restrict__ in,
                              bf16* __restrict__ oh, bf16* __restrict__ ol,
                              int Nin, int Nout, int cOff, int n4) {
    int i = blockIdx.x * blockDim.x + threadIdx.x;
    if (i >= n4) return;
    int rc4 = Nin >> 2;
    int r = i / rc4, c4 = i - r * rc4;
    float4 v = ((const float4*)in)[i];
    float vv[4] = {v.x, v.y, v.z, v.w};
    bf16 h[4], l[4];
    #pragma unroll
    for (int q = 0; q < 4; q++) split1(vv[q], h[q], l[q]);
    size_t oi = ((size_t)r * Nout + cOff) / 4 + c4;
    ((uint2*)oh)[oi] = make_uint2(pack2(h[0],h[1]), pack2(h[2],h[3]));
    ((uint2*)ol)[oi] = make_uint2(pack2(l[0],l[1]), pack2(l[2],l[3]));
}

// ---- gate/up interleaved fp16 split: wg[k][j]->col 2j, wu[k][j]->col 2j+1 ----
__global__ void splitguh_kernel(const float* __restrict__ wg,
                                const float* __restrict__ wu,
                                fp16* __restrict__ oh, fp16* __restrict__ ol, int n4) {
    int i = blockIdx.x * blockDim.x + threadIdx.x;
    if (i >= n4) return;
    float4 gv = ((const float4*)wg)[i];
    float4 uv = ((const float4*)wu)[i];
    float gg[4] = {gv.x, gv.y, gv.z, gv.w};
    float uu[4] = {uv.x, uv.y, uv.z, uv.w};
    fp16 ghh[4], gll[4], uhh[4], ull[4];
    #pragma unroll
    for (int q = 0; q < 4; q++) { split1h(gg[q], ghh[q], gll[q]); split1h(uu[q], uhh[q], ull[q]); }
    uint4 hO, lO;
    hO.x = pack2h(ghh[0], uhh[0]); hO.y = pack2h(ghh[1], uhh[1]);
    hO.z = pack2h(ghh[2], uhh[2]); hO.w = pack2h(ghh[3], uhh[3]);
    lO.x = pack2h(gll[0], ull[0]); lO.y = pack2h(gll[1], ull[1]);
    lO.z = pack2h(gll[2], ull[2]); lO.w = pack2h(gll[3], ull[3]);
    ((uint4*)oh)[i] = hO;
    ((uint4*)ol)[i] = lO;
}

// ---------------- idx detection + embed ----------------
__global__ void detect_idx_kernel(const int* idx) {
    __shared__ int ok;
    if (threadIdx.x == 0) ok = 1;
    __syncthreads();
    int bad = 0;
    for (int i = threadIdx.x; i < T_/2; i += blockDim.x)
        if (idx[2*i + 1] != 0) bad = 1;
    if (bad) atomicAnd(&ok, 0);
    __syncthreads();
    if (threadIdx.x == 0) g_is64 = ok;
}
__global__ void embed_kernel(const void* idx, const float* __restrict__ emb) {
    int t = blockIdx.x;
    int tok = g_is64 ? (int)((const long long*)idx)[t] : ((const int*)idx)[t];
    ((float4*)(g_x + (size_t)t * D_))[threadIdx.x] =
        ((const float4*)(emb + (size_t)tok * D_))[threadIdx.x];
}

// ---------------- RMSNorm -> bf16 planes ----------------
__global__ void rmsnorm_split_kernel(const float* __restrict__ x,
                                     const float* __restrict__ w,
                                     bf16* __restrict__ oh, bf16* __restrict__ ol) {
    int t = blockIdx.x;
    __shared__ float red[8];
    float4 v = ((const float4*)(x + (size_t)t * D_))[threadIdx.x];
    float ss = v.x*v.x + v.y*v.y + v.z*v.z + v.w*v.w;
    #pragma unroll
    for (int o = 16; o > 0; o >>= 1) ss += __shfl_xor_sync(0xffffffffu, ss, o);
    if ((threadIdx.x & 31) == 0) red[threadIdx.x >> 5] = ss;
    __syncthreads();
    if (threadIdx.x < 8) {
        float s = red[threadIdx.x];
        #pragma unroll
        for (int o = 4; o > 0; o >>= 1) s += __shfl_xor_sync(0xffu, s, o);
        if (threadIdx.x == 0) red[0] = s;
    }
    __syncthreads();
    float inv = rsqrtf(red[0] * (1.0f / D_) + EPS_);
    float4 wv = ((const float4*)w)[threadIdx.x];
    float vv[4] = {v.x*inv*wv.x, v.y*inv*wv.y, v.z*inv*wv.z, v.w*inv*wv.w};
    bf16 h[4], l[4];
    #pragma unroll
    for (int j = 0; j < 4; j++) split1(vv[j], h[j], l[j]);
    ((uint2*)(oh + (size_t)t*D_))[threadIdx.x] = make_uint2(pack2(h[0],h[1]), pack2(h[2],h[3]));
    ((uint2*)(ol + (size_t)t*D_))[threadIdx.x] = make_uint2(pack2(l[0],l[1]), pack2(l[2],l[3]));
}

// ---------------- RMSNorm -> fp16 single plane --------------------------
__global__ void rmsnorm_h_kernel(const float* __restrict__ x,
                                 const float* __restrict__ w,
                                 fp16* __restrict__ o) {
    int t = blockIdx.x;
    __shared__ float red[8];
    float4 v = ((const float4*)(x + (size_t)t * D_))[threadIdx.x];
    float ss = v.x*v.x + v.y*v.y + v.z*v.z + v.w*v.w;
    #pragma unroll
    for (int off = 16; off > 0; off >>= 1) ss += __shfl_xor_sync(0xffffffffu, ss, off);
    if ((threadIdx.x & 31) == 0) red[threadIdx.x >> 5] = ss;
    __syncthreads();
    if (threadIdx.x < 8) {
        float s = red[threadIdx.x];
        #pragma unroll
        for (int off = 4; off > 0; off >>= 1) s += __shfl_xor_sync(0xffu, s, off);
        if (threadIdx.x == 0) red[0] = s;
    }
    __syncthreads();
    float inv = rsqrtf(red[0] * (1.0f / D_) + EPS_);
    float4 wv = ((const float4*)w)[threadIdx.x];
    fp16 h0 = __float2half(v.x*inv*wv.x), h1 = __float2half(v.y*inv*wv.y);
    fp16 h2 = __float2half(v.z*inv*wv.z), h3 = __float2half(v.w*inv*wv.w);
    ((uint2*)(o + (size_t)t*D_))[threadIdx.x] = make_uint2(pack2h(h0,h1), pack2h(h2,h3));
}

// ---------------- RoPE (strided in) -> dense bf16 planes ----------------
__global__ void rope_split_kernel(const float* __restrict__ x, int xStride, int xOff,
                                  bf16* __restrict__ xh, bf16* __restrict__ xl,
                                  int nheads, float scl) {
    int t   = blockIdx.x;
    int pos = t % S_;
    int j   = threadIdx.x & 31;
    int h   = threadIdx.x >> 5;
    float invf = powf(500000.0f, -(float)(2 * j) / (float)HD_);
    float ang = (float)pos * invf;
    float s, c;
    sincosf(ang, &s, &c);
    const float* p = x + (size_t)t * xStride + xOff + h * HD_;
    size_t ob = (size_t)t * nheads * HD_ + h * HD_;
    float a = p[j], b = p[j + 32];
    float r0 = (a * c - b * s) * scl;
    float r1 = (b * c + a * s) * scl;
    bf16 h0, l0, h1, l1;
    split1(r0, h0, l0); split1(r1, h1, l1);
    xh[ob + j] = h0; xl[ob + j] = l0;
    xh[ob + j + 32] = h1; xl[ob + j + 32] = l1;
}

// ---------------- strided V split ----------------
__global__ void vsplit_kernel(const float* __restrict__ x,
                              bf16* __restrict__ oh, bf16* __restrict__ ol) {
    int t = blockIdx.x, i = threadIdx.x;
    float4 v = *(const float4*)(x + (size_t)t*QKV_ + 1280 + i*4);
    float vv[4] = {v.x, v.y, v.z, v.w};
    bf16 h[4], l[4];
    #pragma unroll
    for (int j = 0; j < 4; j++) split1(vv[j], h[j], l[j]);
    ((uint2*)(oh + (size_t)t*256))[i] = make_uint2(pack2(h[0],h[1]), pack2(h[2],h[3]));
    ((uint2*)(ol + (size_t)t*256))[i] = make_uint2(pack2(l[0],l[1]), pack2(l[2],l[3]));
}

// ================= bf16-split HMMA GEMM (proven core; attention path) ===
#define BM_  128
#define BN_  128
#define BKK_ 32
#define AST_ 40
#define BST_ 136
#define ASZ_ (BM_*AST_)
#define BSZ_ (BKK_*BST_)
#define BG_SMEM ((2*ASZ_*2 + 2*BSZ_*2) * 2)

__global__ void __launch_bounds__(256)
bgemm_kernel(const bf16* __restrict__ Ahg, const bf16* __restrict__ Alg,
             const bf16* __restrict__ Bhg, const bf16* __restrict__ Blg,
             const float* __restrict__ Res, float* __restrict__ C,
             int M, int N, int K) {
    extern __shared__ bf16 sm[];
    bf16* sAh = sm;
    bf16* sAl = sAh + 2*ASZ_;
    bf16* sBh = sAl + 2*ASZ_;
    bf16* sBl = sBh + 2*BSZ_;

    const int tid  = threadIdx.x;
    const int lane = tid & 31, warp = tid >> 5;
    const int warpM = warp >> 1, warpN = warp & 1;
    const int bx = blockIdx.x, by = blockIdx.y;

    const bf16* Ahb = Ahg + (size_t)by * BM_ * K;
    const bf16* Alb = Alg + (size_t)by * BM_ * K;
    const bf16* Bhb = Bhg + (size_t)bx * BN_;
    const bf16* Blb = Blg + (size_t)bx * BN_;

    const uint32_t uAh = (uint32_t)__cvta_generic_to_shared(sAh);
    const uint32_t uAl = (uint32_t)__cvta_generic_to_shared(sAl);
    const uint32_t uBh = (uint32_t)__cvta_generic_to_shared(sBh);
    const uint32_t uBl = (uint32_t)__cvta_generic_to_shared(sBl);

    const int ar = tid >> 2, ac = (tid & 3) * 8;
    const int br = tid >> 4, bc = (tid & 15) * 8;

    auto load_stage = [&](int st, int k0) {
        #pragma unroll
        for (int p = 0; p < 2; p++) {
            int r = ar + p*64;
            uint32_t d = (uint32_t)((st*ASZ_ + r*AST_ + ac) * 2);
            CP16(uAh + d, Ahb + (size_t)r*K + k0 + ac);
            CP16(uAl + d, Alb + (size_t)r*K + k0 + ac);
        }
        #pragma unroll
        for (int p = 0; p < 2; p++) {
            int r = br + p*16;
            uint32_t d = (uint32_t)((st*BSZ_ + r*BST_ + bc) * 2);
            CP16(uBh + d, Bhb + (size_t)(k0 + r)*N + bc);
            CP16(uBl + d, Blb + (size_t)(k0 + r)*N + bc);
        }
    };

    float acc[2][8][4];
    #pragma unroll
    for (int i = 0; i < 2; i++)
        #pragma unroll
        for (int j = 0; j < 8; j++)
            #pragma unroll
            for (int q = 0; q < 4; q++) acc[i][j][q] = 0.f;

    const int arow = warpM*32 + (lane & 15);
    const int acol = (lane >> 4) * 8;
    const int brow = (lane & 15);
    const int bcol = warpN*64 + (lane >> 4) * 8;

    const int kIters = K / BKK_;
    load_stage(0, 0);
    CP_COMMIT();

    for (int it = 0; it < kIters; ++it) {
        if (it + 1 < kIters) {
            load_stage((it+1)&1, (it+1)*BKK_);
            CP_COMMIT();
            CP_WAIT(1);
        } else {
            CP_WAIT(0);
        }
        __syncthreads();
        const int st = it & 1;
        const uint32_t aH = uAh + (uint32_t)(st*ASZ_*2);
        const uint32_t aL = uAl + (uint32_t)(st*ASZ_*2);
        const uint32_t bH = uBh + (uint32_t)(st*BSZ_*2);
        const uint32_t bL = uBl + (uint32_t)(st*BSZ_*2);
        #pragma unroll
        for (int kk = 0; kk < BKK_; kk += 16) {
            uint32_t ah[2][4], al[2][4];
            #pragma unroll
            for (int mt = 0; mt < 2; mt++) {
                uint32_t off = (uint32_t)(((arow + mt*16)*AST_ + kk + acol) * 2);
                LDSM4(ah[mt], aH + off);
                LDSM4(al[mt], aL + off);
            }
            #pragma unroll
            for (int pr = 0; pr < 4; pr++) {
                uint32_t off = (uint32_t)(((brow + kk)*BST_ + bcol + pr*16) * 2);
                uint32_t bh[4], bl[4];
                LDSM4T(bh, bH + off);
                LDSM4T(bl, bL + off);
                #pragma unroll
                for (int mt = 0; mt < 2; mt++) {
                    #pragma unroll
                    for (int h2 = 0; h2 < 2; h2++) {
                        int nt = pr*2 + h2;
                        MMA_BF16(acc[mt][nt], ah[mt], bh[h2*2], bh[h2*2+1]);
                        MMA_BF16(acc[mt][nt], ah[mt], bl[h2*2], bl[h2*2+1]);
                        MMA_BF16(acc[mt][nt], al[mt], bh[h2*2], bh[h2*2+1]);
                    }
                }
            }
        }
        __syncthreads();
    }

    const int g = lane >> 2, tg = lane & 3;
    #pragma unroll
    for (int mt = 0; mt < 2; mt++) {
        #pragma unroll
        for (int nt = 0; nt < 8; nt++) {
            size_t r0 = (size_t)by*BM_ + warpM*32 + mt*16 + g;
            size_t c  = (size_t)bx*BN_ + warpN*64 + nt*8 + tg*2;
            float2 v0 = make_float2(acc[mt][nt][0], acc[mt][nt][1]);
            float2 v1 = make_float2(acc[mt][nt][2], acc[mt][nt][3]);
            if (Res) {
                float2 q0 = *(const float2*)(Res + r0*N + c);
                float2 q1 = *(const float2*)(Res + (r0+8)*N + c);
                v0.x += q0.x; v0.y += q0.y; v1.x += q1.x; v1.y += q1.y;
            }
            *(float2*)(C + r0*N + c)     = v0;
            *(float2*)(C + (r0+8)*N + c) = v1;
        }
    }
}

// ======== fp16 2-MMA GEMM: A 1-plane, B 2-plane =========================
// EPI 0: fp32 out (+opt Res).  EPI 1: silu(gate)*up from interleaved cols,
//        fp16 1-plane out of width N/2.
#define HG_SMEM ((2*ASZ_ + 2*BSZ_*2) * 2)

template <int EPI>
__global__ void __launch_bounds__(256)
hgemm_kernel(const fp16* __restrict__ Ag,
             const fp16* __restrict__ Bhg, const fp16* __restrict__ Blg,
             const float* __restrict__ Res, float* __restrict__ C,
             fp16* __restrict__ O, int M, int N, int K) {
    extern __shared__ fp16 hsm[];
    fp16* sA  = hsm;
    fp16* sBh = sA + 2*ASZ_;
    fp16* sBl = sBh + 2*BSZ_;

    const int tid  = threadIdx.x;
    const int lane = tid & 31, warp = tid >> 5;
    const int warpM = warp >> 1, warpN = warp & 1;
    const int bx = blockIdx.x, by = blockIdx.y;

    const fp16* Ab  = Ag  + (size_t)by * BM_ * K;
    const fp16* Bhb = Bhg + (size_t)bx * BN_;
    const fp16* Blb = Blg + (size_t)bx * BN_;

    const uint32_t uA  = (uint32_t)__cvta_generic_to_shared(sA);
    const uint32_t uBh = (uint32_t)__cvta_generic_to_shared(sBh);
    const uint32_t uBl = (uint32_t)__cvta_generic_to_shared(sBl);

    const int ar = tid >> 2, ac = (tid & 3) * 8;
    const int br = tid >> 4, bc = (tid & 15) * 8;

    auto load_stage = [&](int st, int k0) {
        #pragma unroll
        for (int p = 0; p < 2; p++) {
            int r = ar + p*64;
            uint32_t d = (uint32_t)((st*ASZ_ + r*AST_ + ac) * 2);
            CP16(uA + d, Ab + (size_t)r*K + k0 + ac);
        }
        #pragma unroll
        for (int p = 0; p < 2; p++) {
            int r = br + p*16;
            uint32_t d = (uint32_t)((st*BSZ_ + r*BST_ + bc) * 2);
            CP16(uBh + d, Bhb + (size_t)(k0 + r)*N + bc);
            CP16(uBl + d, Blb + (size_t)(k0 + r)*N + bc);
        }
    };

    float acc[2][8][4];
    #pragma unroll
    for (int i = 0; i < 2; i++)
        #pragma unroll
        for (int j = 0; j < 8; j++)
            #pragma unroll
            for (int q = 0; q < 4; q++) acc[i][j][q] = 0.f;

    const int arow = warpM*32 + (lane & 15);
    const int acol = (lane >> 4) * 8;
    const int brow = (lane & 15);
    const int bcol = warpN*64 + (lane >> 4) * 8;

    const int kIters = K / BKK_;
    load_stage(0, 0);
    CP_COMMIT();

    for (int it = 0; it < kIters; ++it) {
        if (it + 1 < kIters) {
            load_stage((it+1)&1, (it+1)*BKK_);
            CP_COMMIT();
            CP_WAIT(1);
        } else {
            CP_WAIT(0);
        }
        __syncthreads();
        const int st = it & 1;
        const uint32_t aA = uA  + (uint32_t)(st*ASZ_*2);
        const uint32_t bH = uBh + (uint32_t)(st*BSZ_*2);
        const uint32_t bL = uBl + (uint32_t)(st*BSZ_*2);
        #pragma unroll
        for (int kk = 0; kk < BKK_; kk += 16) {
            uint32_t a4[2][4];
            #pragma unroll
            for (int mt = 0; mt < 2; mt++) {
                uint32_t off = (uint32_t)(((arow + mt*16)*AST_ + kk + acol) * 2);
                LDSM4(a4[mt], aA + off);
            }
            #pragma unroll
            for (int pr = 0; pr < 4; pr++) {
                uint32_t off = (uint32_t)(((brow + kk)*BST_ + bcol + pr*16) * 2);
                uint32_t bh[4], bl[4];
                LDSM4T(bh, bH + off);
                LDSM4T(bl, bL + off);
                #pragma unroll
                for (int mt = 0; mt < 2; mt++) {
                    #pragma unroll
                    for (int h2 = 0; h2 < 2; h2++) {
                        int nt = pr*2 + h2;
                        MMA_F16(acc[mt][nt], a4[mt], bh[h2*2], bh[h2*2+1]);
                        MMA_F16(acc[mt][nt], a4[mt], bl[h2*2], bl[h2*2+1]);
                    }
                }
            }
        }
        __syncthreads();
    }

    const int g = lane >> 2, tg = lane & 3;
    if (EPI == 0) {
        #pragma unroll
        for (int mt = 0; mt < 2; mt++) {
            #pragma unroll
            for (int nt = 0; nt < 8; nt++) {
                size_t r0 = (size_t)by*BM_ + warpM*32 + mt*16 + g;
                size_t c  = (size_t)bx*BN_ + warpN*64 + nt*8 + tg*2;
                float2 v0 = make_float2(acc[mt][nt][0], acc[mt][nt][1]);
                float2 v1 = make_float2(acc[mt][nt][2], acc[mt][nt][3]);
                if (Res) {
                    float2 q0 = *(const float2*)(Res + r0*N + c);
                    float2 q1 = *(const float2*)(Res + (r0+8)*N + c);
                    v0.x += q0.x; v0.y += q0.y; v1.x += q1.x; v1.y += q1.y;
                }
                *(float2*)(C + r0*N + c)     = v0;
                *(float2*)(C + (r0+8)*N + c) = v1;
            }
        }
    } else {
        // silu(gate)*up epilogue: cols (c, c+1) = (gate_j, up_j), j = c/2.
        const int NO = N >> 1;
        #pragma unroll
        for (int mt = 0; mt < 2; mt++) {
            #pragma unroll
            for (int nt = 0; nt < 8; nt++) {
                size_t r0 = (size_t)by*BM_ + warpM*32 + mt*16 + g;
                size_t j  = (size_t)bx*(BN_/2) + warpN*32 + nt*4 + tg;
                float gate0 = acc[mt][nt][0], up0 = acc[mt][nt][1];
                float gate1 = acc[mt][nt][2], up1 = acc[mt][nt][3];
                float v0 = gate0 / (1.f + __expf(-gate0)) * up0;
                float v1 = gate1 / (1.f + __expf(-gate1)) * up1;
                O[r0*NO + j]     = __float2half(v0);
                O[(r0+8)*NO + j] = __float2half(v1);
            }
        }
    }
}

// ================= tensor-core flash attention (proven) =================
#define FST 72
#define FQSZ (64*FST)

__global__ void __launch_bounds__(128)
flash_tc_kernel(const bf16* __restrict__ qh, const bf16* __restrict__ ql,
                const bf16* __restrict__ kh, const bf16* __restrict__ kl,
                const bf16* __restrict__ vh, const bf16* __restrict__ vl,
                bf16* __restrict__ ch, bf16* __restrict__ cl) {
    extern __shared__ bf16 fsm[];
    bf16* sQh = fsm;
    bf16* sQl = sQh + FQSZ;
    bf16* sKh = sQl + FQSZ;
    bf16* sKl = sKh + FQSZ;
    bf16* sVh = sKl + FQSZ;
    bf16* sVl = sVh + FQSZ;

    const int q0  = blockIdx.x * 64;
    const int h   = blockIdx.y;
    const int b   = blockIdx.z;
    const int kvh = h / REP_;
    const int tid = threadIdx.x;
    const int lane = tid & 31, warp = tid >> 5;
    const int g = lane >> 2, tg = lane & 3;

    for (int li = tid; li < 512; li += 128) {
        int r = li >> 3, c8 = (li & 7) * 8;
        size_t src = ((size_t)(b * S_ + q0 + r) * D_ + h * HD_ + c8);
        *(uint4*)&sQh[r*FST + c8] = *(const uint4*)(qh + src);
        *(uint4*)&sQl[r*FST + c8] = *(const uint4*)(ql + src);
    }

    float mrow[2] = {-INFINITY, -INFINITY};
    float lrow[2] = {0.f, 0.f};
    float o[8][4] = {};

    const uint32_t uQh = (uint32_t)__cvta_generic_to_shared(sQh);
    const uint32_t uQl = (uint32_t)__cvta_generic_to_shared(sQl);
    const uint32_t uKh = (uint32_t)__cvta_generic_to_shared(sKh);
    const uint32_t uKl = (uint32_t)__cvta_generic_to_shared(sKl);
    const uint32_t uVh = (uint32_t)__cvta_generic_to_shared(sVh);
    const uint32_t uVl = (uint32_t)__cvta_generic_to_shared(sVl);
    const int fr = (lane & 15);
    const int fc = (lane >> 4) * 8;

    const int ntiles = q0 / 64 + 1;
    for (int tI = 0; tI < ntiles; tI++) {
        int kv0 = tI * 64;
        __syncthreads();
        for (int li = tid; li < 512; li += 128) {
            int r = li >> 3, c8 = (li & 7) * 8;
            size_t src = ((size_t)(b * S_ + kv0 + r) * (KVH_*HD_) + kvh * HD_ + c8);
            *(uint4*)&sKh[r*FST + c8] = *(const uint4*)(kh + src);
            *(uint4*)&sKl[r*FST + c8] = *(const uint4*)(kl + src);
            *(uint4*)&sVh[r*FST + c8] = *(const uint4*)(vh + src);
            *(uint4*)&sVl[r*FST + c8] = *(const uint4*)(vl + src);
        }
        __syncthreads();

        float s[8][4] = {};
        #pragma unroll
        for (int kk = 0; kk < 64; kk += 16) {
            uint32_t aqh[4], aql[4];
            uint32_t qoff = (uint32_t)(((warp*16 + fr)*FST + kk + fc) * 2);
            LDSM4(aqh, uQh + qoff);
            LDSM4(aql, uQl + qoff);
            #pragma unroll
            for (int nb = 0; nb < 4; nb++) {
                uint32_t koff = (uint32_t)(((nb*16 + fr)*FST + kk + fc) * 2);
                uint32_t k4h[4], k4l[4];
                LDSM4(k4h, uKh + koff);
                LDSM4(k4l, uKl + koff);
                MMA_BF16(s[nb*2],   aqh, k4h[0], k4h[2]);
                MMA_BF16(s[nb*2],   aqh, k4l[0], k4l[2]);
                MMA_BF16(s[nb*2],   aql, k4h[0], k4h[2]);
                MMA_BF16(s[nb*2+1], aqh, k4h[1], k4h[3]);
                MMA_BF16(s[nb*2+1], aqh, k4l[1], k4l[3]);
                MMA_BF16(s[nb*2+1], aql, k4h[1], k4h[3]);
            }
        }

        if (tI == ntiles - 1) {
            #pragma unroll
            for (int nt = 0; nt < 8; nt++) {
                int col = kv0 + nt*8 + tg*2;
                int r0g = q0 + warp*16 + g;
                if (col     > r0g)   s[nt][0] = -INFINITY;
                if (col + 1 > r0g)   s[nt][1] = -INFINITY;
                if (col     > r0g+8) s[nt][2] = -INFINITY;
                if (col + 1 > r0g+8) s[nt][3] = -INFINITY;
            }
        }

        #pragma unroll
        for (int qi = 0; qi < 2; qi++) {
            float mx = -INFINITY;
            #pragma unroll
            for (int nt = 0; nt < 8; nt++)
                mx = fmaxf(mx, fmaxf(s[nt][qi*2], s[nt][qi*2+1]));
            mx = fmaxf(mx, __shfl_xor_sync(0xffffffffu, mx, 1));
            mx = fmaxf(mx, __shfl_xor_sync(0xffffffffu, mx, 2));
            float mnew = fmaxf(mrow[qi], mx);
            float scale = __expf(mrow[qi] - mnew);
            mrow[qi] = mnew;
            float sum = 0.f;
            #pragma unroll
            for (int nt = 0; nt < 8; nt++) {
                float p0 = __expf(s[nt][qi*2]   - mnew);
                float p1 = __expf(s[nt][qi*2+1] - mnew);
                s[nt][qi*2] = p0; s[nt][qi*2+1] = p1;
                sum += p0 + p1;
            }
            sum += __shfl_xor_sync(0xffffffffu, sum, 1);
            sum += __shfl_xor_sync(0xffffffffu, sum, 2);
            lrow[qi] = lrow[qi]*scale + sum;
            #pragma unroll
            for (int nt = 0; nt < 8; nt++) {
                o[nt][qi*2]   *= scale;
                o[nt][qi*2+1] *= scale;
            }
        }

        #pragma unroll
        for (int ks = 0; ks < 4; ks++) {
            const float* s0 = s[2*ks];
            const float* s1 = s[2*ks+1];
            uint32_t ph[4], pl[4];
            {
                bf16 h0,l0,h1,l1;
                split1(s0[0], h0, l0); split1(s0[1], h1, l1);
                ph[0] = pack2(h0,h1); pl[0] = pack2(l0,l1);
                split1(s0[2], h0, l0); split1(s0[3], h1, l1);
                ph[1] = pack2(h0,h1); pl[1] = pack2(l0,l1);
                split1(s1[0], h0, l0); split1(s1[1], h1, l1);
                ph[2] = pack2(h0,h1); pl[2] = pack2(l0,l1);
                split1(s1[2], h0, l0); split1(s1[3], h1, l1);
                ph[3] = pack2(h0,h1); pl[3] = pack2(l0,l1);
            }
            #pragma unroll
            for (int nb = 0; nb < 4; nb++) {
                uint32_t voff = (uint32_t)(((ks*16 + fr)*FST + nb*16 + fc) * 2);
                uint32_t v4h[4], v4l[4];
                LDSM4T(v4h, uVh + voff);
                LDSM4T(v4l, uVl + voff);
                MMA_BF16(o[nb*2],   ph, v4h[0], v4h[1]);
                MMA_BF16(o[nb*2],   ph, v4l[0], v4l[1]);
                MMA_BF16(o[nb*2],   pl, v4h[0], v4h[1]);
                MMA_BF16(o[nb*2+1], ph, v4h[2], v4h[3]);
                MMA_BF16(o[nb*2+1], ph, v4l[2], v4l[3]);
                MMA_BF16(o[nb*2+1], pl, v4h[2], v4h[3]);
            }
        }
    }

    #pragma unroll
    for (int qi = 0; qi < 2; qi++) {
        float inv = 1.0f / lrow[qi];
        int r = q0 + warp*16 + g + qi*8;
        size_t base = (size_t)(b * S_ + r) * D_ + h * HD_;
        #pragma unroll
        for (int nt = 0; nt < 8; nt++) {
            int c = nt*8 + tg*2;
            float v0 = o[nt][qi*2]   * inv;
            float v1 = o[nt][qi*2+1] * inv;
            bf16 h0,l0,h1,l1;
            split1(v0, h0, l0); split1(v1, h1, l1);
            *(uint32_t*)(ch + base + c) = pack2(h0,h1);
            *(uint32_t*)(cl + base + c) = pack2(l0,l1);
        }
    }
}

// ---------------- host orchestration ----------------
#define FL_SMEM (6 * FQSZ * 2)

static inline void run_bgemm(const bf16* Ah, const bf16* Al,
                             const bf16* Bh, const bf16* Bl,
                             const float* Res, float* C, int M, int N, int K) {
    dim3 grid(N / BN_, M / BM_);
    bgemm_kernel<<<grid, 256, BG_SMEM>>>(Ah, Al, Bh, Bl, Res, C, M, N, K);
}
static inline void run_split(const float* src, bf16* h, bf16* l, size_t n) {
    int n4 = (int)(n / 4);
    split_kernel<<<(n4 + 255) / 256, 256>>>(src, h, l, n4);
}
static inline void run_splitw(const float* src, bf16* h, bf16* l,
                              int K, int Nin, int Nout, int cOff) {
    int n4 = K * Nin / 4;
    splitw_kernel<<<(n4 + 255) / 256, 256>>>(src, h, l, Nin, Nout, cOff, n4);
}

extern "C" void kernel_launch(void* const* d_in, const int* in_sizes, int n_in,
                              void* d_out, int out_size) {
    const void*  idx    = d_in[0];
    const float* emb    = (const float*)d_in[1];
    const float* wq     = (const float*)d_in[2];
    const float* wk     = (const float*)d_in[3];
    const float* wv     = (const float*)d_in[4];
    const float* wo     = (const float*)d_in[5];
    const float* wgate  = (const float*)d_in[6];
    const float* wup    = (const float*)d_in[7];
    const float* wdown  = (const float*)d_in[8];
    const float* na     = (const float*)d_in[9];
    const float* nf     = (const float*)d_in[10];
    const float* nfin   = (const float*)d_in[11];
    const float* wout   = (const float*)d_in[12];

    float *x, *qkv;
    cudaGetSymbolAddress((void**)&x,   g_x);
    cudaGetSymbolAddress((void**)&qkv, g_qkv);

    bf16 *nh,*nl,*qh,*ql,*kh,*kl,*vh,*vl,*ch,*cl;
    cudaGetSymbolAddress((void**)&nh, g_nh); cudaGetSymbolAddress((void**)&nl, g_nl);
    cudaGetSymbolAddress((void**)&qh, g_qh); cudaGetSymbolAddress((void**)&ql, g_ql);
    cudaGetSymbolAddress((void**)&kh, g_kh); cudaGetSymbolAddress((void**)&kl, g_kl);
    cudaGetSymbolAddress((void**)&vh, g_vh); cudaGetSymbolAddress((void**)&vl, g_vl);
    cudaGetSymbolAddress((void**)&ch, g_ch); cudaGetSymbolAddress((void**)&cl, g_cl);
    fp16 *nH, *gH, *woutH_h, *woutH_l, *wguH_h, *wguH_l, *wdH_h, *wdH_l;
    cudaGetSymbolAddress((void**)&nH, g_nH);
    cudaGetSymbolAddress((void**)&gH, g_gH);
    cudaGetSymbolAddress((void**)&woutH_h, g_woutH_h);
    cudaGetSymbolAddress((void**)&woutH_l, g_woutH_l);
    cudaGetSymbolAddress((void**)&wguH_h, g_wguH_h);
    cudaGetSymbolAddress((void**)&wguH_l, g_wguH_l);
    cudaGetSymbolAddress((void**)&wdH_h, g_wdH_h);
    cudaGetSymbolAddress((void**)&wdH_l, g_wdH_l);

    bf16 *wqkvB_h,*wqkvB_l,*woB_h,*woB_l;
    cudaGetSymbolAddress((void**)&wqkvB_h, g_wqkvB_h); cudaGetSymbolAddress((void**)&wqkvB_l, g_wqkvB_l);
    cudaGetSymbolAddress((void**)&woB_h,  g_woB_h);   cudaGetSymbolAddress((void**)&woB_l,  g_woB_l);

    cudaFuncSetAttribute(bgemm_kernel,
                         cudaFuncAttributeMaxDynamicSharedMemorySize, BG_SMEM);
    cudaFuncSetAttribute(hgemm_kernel<0>,
                         cudaFuncAttributeMaxDynamicSharedMemorySize, HG_SMEM);
    cudaFuncSetAttribute(hgemm_kernel<1>,
                         cudaFuncAttributeMaxDynamicSharedMemorySize, HG_SMEM);
    cudaFuncSetAttribute(flash_tc_kernel,
                         cudaFuncAttributeMaxDynamicSharedMemorySize, FL_SMEM);

    // weight splits
    for (int l = 0; l < L_; l++) {
        size_t qo = (size_t)l * D_ * QKV_;
        run_splitw(wq + (size_t)l*D_*D_,   wqkvB_h + qo, wqkvB_l + qo, D_, D_,   QKV_, 0);
        run_splitw(wk + (size_t)l*D_*256,  wqkvB_h + qo, wqkvB_l + qo, D_, 256,  QKV_, 1024);
        run_splitw(wv + (size_t)l*D_*256,  wqkvB_h + qo, wqkvB_l + qo, D_, 256,  QKV_, 1280);
        run_split(wo + (size_t)l*D_*D_,  woB_h + (size_t)l*D_*D_, woB_l + (size_t)l*D_*D_, (size_t)D_*D_);
        size_t go = (size_t)l * D_ * GU_;
        {   // interleaved gate/up fp16 split
            int n4 = D_ * F_ / 4;
            splitguh_kernel<<<(n4 + 255) / 256, 256>>>(
                wgate + (size_t)l*D_*F_, wup + (size_t)l*D_*F_,
                wguH_h + go, wguH_l + go, n4);
        }
        {   // wdown fp16 2-plane split
            int n4 = F_ * D_ / 4;
            splith_kernel<<<(n4 + 255) / 256, 256>>>(
                wdown + (size_t)l*F_*D_, wdH_h + (size_t)l*F_*D_,
                wdH_l + (size_t)l*F_*D_, n4);
        }
    }
    {   // wout fp16 2-plane
        int n4 = (int)((size_t)D_*V_/4);
        splith_kernel<<<(n4 + 255) / 256, 256>>>(wout, woutH_h, woutH_l, n4);
    }

    detect_idx_kernel<<<1, 256>>>((const int*)idx);
    embed_kernel<<<T_, 256>>>(idx, emb);

    for (int l = 0; l < L_; l++) {
        size_t qo = (size_t)l * D_ * QKV_;
        size_t go = (size_t)l * D_ * GU_;
        rmsnorm_split_kernel<<<T_, 256>>>(x, na + (size_t)l * D_, nh, nl);
        run_bgemm(nh, nl, wqkvB_h + qo, wqkvB_l + qo, nullptr, qkv, T_, QKV_, D_);
        rope_split_kernel<<<T_, H_*32>>>(qkv, QKV_, 0, qh, ql, H_, SCALE_);
        rope_split_kernel<<<T_, KVH_*32>>>(qkv, QKV_, 1024, kh, kl, KVH_, 1.0f);
        vsplit_kernel<<<T_, 64>>>(qkv, vh, vl);
        flash_tc_kernel<<<dim3(S_/64, H_, B_), 128, FL_SMEM>>>(qh,ql,kh,kl,vh,vl,ch,cl);
        run_bgemm(ch, cl, woB_h + (size_t)l*D_*D_, woB_l + (size_t)l*D_*D_, x, x, T_, D_, D_);
        // FFN: fp16 2-MMA path
        rmsnorm_h_kernel<<<T_, 256>>>(x, nf + (size_t)l * D_, nH);
        {   // GU with fused silu -> fp16 plane
            dim3 grid(GU_ / BN_, T_ / BM_);
            hgemm_kernel<1><<<grid, 256, HG_SMEM>>>(nH, wguH_h + go, wguH_l + go,
                                                    nullptr, nullptr, gH, T_, GU_, D_);
        }
        {   // wdown + residual
            dim3 grid(D_ / BN_, T_ / BM_);
            hgemm_kernel<0><<<grid, 256, HG_SMEM>>>(gH, wdH_h + (size_t)l*F_*D_,
                                                    wdH_l + (size_t)l*F_*D_,
                                                    x, x, nullptr, T_, D_, F_);
        }
    }

    rmsnorm_h_kernel<<<T_, 256>>>(x, nfin, nH);
    {   // vocab projection: fp16 2-MMA GEMM
        dim3 grid(V_ / BN_, T_ / BM_);
        hgemm_kernel<0><<<grid, 256, HG_SMEM>>>(nH, woutH_h, woutH_l,
                                                nullptr, (float*)d_out, nullptr,
                                                T_, V_, D_);
    }
}

// round 15
// speedup vs baseline: 1.7325x; 1.0518x over previous
#include <cuda_runtime.h>
#include <cuda_bf16.h>
#include <cuda_fp16.h>
#include <math.h>
#include <stdint.h>

// ---------------- problem constants ----------------
#define V_   32000
#define D_   1024
#define H_   16
#define KVH_ 4
#define HD_  64
#define F_   4096
#define L_   2
#define B_   2
#define S_   2048
#define T_   (B_*S_)
#define REP_ (H_/KVH_)
#define EPS_ 1e-5f
#define SCALE_ 0.125f
#define QKV_ 1536            // fused q|k|v width
#define GU_  8192            // fused gate|up width (interleaved: even=gate, odd=up)

typedef __half fp16;

// ---------------- scratch ----------------
__device__ float g_x  [T_*D_];
__device__ float g_qkv[T_*QKV_];
__device__ int   g_is64;

// activation fp16 planes
__device__ fp16 g_nH [T_*D_];                       // norm out, 1-plane
__device__ fp16 g_qH [T_*D_];                       // q, 1-plane (scaled)
__device__ fp16 g_kh [T_*KVH_*HD_], g_kl [T_*KVH_*HD_];  // k, 2-plane
__device__ fp16 g_vh [T_*KVH_*HD_], g_vl [T_*KVH_*HD_];  // v, 2-plane
__device__ fp16 g_cH [T_*D_];                       // ctx, 1-plane
__device__ fp16 g_gH [T_*F_];                       // silu out, 1-plane

// weight planes, [K, N] layout, fp16 2-plane, fused along N
__device__ fp16 g_wqkvH_h[L_*D_*QKV_], g_wqkvH_l[L_*D_*QKV_];
__device__ fp16 g_woH_h  [L_*D_*D_],   g_woH_l  [L_*D_*D_];
__device__ fp16 g_wguH_h [L_*D_*GU_],  g_wguH_l [L_*D_*GU_];   // interleaved g/u
__device__ fp16 g_wdH_h  [L_*F_*D_],   g_wdH_l  [L_*F_*D_];
__device__ fp16 g_woutH_h[D_*V_],      g_woutH_l[D_*V_];

// ---------------- helpers ----------------
__device__ __forceinline__ uint32_t pack2h(fp16 a, fp16 b) {
    __half2 t = __halves2half2(a, b);
    return *reinterpret_cast<uint32_t*>(&t);
}
__device__ __forceinline__ void split1h(float v, fp16& h, fp16& l) {
    h = __float2half(v);
    l = __float2half(v - __half2float(h));
}

#define LDSM4(r, addr) \
    asm volatile("ldmatrix.sync.aligned.m8n8.x4.shared.b16 {%0,%1,%2,%3}, [%4];" \
        : "=r"((r)[0]), "=r"((r)[1]), "=r"((r)[2]), "=r"((r)[3]) : "r"(addr))
#define LDSM4T(r, addr) \
    asm volatile("ldmatrix.sync.aligned.m8n8.x4.trans.shared.b16 {%0,%1,%2,%3}, [%4];" \
        : "=r"((r)[0]), "=r"((r)[1]), "=r"((r)[2]), "=r"((r)[3]) : "r"(addr))
#define MMA_F16(acc, a, b0, b1) \
    asm volatile("mma.sync.aligned.m16n8k16.row.col.f32.f16.f16.f32 " \
        "{%0,%1,%2,%3}, {%4,%5,%6,%7}, {%8,%9}, {%0,%1,%2,%3};" \
        : "+f"((acc)[0]), "+f"((acc)[1]), "+f"((acc)[2]), "+f"((acc)[3]) \
        : "r"((a)[0]), "r"((a)[1]), "r"((a)[2]), "r"((a)[3]), "r"(b0), "r"(b1))
#define CP16(dst, src) \
    asm volatile("cp.async.cg.shared.global [%0], [%1], 16;\n" :: "r"(dst), "l"(src) : "memory")
#define CP_COMMIT() asm volatile("cp.async.commit_group;\n" ::: "memory")
#define CP_WAIT(n)  asm volatile("cp.async.wait_group %0;\n" :: "n"(n) : "memory")

// ---------------- fp32 -> fp16 hi/lo split ----------------
__global__ void splith_kernel(const float* __restrict__ in,
                              fp16* __restrict__ hi, fp16* __restrict__ lo, int n4) {
    int i = blockIdx.x * blockDim.x + threadIdx.x;
    if (i >= n4) return;
    float4 v = ((const float4*)in)[i];
    float vv[4] = {v.x, v.y, v.z, v.w};
    fp16 h[4], l[4];
    #pragma unroll
    for (int j = 0; j < 4; j++) split1h(vv[j], h[j], l[j]);
    ((uint2*)hi)[i] = make_uint2(pack2h(h[0],h[1]), pack2h(h[2],h[3]));
    ((uint2*)lo)[i] = make_uint2(pack2h(l[0],l[1]), pack2h(l[2],l[3]));
}

// ---- strided fp16 split: in[K,Nin] -> planes[K,Nout] at column cOff ----
__global__ void splitwh_kernel(const float* __restrict__ in,
                               fp16* __restrict__ oh, fp16* __restrict__ ol,
                               int Nin, int Nout, int cOff, int n4) {
    int i = blockIdx.x * blockDim.x + threadIdx.x;
    if (i >= n4) return;
    int rc4 = Nin >> 2;
    int r = i / rc4, c4 = i - r * rc4;
    float4 v = ((const float4*)in)[i];
    float vv[4] = {v.x, v.y, v.z, v.w};
    fp16 h[4], l[4];
    #pragma unroll
    for (int q = 0; q < 4; q++) split1h(vv[q], h[q], l[q]);
    size_t oi = ((size_t)r * Nout + cOff) / 4 + c4;
    ((uint2*)oh)[oi] = make_uint2(pack2h(h[0],h[1]), pack2h(h[2],h[3]));
    ((uint2*)ol)[oi] = make_uint2(pack2h(l[0],l[1]), pack2h(l[2],l[3]));
}

// ---- gate/up interleaved fp16 split ----
__global__ void splitguh_kernel(const float* __restrict__ wg,
                                const float* __restrict__ wu,
                                fp16* __restrict__ oh, fp16* __restrict__ ol, int n4) {
    int i = blockIdx.x * blockDim.x + threadIdx.x;
    if (i >= n4) return;
    float4 gv = ((const float4*)wg)[i];
    float4 uv = ((const float4*)wu)[i];
    float gg[4] = {gv.x, gv.y, gv.z, gv.w};
    float uu[4] = {uv.x, uv.y, uv.z, uv.w};
    fp16 ghh[4], gll[4], uhh[4], ull[4];
    #pragma unroll
    for (int q = 0; q < 4; q++) { split1h(gg[q], ghh[q], gll[q]); split1h(uu[q], uhh[q], ull[q]); }
    uint4 hO, lO;
    hO.x = pack2h(ghh[0], uhh[0]); hO.y = pack2h(ghh[1], uhh[1]);
    hO.z = pack2h(ghh[2], uhh[2]); hO.w = pack2h(ghh[3], uhh[3]);
    lO.x = pack2h(gll[0], ull[0]); lO.y = pack2h(gll[1], ull[1]);
    lO.z = pack2h(gll[2], ull[2]); lO.w = pack2h(gll[3], ull[3]);
    ((uint4*)oh)[i] = hO;
    ((uint4*)ol)[i] = lO;
}

// ---------------- idx detection + embed ----------------
__global__ void detect_idx_kernel(const int* idx) {
    __shared__ int ok;
    if (threadIdx.x == 0) ok = 1;
    __syncthreads();
    int bad = 0;
    for (int i = threadIdx.x; i < T_/2; i += blockDim.x)
        if (idx[2*i + 1] != 0) bad = 1;
    if (bad) atomicAnd(&ok, 0);
    __syncthreads();
    if (threadIdx.x == 0) g_is64 = ok;
}
__global__ void embed_kernel(const void* idx, const float* __restrict__ emb) {
    int t = blockIdx.x;
    int tok = g_is64 ? (int)((const long long*)idx)[t] : ((const int*)idx)[t];
    ((float4*)(g_x + (size_t)t * D_))[threadIdx.x] =
        ((const float4*)(emb + (size_t)tok * D_))[threadIdx.x];
}

// ---------------- RMSNorm -> fp16 single plane --------------------------
__global__ void rmsnorm_h_kernel(const float* __restrict__ x,
                                 const float* __restrict__ w,
                                 fp16* __restrict__ o) {
    int t = blockIdx.x;
    __shared__ float red[8];
    float4 v = ((const float4*)(x + (size_t)t * D_))[threadIdx.x];
    float ss = v.x*v.x + v.y*v.y + v.z*v.z + v.w*v.w;
    #pragma unroll
    for (int off = 16; off > 0; off >>= 1) ss += __shfl_xor_sync(0xffffffffu, ss, off);
    if ((threadIdx.x & 31) == 0) red[threadIdx.x >> 5] = ss;
    __syncthreads();
    if (threadIdx.x < 8) {
        float s = red[threadIdx.x];
        #pragma unroll
        for (int off = 4; off > 0; off >>= 1) s += __shfl_xor_sync(0xffu, s, off);
        if (threadIdx.x == 0) red[0] = s;
    }
    __syncthreads();
    float inv = rsqrtf(red[0] * (1.0f / D_) + EPS_);
    float4 wv = ((const float4*)w)[threadIdx.x];
    fp16 h0 = __float2half(v.x*inv*wv.x), h1 = __float2half(v.y*inv*wv.y);
    fp16 h2 = __float2half(v.z*inv*wv.z), h3 = __float2half(v.w*inv*wv.w);
    ((uint2*)(o + (size_t)t*D_))[threadIdx.x] = make_uint2(pack2h(h0,h1), pack2h(h2,h3));
}

// ---------------- RoPE -> q fp16 single plane (scaled) ------------------
__global__ void rope_q_kernel(const float* __restrict__ x,
                              fp16* __restrict__ q) {
    int t   = blockIdx.x;
    int pos = t % S_;
    int j   = threadIdx.x & 31;
    int h   = threadIdx.x >> 5;
    float invf = powf(500000.0f, -(float)(2 * j) / (float)HD_);
    float ang = (float)pos * invf;
    float s, c;
    sincosf(ang, &s, &c);
    const float* p = x + (size_t)t * QKV_ + h * HD_;
    size_t ob = (size_t)t * D_ + h * HD_;
    float a = p[j], b = p[j + 32];
    q[ob + j]      = __float2half((a * c - b * s) * SCALE_);
    q[ob + j + 32] = __float2half((b * c + a * s) * SCALE_);
}

// ---------------- RoPE -> k fp16 2-plane --------------------------------
__global__ void rope_k_kernel(const float* __restrict__ x,
                              fp16* __restrict__ kh, fp16* __restrict__ kl) {
    int t   = blockIdx.x;
    int pos = t % S_;
    int j   = threadIdx.x & 31;
    int h   = threadIdx.x >> 5;
    float invf = powf(500000.0f, -(float)(2 * j) / (float)HD_);
    float ang = (float)pos * invf;
    float s, c;
    sincosf(ang, &s, &c);
    const float* p = x + (size_t)t * QKV_ + 1024 + h * HD_;
    size_t ob = (size_t)t * (KVH_*HD_) + h * HD_;
    float a = p[j], b = p[j + 32];
    float r0 = a * c - b * s;
    float r1 = b * c + a * s;
    fp16 h0, l0, h1, l1;
    split1h(r0, h0, l0); split1h(r1, h1, l1);
    kh[ob + j] = h0;       kl[ob + j] = l0;
    kh[ob + j + 32] = h1;  kl[ob + j + 32] = l1;
}

// ---------------- strided V split (fp16 2-plane) ------------------------
__global__ void vsplit_kernel(const float* __restrict__ x,
                              fp16* __restrict__ oh, fp16* __restrict__ ol) {
    int t = blockIdx.x, i = threadIdx.x;   // 64 threads * float4 = 256
    float4 v = *(const float4*)(x + (size_t)t*QKV_ + 1280 + i*4);
    float vv[4] = {v.x, v.y, v.z, v.w};
    fp16 h[4], l[4];
    #pragma unroll
    for (int j = 0; j < 4; j++) split1h(vv[j], h[j], l[j]);
    ((uint2*)(oh + (size_t)t*256))[i] = make_uint2(pack2h(h[0],h[1]), pack2h(h[2],h[3]));
    ((uint2*)(ol + (size_t)t*256))[i] = make_uint2(pack2h(l[0],l[1]), pack2h(l[2],l[3]));
}

// ======== fp16 2-MMA GEMM: A 1-plane, B 2-plane =========================
// EPI 0: fp32 out (+opt Res).  EPI 1: silu(gate)*up from interleaved cols,
//        fp16 1-plane out of width N/2.
#define BM_  128
#define BN_  128
#define BKK_ 32
#define AST_ 40
#define BST_ 136
#define ASZ_ (BM_*AST_)
#define BSZ_ (BKK_*BST_)
#define HG_SMEM ((2*ASZ_ + 2*BSZ_*2) * 2)

template <int EPI>
__global__ void __launch_bounds__(256)
hgemm_kernel(const fp16* __restrict__ Ag,
             const fp16* __restrict__ Bhg, const fp16* __restrict__ Blg,
             const float* __restrict__ Res, float* __restrict__ C,
             fp16* __restrict__ O, int M, int N, int K) {
    extern __shared__ fp16 hsm[];
    fp16* sA  = hsm;
    fp16* sBh = sA + 2*ASZ_;
    fp16* sBl = sBh + 2*BSZ_;

    const int tid  = threadIdx.x;
    const int lane = tid & 31, warp = tid >> 5;
    const int warpM = warp >> 1, warpN = warp & 1;
    const int bx = blockIdx.x, by = blockIdx.y;

    const fp16* Ab  = Ag  + (size_t)by * BM_ * K;
    const fp16* Bhb = Bhg + (size_t)bx * BN_;
    const fp16* Blb = Blg + (size_t)bx * BN_;

    const uint32_t uA  = (uint32_t)__cvta_generic_to_shared(sA);
    const uint32_t uBh = (uint32_t)__cvta_generic_to_shared(sBh);
    const uint32_t uBl = (uint32_t)__cvta_generic_to_shared(sBl);

    const int ar = tid >> 2, ac = (tid & 3) * 8;
    const int br = tid >> 4, bc = (tid & 15) * 8;

    auto load_stage = [&](int st, int k0) {
        #pragma unroll
        for (int p = 0; p < 2; p++) {
            int r = ar + p*64;
            uint32_t d = (uint32_t)((st*ASZ_ + r*AST_ + ac) * 2);
            CP16(uA + d, Ab + (size_t)r*K + k0 + ac);
        }
        #pragma unroll
        for (int p = 0; p < 2; p++) {
            int r = br + p*16;
            uint32_t d = (uint32_t)((st*BSZ_ + r*BST_ + bc) * 2);
            CP16(uBh + d, Bhb + (size_t)(k0 + r)*N + bc);
            CP16(uBl + d, Blb + (size_t)(k0 + r)*N + bc);
        }
    };

    float acc[2][8][4];
    #pragma unroll
    for (int i = 0; i < 2; i++)
        #pragma unroll
        for (int j = 0; j < 8; j++)
            #pragma unroll
            for (int q = 0; q < 4; q++) acc[i][j][q] = 0.f;

    const int arow = warpM*32 + (lane & 15);
    const int acol = (lane >> 4) * 8;
    const int brow = (lane & 15);
    const int bcol = warpN*64 + (lane >> 4) * 8;

    const int kIters = K / BKK_;
    load_stage(0, 0);
    CP_COMMIT();

    for (int it = 0; it < kIters; ++it) {
        if (it + 1 < kIters) {
            load_stage((it+1)&1, (it+1)*BKK_);
            CP_COMMIT();
            CP_WAIT(1);
        } else {
            CP_WAIT(0);
        }
        __syncthreads();
        const int st = it & 1;
        const uint32_t aA = uA  + (uint32_t)(st*ASZ_*2);
        const uint32_t bH = uBh + (uint32_t)(st*BSZ_*2);
        const uint32_t bL = uBl + (uint32_t)(st*BSZ_*2);
        #pragma unroll
        for (int kk = 0; kk < BKK_; kk += 16) {
            uint32_t a4[2][4];
            #pragma unroll
            for (int mt = 0; mt < 2; mt++) {
                uint32_t off = (uint32_t)(((arow + mt*16)*AST_ + kk + acol) * 2);
                LDSM4(a4[mt], aA + off);
            }
            #pragma unroll
            for (int pr = 0; pr < 4; pr++) {
                uint32_t off = (uint32_t)(((brow + kk)*BST_ + bcol + pr*16) * 2);
                uint32_t bh[4], bl[4];
                LDSM4T(bh, bH + off);
                LDSM4T(bl, bL + off);
                #pragma unroll
                for (int mt = 0; mt < 2; mt++) {
                    #pragma unroll
                    for (int h2 = 0; h2 < 2; h2++) {
                        int nt = pr*2 + h2;
                        MMA_F16(acc[mt][nt], a4[mt], bh[h2*2], bh[h2*2+1]);
                        MMA_F16(acc[mt][nt], a4[mt], bl[h2*2], bl[h2*2+1]);
                    }
                }
            }
        }
        __syncthreads();
    }

    const int g = lane >> 2, tg = lane & 3;
    if (EPI == 0) {
        #pragma unroll
        for (int mt = 0; mt < 2; mt++) {
            #pragma unroll
            for (int nt = 0; nt < 8; nt++) {
                size_t r0 = (size_t)by*BM_ + warpM*32 + mt*16 + g;
                size_t c  = (size_t)bx*BN_ + warpN*64 + nt*8 + tg*2;
                float2 v0 = make_float2(acc[mt][nt][0], acc[mt][nt][1]);
                float2 v1 = make_float2(acc[mt][nt][2], acc[mt][nt][3]);
                if (Res) {
                    float2 q0 = *(const float2*)(Res + r0*N + c);
                    float2 q1 = *(const float2*)(Res + (r0+8)*N + c);
                    v0.x += q0.x; v0.y += q0.y; v1.x += q1.x; v1.y += q1.y;
                }
                *(float2*)(C + r0*N + c)     = v0;
                *(float2*)(C + (r0+8)*N + c) = v1;
            }
        }
    } else {
        // silu(gate)*up epilogue: cols (c, c+1) = (gate_j, up_j), j = c/2.
        const int NO = N >> 1;
        #pragma unroll
        for (int mt = 0; mt < 2; mt++) {
            #pragma unroll
            for (int nt = 0; nt < 8; nt++) {
                size_t r0 = (size_t)by*BM_ + warpM*32 + mt*16 + g;
                size_t j  = (size_t)bx*(BN_/2) + warpN*32 + nt*4 + tg;
                float gate0 = acc[mt][nt][0], up0 = acc[mt][nt][1];
                float gate1 = acc[mt][nt][2], up1 = acc[mt][nt][3];
                float v0 = gate0 / (1.f + __expf(-gate0)) * up0;
                float v1 = gate1 / (1.f + __expf(-gate1)) * up1;
                O[r0*NO + j]     = __float2half(v0);
                O[(r0+8)*NO + j] = __float2half(v1);
            }
        }
    }
}

// ================= fp16 flash attention (2-MMA) =========================
// Q 1-plane (pre-scaled), K/V 2-plane, P 1-plane, ctx 1-plane out.
#define FST 72
#define FQSZ (64*FST)
#define FL_SMEM (5 * FQSZ * 2)

__global__ void __launch_bounds__(128)
flash_h_kernel(const fp16* __restrict__ qg,
               const fp16* __restrict__ kh, const fp16* __restrict__ kl,
               const fp16* __restrict__ vh, const fp16* __restrict__ vl,
               fp16* __restrict__ cg) {
    extern __shared__ fp16 fsm[];
    fp16* sQ  = fsm;
    fp16* sKh = sQ  + FQSZ;
    fp16* sKl = sKh + FQSZ;
    fp16* sVh = sKl + FQSZ;
    fp16* sVl = sVh + FQSZ;

    const int q0  = blockIdx.x * 64;
    const int h   = blockIdx.y;
    const int b   = blockIdx.z;
    const int kvh = h / REP_;
    const int tid = threadIdx.x;
    const int lane = tid & 31, warp = tid >> 5;
    const int g = lane >> 2, tg = lane & 3;

    for (int li = tid; li < 512; li += 128) {
        int r = li >> 3, c8 = (li & 7) * 8;
        size_t src = ((size_t)(b * S_ + q0 + r) * D_ + h * HD_ + c8);
        *(uint4*)&sQ[r*FST + c8] = *(const uint4*)(qg + src);
    }

    float mrow[2] = {-INFINITY, -INFINITY};
    float lrow[2] = {0.f, 0.f};
    float o[8][4] = {};

    const uint32_t uQ  = (uint32_t)__cvta_generic_to_shared(sQ);
    const uint32_t uKh = (uint32_t)__cvta_generic_to_shared(sKh);
    const uint32_t uKl = (uint32_t)__cvta_generic_to_shared(sKl);
    const uint32_t uVh = (uint32_t)__cvta_generic_to_shared(sVh);
    const uint32_t uVl = (uint32_t)__cvta_generic_to_shared(sVl);
    const int fr = (lane & 15);
    const int fc = (lane >> 4) * 8;

    const int ntiles = q0 / 64 + 1;
    for (int tI = 0; tI < ntiles; tI++) {
        int kv0 = tI * 64;
        __syncthreads();
        for (int li = tid; li < 512; li += 128) {
            int r = li >> 3, c8 = (li & 7) * 8;
            size_t src = ((size_t)(b * S_ + kv0 + r) * (KVH_*HD_) + kvh * HD_ + c8);
            *(uint4*)&sKh[r*FST + c8] = *(const uint4*)(kh + src);
            *(uint4*)&sKl[r*FST + c8] = *(const uint4*)(kl + src);
            *(uint4*)&sVh[r*FST + c8] = *(const uint4*)(vh + src);
            *(uint4*)&sVl[r*FST + c8] = *(const uint4*)(vl + src);
        }
        __syncthreads();

        // S = Q K^T : 2 MMAs (q·kh + q·kl)
        float s[8][4] = {};
        #pragma unroll
        for (int kk = 0; kk < 64; kk += 16) {
            uint32_t aq[4];
            uint32_t qoff = (uint32_t)(((warp*16 + fr)*FST + kk + fc) * 2);
            LDSM4(aq, uQ + qoff);
            #pragma unroll
            for (int nb = 0; nb < 4; nb++) {
                uint32_t koff = (uint32_t)(((nb*16 + fr)*FST + kk + fc) * 2);
                uint32_t k4h[4], k4l[4];
                LDSM4(k4h, uKh + koff);
                LDSM4(k4l, uKl + koff);
                MMA_F16(s[nb*2],   aq, k4h[0], k4h[2]);
                MMA_F16(s[nb*2],   aq, k4l[0], k4l[2]);
                MMA_F16(s[nb*2+1], aq, k4h[1], k4h[3]);
                MMA_F16(s[nb*2+1], aq, k4l[1], k4l[3]);
            }
        }

        if (tI == ntiles - 1) {
            #pragma unroll
            for (int nt = 0; nt < 8; nt++) {
                int col = kv0 + nt*8 + tg*2;
                int r0g = q0 + warp*16 + g;
                if (col     > r0g)   s[nt][0] = -INFINITY;
                if (col + 1 > r0g)   s[nt][1] = -INFINITY;
                if (col     > r0g+8) s[nt][2] = -INFINITY;
                if (col + 1 > r0g+8) s[nt][3] = -INFINITY;
            }
        }

        #pragma unroll
        for (int qi = 0; qi < 2; qi++) {
            float mx = -INFINITY;
            #pragma unroll
            for (int nt = 0; nt < 8; nt++)
                mx = fmaxf(mx, fmaxf(s[nt][qi*2], s[nt][qi*2+1]));
            mx = fmaxf(mx, __shfl_xor_sync(0xffffffffu, mx, 1));
            mx = fmaxf(mx, __shfl_xor_sync(0xffffffffu, mx, 2));
            float mnew = fmaxf(mrow[qi], mx);
            float scale = __expf(mrow[qi] - mnew);
            mrow[qi] = mnew;
            float sum = 0.f;
            #pragma unroll
            for (int nt = 0; nt < 8; nt++) {
                float p0 = __expf(s[nt][qi*2]   - mnew);
                float p1 = __expf(s[nt][qi*2+1] - mnew);
                s[nt][qi*2] = p0; s[nt][qi*2+1] = p1;
                sum += p0 + p1;
            }
            sum += __shfl_xor_sync(0xffffffffu, sum, 1);
            sum += __shfl_xor_sync(0xffffffffu, sum, 2);
            lrow[qi] = lrow[qi]*scale + sum;
            #pragma unroll
            for (int nt = 0; nt < 8; nt++) {
                o[nt][qi*2]   *= scale;
                o[nt][qi*2+1] *= scale;
            }
        }

        // O += P V : 2 MMAs (p·vh + p·vl); P packed fp16 1-plane
        #pragma unroll
        for (int ks = 0; ks < 4; ks++) {
            const float* s0 = s[2*ks];
            const float* s1 = s[2*ks+1];
            uint32_t ph[4];
            ph[0] = pack2h(__float2half(s0[0]), __float2half(s0[1]));
            ph[1] = pack2h(__float2half(s0[2]), __float2half(s0[3]));
            ph[2] = pack2h(__float2half(s1[0]), __float2half(s1[1]));
            ph[3] = pack2h(__float2half(s1[2]), __float2half(s1[3]));
            #pragma unroll
            for (int nb = 0; nb < 4; nb++) {
                uint32_t voff = (uint32_t)(((ks*16 + fr)*FST + nb*16 + fc) * 2);
                uint32_t v4h[4], v4l[4];
                LDSM4T(v4h, uVh + voff);
                LDSM4T(v4l, uVl + voff);
                MMA_F16(o[nb*2],   ph, v4h[0], v4h[1]);
                MMA_F16(o[nb*2],   ph, v4l[0], v4l[1]);
                MMA_F16(o[nb*2+1], ph, v4h[2], v4h[3]);
                MMA_F16(o[nb*2+1], ph, v4l[2], v4l[3]);
            }
        }
    }

    #pragma unroll
    for (int qi = 0; qi < 2; qi++) {
        float inv = 1.0f / lrow[qi];
        int r = q0 + warp*16 + g + qi*8;
        size_t base = (size_t)(b * S_ + r) * D_ + h * HD_;
        #pragma unroll
        for (int nt = 0; nt < 8; nt++) {
            int c = nt*8 + tg*2;
            *(uint32_t*)(cg + base + c) =
                pack2h(__float2half(o[nt][qi*2] * inv),
                       __float2half(o[nt][qi*2+1] * inv));
        }
    }
}

// ---------------- host orchestration ----------------
extern "C" void kernel_launch(void* const* d_in, const int* in_sizes, int n_in,
                              void* d_out, int out_size) {
    const void*  idx    = d_in[0];
    const float* emb    = (const float*)d_in[1];
    const float* wq     = (const float*)d_in[2];
    const float* wk     = (const float*)d_in[3];
    const float* wv     = (const float*)d_in[4];
    const float* wo     = (const float*)d_in[5];
    const float* wgate  = (const float*)d_in[6];
    const float* wup    = (const float*)d_in[7];
    const float* wdown  = (const float*)d_in[8];
    const float* na     = (const float*)d_in[9];
    const float* nf     = (const float*)d_in[10];
    const float* nfin   = (const float*)d_in[11];
    const float* wout   = (const float*)d_in[12];

    float *x, *qkv;
    cudaGetSymbolAddress((void**)&x,   g_x);
    cudaGetSymbolAddress((void**)&qkv, g_qkv);

    fp16 *nH, *qH, *kh, *kl, *vh, *vl, *cH, *gH;
    cudaGetSymbolAddress((void**)&nH, g_nH);
    cudaGetSymbolAddress((void**)&qH, g_qH);
    cudaGetSymbolAddress((void**)&kh, g_kh); cudaGetSymbolAddress((void**)&kl, g_kl);
    cudaGetSymbolAddress((void**)&vh, g_vh); cudaGetSymbolAddress((void**)&vl, g_vl);
    cudaGetSymbolAddress((void**)&cH, g_cH);
    cudaGetSymbolAddress((void**)&gH, g_gH);

    fp16 *wqkvH_h,*wqkvH_l,*woH_h,*woH_l,*wguH_h,*wguH_l,*wdH_h,*wdH_l,*woutH_h,*woutH_l;
    cudaGetSymbolAddress((void**)&wqkvH_h, g_wqkvH_h); cudaGetSymbolAddress((void**)&wqkvH_l, g_wqkvH_l);
    cudaGetSymbolAddress((void**)&woH_h,  g_woH_h);   cudaGetSymbolAddress((void**)&woH_l,  g_woH_l);
    cudaGetSymbolAddress((void**)&wguH_h, g_wguH_h);  cudaGetSymbolAddress((void**)&wguH_l, g_wguH_l);
    cudaGetSymbolAddress((void**)&wdH_h,  g_wdH_h);   cudaGetSymbolAddress((void**)&wdH_l,  g_wdH_l);
    cudaGetSymbolAddress((void**)&woutH_h,g_woutH_h); cudaGetSymbolAddress((void**)&woutH_l,g_woutH_l);

    cudaFuncSetAttribute(hgemm_kernel<0>,
                         cudaFuncAttributeMaxDynamicSharedMemorySize, HG_SMEM);
    cudaFuncSetAttribute(hgemm_kernel<1>,
                         cudaFuncAttributeMaxDynamicSharedMemorySize, HG_SMEM);
    cudaFuncSetAttribute(flash_h_kernel,
                         cudaFuncAttributeMaxDynamicSharedMemorySize, FL_SMEM);

    // weight splits (all fp16 2-plane)
    for (int l = 0; l < L_; l++) {
        size_t qo = (size_t)l * D_ * QKV_;
        {
            int n4 = D_ * D_ / 4;
            splitwh_kernel<<<(n4 + 255) / 256, 256>>>(
                wq + (size_t)l*D_*D_, wqkvH_h + qo, wqkvH_l + qo, D_, QKV_, 0, n4);
        }
        {
            int n4 = D_ * 256 / 4;
            splitwh_kernel<<<(n4 + 255) / 256, 256>>>(
                wk + (size_t)l*D_*256, wqkvH_h + qo, wqkvH_l + qo, 256, QKV_, 1024, n4);
            splitwh_kernel<<<(n4 + 255) / 256, 256>>>(
                wv + (size_t)l*D_*256, wqkvH_h + qo, wqkvH_l + qo, 256, QKV_, 1280, n4);
        }
        {
            int n4 = D_ * D_ / 4;
            splith_kernel<<<(n4 + 255) / 256, 256>>>(
                wo + (size_t)l*D_*D_, woH_h + (size_t)l*D_*D_, woH_l + (size_t)l*D_*D_, n4);
        }
        size_t go = (size_t)l * D_ * GU_;
        {
            int n4 = D_ * F_ / 4;
            splitguh_kernel<<<(n4 + 255) / 256, 256>>>(
                wgate + (size_t)l*D_*F_, wup + (size_t)l*D_*F_,
                wguH_h + go, wguH_l + go, n4);
        }
        {
            int n4 = F_ * D_ / 4;
            splith_kernel<<<(n4 + 255) / 256, 256>>>(
                wdown + (size_t)l*F_*D_, wdH_h + (size_t)l*F_*D_,
                wdH_l + (size_t)l*F_*D_, n4);
        }
    }
    {
        int n4 = (int)((size_t)D_*V_/4);
        splith_kernel<<<(n4 + 255) / 256, 256>>>(wout, woutH_h, woutH_l, n4);
    }

    detect_idx_kernel<<<1, 256>>>((const int*)idx);
    embed_kernel<<<T_, 256>>>(idx, emb);

    for (int l = 0; l < L_; l++) {
        size_t qo = (size_t)l * D_ * QKV_;
        size_t go = (size_t)l * D_ * GU_;
        rmsnorm_h_kernel<<<T_, 256>>>(x, na + (size_t)l * D_, nH);
        {   // QKV
            dim3 grid(QKV_ / BN_, T_ / BM_);
            hgemm_kernel<0><<<grid, 256, HG_SMEM>>>(nH, wqkvH_h + qo, wqkvH_l + qo,
                                                    nullptr, qkv, nullptr, T_, QKV_, D_);
        }
        rope_q_kernel<<<T_, H_*32>>>(qkv, qH);
        rope_k_kernel<<<T_, KVH_*32>>>(qkv, kh, kl);
        vsplit_kernel<<<T_, 64>>>(qkv, vh, vl);
        flash_h_kernel<<<dim3(S_/64, H_, B_), 128, FL_SMEM>>>(qH, kh, kl, vh, vl, cH);
        {   // wo + residual
            dim3 grid(D_ / BN_, T_ / BM_);
            hgemm_kernel<0><<<grid, 256, HG_SMEM>>>(cH, woH_h + (size_t)l*D_*D_,
                                                    woH_l + (size_t)l*D_*D_,
                                                    x, x, nullptr, T_, D_, D_);
        }
        rmsnorm_h_kernel<<<T_, 256>>>(x, nf + (size_t)l * D_, nH);
        {   // GU with fused silu
            dim3 grid(GU_ / BN_, T_ / BM_);
            hgemm_kernel<1><<<grid, 256, HG_SMEM>>>(nH, wguH_h + go, wguH_l + go,
                                                    nullptr, nullptr, gH, T_, GU_, D_);
        }
        {   // wdown + residual
            dim3 grid(D_ / BN_, T_ / BM_);
            hgemm_kernel<0><<<grid, 256, HG_SMEM>>>(gH, wdH_h + (size_t)l*F_*D_,
                                                    wdH_l + (size_t)l*F_*D_,
                                                    x, x, nullptr, T_, D_, F_);
        }
    }

    rmsnorm_h_kernel<<<T_, 256>>>(x, nfin, nH);
    {   // vocab projection
        dim3 grid(V_ / BN_, T_ / BM_);
        hgemm_kernel<0><<<grid, 256, HG_SMEM>>>(nH, woutH_h, woutH_l,
                                                nullptr, (float*)d_out, nullptr,
                                                T_, V_, D_);
    }
}